// round 1
// baseline (speedup 1.0000x reference)
#include <cuda_runtime.h>
#include <math.h>

#define BATCH 64
#define CDIM 256
#define TDIM 128
#define JDIM 17
#define TJ 2176     // TDIM*JDIM
#define HCC 43
#define WCC 6
#define HW 258      // HCC*WCC
#define HIDDEN 1024

// scratch (static __device__ globals per harness rules)
__device__ float g_qkv[(size_t)3 * BATCH * HW * CDIM];   // [b][t(3)][hw][c]  50.7 MB
__device__ float g_att[(size_t)BATCH * HW * CDIM];       // [b][hw][c]        16.9 MB

__device__ __forceinline__ float gelu_exact(float v) {
    return 0.5f * v * (1.0f + erff(v * 0.70710678118654752f));
}

// ---------------------------------------------------------------------------
// K1: qkv = gelu(qbn(conv3x3_s3(n1bn(x))))  -> g_qkv[b][t][hw][c]
// GEMM per batch: M=768 (out ch), N=258 (positions), K=2304 (=256*9)
// ---------------------------------------------------------------------------
__global__ void __launch_bounds__(256) k_conv_qkv(
    const float* __restrict__ x, const float* __restrict__ w,
    const float* __restrict__ n1g, const float* __restrict__ n1b,
    const float* __restrict__ n1m, const float* __restrict__ n1v,
    const float* __restrict__ qg, const float* __restrict__ qb,
    const float* __restrict__ qm, const float* __restrict__ qv)
{
    __shared__ float Ws[64][65];
    __shared__ float Xs[64][65];
    __shared__ float s_in[256], t_in[256];
    __shared__ float s_o[64], t_o[64];

    const int b  = blockIdx.z;
    const int m0 = blockIdx.x * 64;
    const int n0 = blockIdx.y * 64;
    const int tid = threadIdx.x;

    {   // fold norm1 BN (per input channel)
        float s = n1g[tid] * rsqrtf(n1v[tid] + 1e-5f);
        s_in[tid] = s;
        t_in[tid] = n1b[tid] - n1m[tid] * s;
    }
    if (tid < 64) {   // fold qbn (per output channel of this M tile)
        int o = m0 + tid;
        float s = qg[o] * rsqrtf(qv[o] + 1e-5f);
        s_o[tid] = s;
        t_o[tid] = qb[o] - qm[o] * s;
    }
    __syncthreads();

    float acc[4][4];
#pragma unroll
    for (int u = 0; u < 4; u++)
#pragma unroll
        for (int v2 = 0; v2 < 4; v2++) acc[u][v2] = 0.f;

    const int ty = tid >> 4, tx = tid & 15;

    for (int kc = 0; kc < 2304; kc += 64) {
        // weights tile (contiguous in k)
        for (int e = tid; e < 4096; e += 256) {
            int mm = e >> 6, kk = e & 63;
            Ws[mm][kk] = w[(size_t)(m0 + mm) * 2304 + (kc + kk)];
        }
        // input-patch tile with BN applied per in-bounds element
        for (int e = tid; e < 4096; e += 256) {
            int kk = e >> 6, nn = e & 63;
            int k = kc + kk;
            int i = k / 9;
            int rr = k - i * 9;
            int ky = rr / 3, kx = rr - ky * 3;
            int n = n0 + nn;
            float val = 0.f;
            if (n < HW) {
                int y = n / WCC, xj = n - y * WCC;
                int iy = 3 * y - 1 + ky;
                int ix = 3 * xj - 1 + kx;
                if (iy >= 0 && iy < TDIM && ix >= 0 && ix < JDIM) {
                    val = x[(((size_t)b * CDIM + i) * TDIM + iy) * JDIM + ix]
                              * s_in[i] + t_in[i];
                }
            }
            Xs[kk][nn] = val;
        }
        __syncthreads();
#pragma unroll
        for (int kk = 0; kk < 64; kk++) {
            float a[4], bb[4];
#pragma unroll
            for (int u = 0; u < 4; u++) a[u] = Ws[ty * 4 + u][kk];
#pragma unroll
            for (int u = 0; u < 4; u++) bb[u] = Xs[kk][tx * 4 + u];
#pragma unroll
            for (int u = 0; u < 4; u++)
#pragma unroll
                for (int v2 = 0; v2 < 4; v2++) acc[u][v2] += a[u] * bb[v2];
        }
        __syncthreads();
    }

#pragma unroll
    for (int u = 0; u < 4; u++) {
        int o = m0 + ty * 4 + u;
        int tpart = o >> 8;
        int cc = o & 255;
        float so = s_o[ty * 4 + u], to = t_o[ty * 4 + u];
        float* base = g_qkv + (((size_t)b * 3 + tpart) * HW) * CDIM + cc;
#pragma unroll
        for (int v2 = 0; v2 < 4; v2++) {
            int n = n0 + tx * 4 + v2;
            if (n < HW) base[(size_t)n * CDIM] = gelu_exact(acc[u][v2] * so + to);
        }
    }
}

// ---------------------------------------------------------------------------
// K2: attention, one (b,h) per block, flash-style online softmax
// ---------------------------------------------------------------------------
__global__ void __launch_bounds__(256) k_attn()
{
    extern __shared__ float sm[];
    float* qs = sm;                 // [258][33]
    float* ks = sm + 258 * 33;
    float* vs = sm + 2 * 258 * 33;

    const int bh = blockIdx.x;
    const int b = bh >> 3, h = bh & 7;
    const int tid = threadIdx.x;

    const float* qg = g_qkv + (((size_t)b * 3 + 0) * HW) * CDIM + h * 32;
    const float* kg = g_qkv + (((size_t)b * 3 + 1) * HW) * CDIM + h * 32;
    const float* vg = g_qkv + (((size_t)b * 3 + 2) * HW) * CDIM + h * 32;

    for (int e = tid; e < HW * 32; e += 256) {
        int r = e >> 5, d = e & 31;
        qs[r * 33 + d] = qg[(size_t)r * CDIM + d];
        ks[r * 33 + d] = kg[(size_t)r * CDIM + d];
        vs[r * 33 + d] = vg[(size_t)r * CDIM + d];
    }
    __syncthreads();

    const float scale = 0.17677669529663687f;  // 1/sqrt(32)

    for (int r = tid; r < HW; r += 256) {
        float qr[32];
#pragma unroll
        for (int d = 0; d < 32; d++) qr[d] = qs[r * 33 + d];
        float m = -1e30f, l = 0.f;
        float acc[32];
#pragma unroll
        for (int d = 0; d < 32; d++) acc[d] = 0.f;
        for (int j = 0; j < HW; j++) {
            const float* kj = ks + j * 33;
            float s = 0.f;
#pragma unroll
            for (int d = 0; d < 32; d++) s += qr[d] * kj[d];
            s *= scale;
            float mn = fmaxf(m, s);
            float corr = __expf(m - mn);
            float p = __expf(s - mn);
            l = l * corr + p;
            const float* vj = vs + j * 33;
#pragma unroll
            for (int d = 0; d < 32; d++) acc[d] = acc[d] * corr + p * vj[d];
            m = mn;
        }
        float inv = 1.f / l;
        float* og = g_att + ((size_t)b * HW + r) * CDIM + h * 32;
#pragma unroll
        for (int d = 0; d < 32; d++) og[d] = acc[d] * inv;
    }
}

// ---------------------------------------------------------------------------
// K3: x1 = x + proj1x1(bilinear_resize(att, 43x6 -> 128x17)) ; resize fused
// into the GEMM A-gather (g_att stays L2-resident).
// GEMM per batch: M=256, N=2176, K=256
// ---------------------------------------------------------------------------
__global__ void __launch_bounds__(256) k_proj(
    const float* __restrict__ pw, const float* __restrict__ pb,
    const float* __restrict__ x, float* __restrict__ x1)
{
    __shared__ float Ws[64][65];
    __shared__ float Xs[64][65];
    __shared__ int   iy0[64], iy1[64], ix0[64], ix1[64];
    __shared__ float fwy[64], fwx[64];

    const int b  = blockIdx.z;
    const int m0 = blockIdx.x * 64;
    const int n0 = blockIdx.y * 64;
    const int tid = threadIdx.x;

    if (tid < 64) {   // half-pixel bilinear coords (clamped == jax triangle w/ renorm)
        int p = n0 + tid;
        int t = p / JDIM, j = p - t * JDIM;
        float sy = (t + 0.5f) * (43.0f / 128.0f) - 0.5f;
        sy = fminf(fmaxf(sy, 0.f), 42.f);
        int y0 = (int)sy;
        iy0[tid] = y0; iy1[tid] = min(y0 + 1, 42); fwy[tid] = sy - y0;
        float sx = (j + 0.5f) * (6.0f / 17.0f) - 0.5f;
        sx = fminf(fmaxf(sx, 0.f), 5.f);
        int x0 = (int)sx;
        ix0[tid] = x0; ix1[tid] = min(x0 + 1, 5); fwx[tid] = sx - x0;
    }
    __syncthreads();

    float acc[4][4];
#pragma unroll
    for (int u = 0; u < 4; u++)
#pragma unroll
        for (int v2 = 0; v2 < 4; v2++) acc[u][v2] = 0.f;

    const int ty = tid >> 4, tx = tid & 15;

    for (int kc = 0; kc < 256; kc += 64) {
        for (int e = tid; e < 4096; e += 256) {
            int mm = e >> 6, kk = e & 63;
            Ws[mm][kk] = pw[(size_t)(m0 + mm) * 256 + kc + kk];
        }
        for (int e = tid; e < 4096; e += 256) {
            int kk = e >> 6, nn = e & 63;
            int i = kc + kk;
            const float* base = g_att + (size_t)b * HW * CDIM + i;
            int y0 = iy0[nn], y1 = iy1[nn], x0 = ix0[nn], x1i = ix1[nn];
            float wy = fwy[nn], wx = fwx[nn];
            float a00 = base[(size_t)(y0 * WCC + x0) * CDIM];
            float a01 = base[(size_t)(y0 * WCC + x1i) * CDIM];
            float a10 = base[(size_t)(y1 * WCC + x0) * CDIM];
            float a11 = base[(size_t)(y1 * WCC + x1i) * CDIM];
            Xs[kk][nn] = (a00 * (1.f - wx) + a01 * wx) * (1.f - wy)
                       + (a10 * (1.f - wx) + a11 * wx) * wy;
        }
        __syncthreads();
#pragma unroll
        for (int kk = 0; kk < 64; kk++) {
            float a[4], bb[4];
#pragma unroll
            for (int u = 0; u < 4; u++) a[u] = Ws[ty * 4 + u][kk];
#pragma unroll
            for (int u = 0; u < 4; u++) bb[u] = Xs[kk][tx * 4 + u];
#pragma unroll
            for (int u = 0; u < 4; u++)
#pragma unroll
                for (int v2 = 0; v2 < 4; v2++) acc[u][v2] += a[u] * bb[v2];
        }
        __syncthreads();
    }

#pragma unroll
    for (int u = 0; u < 4; u++) {
        int c = m0 + ty * 4 + u;
        float bias = pb[c];
#pragma unroll
        for (int v2 = 0; v2 < 4; v2++) {
            int p = n0 + tx * 4 + v2;
            size_t idx = ((size_t)b * CDIM + c) * TJ + p;
            x1[idx] = acc[u][v2] + bias + x[idx];
        }
    }
}

// ---------------------------------------------------------------------------
// K4: out = x1 + bn2(fc2(gelu(bn1(fc1(n2bn(x1))))))
// Fused double GEMM; 32 positions per block, hidden chunked by 32, never
// materializing the 570MB hidden tensor. In-place on d_out (disjoint slabs
// per block, all reads of a slab precede its writes).
// ---------------------------------------------------------------------------
__global__ void __launch_bounds__(256) k_mlp(
    const float* x1,
    const float* __restrict__ w1, const float* __restrict__ fb1,
    const float* __restrict__ b1g, const float* __restrict__ b1b,
    const float* __restrict__ b1m, const float* __restrict__ b1v,
    const float* __restrict__ w2, const float* __restrict__ fb2,
    const float* __restrict__ b2g, const float* __restrict__ b2b,
    const float* __restrict__ b2m, const float* __restrict__ b2v,
    const float* __restrict__ n2g, const float* __restrict__ n2b,
    const float* __restrict__ n2m, const float* __restrict__ n2v,
    float* out)
{
    extern __shared__ float sm[];
    float* xa  = sm;                  // [32][260]  n2bn(x1) tile
    float* hsm = xa + 32 * 260;       // [32][36]   hidden chunk, [jl][p] layout
    float* w2s = hsm + 32 * 36;       // [32][257]  W2 chunk transposed
    float* s1c = w2s + 32 * 257;      // [32]
    float* t1c = s1c + 32;            // [32]

    const int blk = blockIdx.x;
    const int b = blk / 68;                 // 2176/32 = 68 tiles per batch
    const int p0 = (blk - b * 68) * 32;
    const int tid = threadIdx.x;
    const int lane = tid & 31;
    const int wp = tid >> 5;

    const float* xb = x1 + (size_t)b * CDIM * TJ;

    for (int e = tid; e < 32 * 256; e += 256) {
        int pp = e & 31, i = e >> 5;
        float s = n2g[i] * rsqrtf(n2v[i] + 1e-5f);
        float t = n2b[i] - n2m[i] * s;
        xa[pp * 260 + i] = xb[(size_t)i * TJ + p0 + pp] * s + t;
    }
    __syncthreads();

    float y[32];
#pragma unroll
    for (int p = 0; p < 32; p++) y[p] = 0.f;
    const int c = tid;

    for (int jc = 0; jc < HIDDEN; jc += 32) {
        if (tid < 32) {   // bn1 fold (incl. fc1 bias) for this hidden chunk
            int j = jc + tid;
            float s = b1g[j] * rsqrtf(b1v[j] + 1e-5f);
            s1c[tid] = s;
            t1c[tid] = b1b[j] - b1m[j] * s + fb1[j] * s;
        }
        for (int e = tid; e < 32 * 256; e += 256) {   // stage W2 chunk transposed
            int jl = e & 31, c2 = e >> 5;
            w2s[jl * 257 + c2] = w2[(size_t)c2 * HIDDEN + jc + jl];
        }
        __syncthreads();

        // hidden: thread (p=lane, j = jc + wp*4 + 0..3), W1 reads warp-uniform
        float h0 = 0.f, h1 = 0.f, h2 = 0.f, h3 = 0.f;
        const float* w1r = w1 + (size_t)(jc + wp * 4) * 256;
#pragma unroll 4
        for (int i = 0; i < 256; i += 4) {
            float4 xv = *(const float4*)&xa[lane * 260 + i];
            float4 a0 = *(const float4*)&w1r[i];
            float4 a1 = *(const float4*)&w1r[256 + i];
            float4 a2 = *(const float4*)&w1r[512 + i];
            float4 a3 = *(const float4*)&w1r[768 + i];
            h0 += xv.x * a0.x + xv.y * a0.y + xv.z * a0.z + xv.w * a0.w;
            h1 += xv.x * a1.x + xv.y * a1.y + xv.z * a1.z + xv.w * a1.w;
            h2 += xv.x * a2.x + xv.y * a2.y + xv.z * a2.z + xv.w * a2.w;
            h3 += xv.x * a3.x + xv.y * a3.y + xv.z * a3.z + xv.w * a3.w;
        }
        {
            int jl = wp * 4;
            hsm[(jl + 0) * 36 + lane] = gelu_exact(h0 * s1c[jl + 0] + t1c[jl + 0]);
            hsm[(jl + 1) * 36 + lane] = gelu_exact(h1 * s1c[jl + 1] + t1c[jl + 1]);
            hsm[(jl + 2) * 36 + lane] = gelu_exact(h2 * s1c[jl + 2] + t1c[jl + 2]);
            hsm[(jl + 3) * 36 + lane] = gelu_exact(h3 * s1c[jl + 3] + t1c[jl + 3]);
        }
        __syncthreads();

        // y accumulate: thread owns output channel c over 32 positions
#pragma unroll 2
        for (int jl = 0; jl < 32; jl++) {
            float wv = w2s[jl * 257 + c];
            const float4* hp = (const float4*)&hsm[jl * 36];
#pragma unroll
            for (int p4 = 0; p4 < 8; p4++) {
                float4 hv = hp[p4];
                y[p4 * 4 + 0] += wv * hv.x;
                y[p4 * 4 + 1] += wv * hv.y;
                y[p4 * 4 + 2] += wv * hv.z;
                y[p4 * 4 + 3] += wv * hv.w;
            }
        }
        __syncthreads();
    }

    float s2 = b2g[c] * rsqrtf(b2v[c] + 1e-5f);
    float t2 = b2b[c] - b2m[c] * s2 + fb2[c] * s2;
    const float* xr = xb + (size_t)c * TJ + p0;
    float* ob = out + ((size_t)b * CDIM + c) * TJ + p0;
#pragma unroll
    for (int p = 0; p < 32; p++) ob[p] = xr[p] + y[p] * s2 + t2;
}

// ---------------------------------------------------------------------------
extern "C" void kernel_launch(void* const* d_in, const int* in_sizes, int n_in,
                              void* d_out, int out_size)
{
    const float* x    = (const float*)d_in[0];
    const float* n1g  = (const float*)d_in[1];
    const float* n1b  = (const float*)d_in[2];
    const float* n1m  = (const float*)d_in[3];
    const float* n1v  = (const float*)d_in[4];
    const float* qkvw = (const float*)d_in[5];
    const float* qg   = (const float*)d_in[6];
    const float* qb   = (const float*)d_in[7];
    const float* qm   = (const float*)d_in[8];
    const float* qv   = (const float*)d_in[9];
    const float* pw   = (const float*)d_in[10];
    const float* pb   = (const float*)d_in[11];
    const float* n2g  = (const float*)d_in[12];
    const float* n2b  = (const float*)d_in[13];
    const float* n2m  = (const float*)d_in[14];
    const float* n2v  = (const float*)d_in[15];
    const float* w1   = (const float*)d_in[16];
    const float* fb1  = (const float*)d_in[17];
    const float* b1g  = (const float*)d_in[18];
    const float* b1b  = (const float*)d_in[19];
    const float* b1m  = (const float*)d_in[20];
    const float* b1v  = (const float*)d_in[21];
    const float* w2   = (const float*)d_in[22];
    const float* fb2  = (const float*)d_in[23];
    const float* b2g  = (const float*)d_in[24];
    const float* b2b  = (const float*)d_in[25];
    const float* b2m  = (const float*)d_in[26];
    const float* b2v  = (const float*)d_in[27];
    float* out = (float*)d_out;

    const int attn_smem = 3 * 258 * 33 * 4;                         // 102168 B
    const int mlp_smem  = (32 * 260 + 32 * 36 + 32 * 257 + 64) * 4; // ~71 KB
    cudaFuncSetAttribute(k_attn, cudaFuncAttributeMaxDynamicSharedMemorySize, attn_smem);
    cudaFuncSetAttribute(k_mlp,  cudaFuncAttributeMaxDynamicSharedMemorySize, mlp_smem);

    k_conv_qkv<<<dim3(12, 5, 64), 256>>>(x, qkvw, n1g, n1b, n1m, n1v, qg, qb, qm, qv);
    k_attn<<<512, 256, attn_smem>>>();
    k_proj<<<dim3(4, 34, 64), 256>>>(pw, pb, x, out);
    k_mlp<<<4352, 256, mlp_smem>>>(out,
                                   w1, fb1, b1g, b1b, b1m, b1v,
                                   w2, fb2, b2g, b2b, b2m, b2v,
                                   n2g, n2b, n2m, n2v, out);
}

// round 3
// speedup vs baseline: 2.2204x; 2.2204x over previous
#include <cuda_runtime.h>
#include <cuda_fp16.h>
#include <math.h>
#include <stdint.h>

#define BATCH 64
#define CDIM 256
#define TDIM 128
#define JDIM 17
#define TJ 2176     // TDIM*JDIM
#define HCC 43
#define WCC 6
#define HW 258      // HCC*WCC
#define HIDDEN 1024

// scratch (static __device__ globals per harness rules)
__device__ float g_qkv[(size_t)3 * BATCH * HW * CDIM];   // [b][t(3)][hw][c]
__device__ float g_att[(size_t)BATCH * HW * CDIM];       // [b][hw][c]
// fp16 hi/lo split weights in per-tile row-major layouts
// W1 tile nt: [128 j_local][256 i]; W2 tile nt: [256 c][128 j_local]
__device__ __half g_w1h[8 * 32768];
__device__ __half g_w1l[8 * 32768];
__device__ __half g_w2h[8 * 32768];
__device__ __half g_w2l[8 * 32768];

__device__ __forceinline__ float gelu_exact(float v) {
    return 0.5f * v * (1.0f + erff(v * 0.70710678118654752f));
}

__device__ __forceinline__ uint32_t smem_u32(const void* p) {
    uint32_t a;
    asm("{ .reg .u64 t; cvta.to.shared.u64 t, %1; cvt.u32.u64 %0, t; }" : "=r"(a) : "l"(p));
    return a;
}

#define LDM_X4(r, addr) \
    asm volatile("ldmatrix.sync.aligned.m8n8.x4.shared.b16 {%0,%1,%2,%3}, [%4];" \
        : "=r"((r)[0]), "=r"((r)[1]), "=r"((r)[2]), "=r"((r)[3]) : "r"(addr))

#define MMA16816(d, a, b0, b1) \
    asm volatile("mma.sync.aligned.m16n8k16.row.col.f32.f16.f16.f32 " \
        "{%0,%1,%2,%3}, {%4,%5,%6,%7}, {%8,%9}, {%0,%1,%2,%3};" \
        : "+f"((d)[0]), "+f"((d)[1]), "+f"((d)[2]), "+f"((d)[3]) \
        : "r"((a)[0]), "r"((a)[1]), "r"((a)[2]), "r"((a)[3]), "r"(b0), "r"(b1))

// ---------------------------------------------------------------------------
// K0: pre-convert W1/W2 fp32 -> hi/lo fp16 tiles
// ---------------------------------------------------------------------------
__global__ void __launch_bounds__(256) k_prep(const float* __restrict__ w1,
                                              const float* __restrict__ w2)
{
    int idx = blockIdx.x * 256 + threadIdx.x;
    if (idx < 262144) {
        int j = idx >> 8, i = idx & 255;
        float v = w1[idx];
        __half h = __float2half(v);
        __half l = __float2half(v - __half2float(h));
        int nt = j >> 7, jl = j & 127;
        uint32_t off = (uint32_t)nt * 32768 + (uint32_t)jl * 256 + i;
        g_w1h[off] = h; g_w1l[off] = l;
    } else {
        int t = idx - 262144;
        int c = t >> 10, j = t & 1023;
        float v = w2[t];
        __half h = __float2half(v);
        __half l = __float2half(v - __half2float(h));
        int nt = j >> 7, jl = j & 127;
        uint32_t off = (uint32_t)nt * 32768 + (uint32_t)c * 128 + jl;
        g_w2h[off] = h; g_w2l[off] = l;
    }
}

// ---------------------------------------------------------------------------
// K1: qkv = gelu(qbn(conv3x3_s3(n1bn(x))))  (fp32 CUDA cores, unchanged)
// ---------------------------------------------------------------------------
__global__ void __launch_bounds__(256) k_conv_qkv(
    const float* __restrict__ x, const float* __restrict__ w,
    const float* __restrict__ n1g, const float* __restrict__ n1b,
    const float* __restrict__ n1m, const float* __restrict__ n1v,
    const float* __restrict__ qg, const float* __restrict__ qb,
    const float* __restrict__ qm, const float* __restrict__ qv)
{
    __shared__ float Ws[64][65];
    __shared__ float Xs[64][65];
    __shared__ float s_in[256], t_in[256];
    __shared__ float s_o[64], t_o[64];

    const int b  = blockIdx.z;
    const int m0 = blockIdx.x * 64;
    const int n0 = blockIdx.y * 64;
    const int tid = threadIdx.x;

    {
        float s = n1g[tid] * rsqrtf(n1v[tid] + 1e-5f);
        s_in[tid] = s;
        t_in[tid] = n1b[tid] - n1m[tid] * s;
    }
    if (tid < 64) {
        int o = m0 + tid;
        float s = qg[o] * rsqrtf(qv[o] + 1e-5f);
        s_o[tid] = s;
        t_o[tid] = qb[o] - qm[o] * s;
    }
    __syncthreads();

    float acc[4][4];
#pragma unroll
    for (int u = 0; u < 4; u++)
#pragma unroll
        for (int v2 = 0; v2 < 4; v2++) acc[u][v2] = 0.f;

    const int ty = tid >> 4, tx = tid & 15;

    for (int kc = 0; kc < 2304; kc += 64) {
        for (int e = tid; e < 4096; e += 256) {
            int mm = e >> 6, kk = e & 63;
            Ws[mm][kk] = w[(size_t)(m0 + mm) * 2304 + (kc + kk)];
        }
        for (int e = tid; e < 4096; e += 256) {
            int kk = e >> 6, nn = e & 63;
            int k = kc + kk;
            int i = k / 9;
            int rr = k - i * 9;
            int ky = rr / 3, kx = rr - ky * 3;
            int n = n0 + nn;
            float val = 0.f;
            if (n < HW) {
                int y = n / WCC, xj = n - y * WCC;
                int iy = 3 * y - 1 + ky;
                int ix = 3 * xj - 1 + kx;
                if (iy >= 0 && iy < TDIM && ix >= 0 && ix < JDIM) {
                    val = x[(((size_t)b * CDIM + i) * TDIM + iy) * JDIM + ix]
                              * s_in[i] + t_in[i];
                }
            }
            Xs[kk][nn] = val;
        }
        __syncthreads();
#pragma unroll
        for (int kk = 0; kk < 64; kk++) {
            float a[4], bb[4];
#pragma unroll
            for (int u = 0; u < 4; u++) a[u] = Ws[ty * 4 + u][kk];
#pragma unroll
            for (int u = 0; u < 4; u++) bb[u] = Xs[kk][tx * 4 + u];
#pragma unroll
            for (int u = 0; u < 4; u++)
#pragma unroll
                for (int v2 = 0; v2 < 4; v2++) acc[u][v2] += a[u] * bb[v2];
        }
        __syncthreads();
    }

#pragma unroll
    for (int u = 0; u < 4; u++) {
        int o = m0 + ty * 4 + u;
        int tpart = o >> 8;
        int cc = o & 255;
        float so = s_o[ty * 4 + u], to = t_o[ty * 4 + u];
        float* base = g_qkv + (((size_t)b * 3 + tpart) * HW) * CDIM + cc;
#pragma unroll
        for (int v2 = 0; v2 < 4; v2++) {
            int n = n0 + tx * 4 + v2;
            if (n < HW) base[(size_t)n * CDIM] = gelu_exact(acc[u][v2] * so + to);
        }
    }
}

// ---------------------------------------------------------------------------
// K2: attention (fp32, unchanged)
// ---------------------------------------------------------------------------
__global__ void __launch_bounds__(256) k_attn()
{
    extern __shared__ float sm[];
    float* qs = sm;
    float* ks = sm + 258 * 33;
    float* vs = sm + 2 * 258 * 33;

    const int bh = blockIdx.x;
    const int b = bh >> 3, h = bh & 7;
    const int tid = threadIdx.x;

    const float* qg = g_qkv + (((size_t)b * 3 + 0) * HW) * CDIM + h * 32;
    const float* kg = g_qkv + (((size_t)b * 3 + 1) * HW) * CDIM + h * 32;
    const float* vg = g_qkv + (((size_t)b * 3 + 2) * HW) * CDIM + h * 32;

    for (int e = tid; e < HW * 32; e += 256) {
        int r = e >> 5, d = e & 31;
        qs[r * 33 + d] = qg[(size_t)r * CDIM + d];
        ks[r * 33 + d] = kg[(size_t)r * CDIM + d];
        vs[r * 33 + d] = vg[(size_t)r * CDIM + d];
    }
    __syncthreads();

    const float scale = 0.17677669529663687f;

    for (int r = tid; r < HW; r += 256) {
        float qr[32];
#pragma unroll
        for (int d = 0; d < 32; d++) qr[d] = qs[r * 33 + d];
        float m = -1e30f, l = 0.f;
        float acc[32];
#pragma unroll
        for (int d = 0; d < 32; d++) acc[d] = 0.f;
        for (int j = 0; j < HW; j++) {
            const float* kj = ks + j * 33;
            float s = 0.f;
#pragma unroll
            for (int d = 0; d < 32; d++) s += qr[d] * kj[d];
            s *= scale;
            float mn = fmaxf(m, s);
            float corr = __expf(m - mn);
            float p = __expf(s - mn);
            l = l * corr + p;
            const float* vj = vs + j * 33;
#pragma unroll
            for (int d = 0; d < 32; d++) acc[d] = acc[d] * corr + p * vj[d];
            m = mn;
        }
        float inv = 1.f / l;
        float* og = g_att + ((size_t)b * HW + r) * CDIM + h * 32;
#pragma unroll
        for (int d = 0; d < 32; d++) og[d] = acc[d] * inv;
    }
}

// ---------------------------------------------------------------------------
// K3: x1 = x + proj1x1(bilinear_resize(att)) (fp32, unchanged)
// ---------------------------------------------------------------------------
__global__ void __launch_bounds__(256) k_proj(
    const float* __restrict__ pw, const float* __restrict__ pb,
    const float* __restrict__ x, float* __restrict__ x1)
{
    __shared__ float Ws[64][65];
    __shared__ float Xs[64][65];
    __shared__ int   iy0[64], iy1[64], ix0[64], ix1[64];
    __shared__ float fwy[64], fwx[64];

    const int b  = blockIdx.z;
    const int m0 = blockIdx.x * 64;
    const int n0 = blockIdx.y * 64;
    const int tid = threadIdx.x;

    if (tid < 64) {
        int p = n0 + tid;
        int t = p / JDIM, j = p - t * JDIM;
        float sy = (t + 0.5f) * (43.0f / 128.0f) - 0.5f;
        sy = fminf(fmaxf(sy, 0.f), 42.f);
        int y0 = (int)sy;
        iy0[tid] = y0; iy1[tid] = min(y0 + 1, 42); fwy[tid] = sy - y0;
        float sx = (j + 0.5f) * (6.0f / 17.0f) - 0.5f;
        sx = fminf(fmaxf(sx, 0.f), 5.f);
        int x0 = (int)sx;
        ix0[tid] = x0; ix1[tid] = min(x0 + 1, 5); fwx[tid] = sx - x0;
    }
    __syncthreads();

    float acc[4][4];
#pragma unroll
    for (int u = 0; u < 4; u++)
#pragma unroll
        for (int v2 = 0; v2 < 4; v2++) acc[u][v2] = 0.f;

    const int ty = tid >> 4, tx = tid & 15;

    for (int kc = 0; kc < 256; kc += 64) {
        for (int e = tid; e < 4096; e += 256) {
            int mm = e >> 6, kk = e & 63;
            Ws[mm][kk] = pw[(size_t)(m0 + mm) * 256 + kc + kk];
        }
        for (int e = tid; e < 4096; e += 256) {
            int kk = e >> 6, nn = e & 63;
            int i = kc + kk;
            const float* base = g_att + (size_t)b * HW * CDIM + i;
            int y0 = iy0[nn], y1 = iy1[nn], x0 = ix0[nn], x1i = ix1[nn];
            float wy = fwy[nn], wx = fwx[nn];
            float a00 = base[(size_t)(y0 * WCC + x0) * CDIM];
            float a01 = base[(size_t)(y0 * WCC + x1i) * CDIM];
            float a10 = base[(size_t)(y1 * WCC + x0) * CDIM];
            float a11 = base[(size_t)(y1 * WCC + x1i) * CDIM];
            Xs[kk][nn] = (a00 * (1.f - wx) + a01 * wx) * (1.f - wy)
                       + (a10 * (1.f - wx) + a11 * wx) * wy;
        }
        __syncthreads();
#pragma unroll
        for (int kk = 0; kk < 64; kk++) {
            float a[4], bb[4];
#pragma unroll
            for (int u = 0; u < 4; u++) a[u] = Ws[ty * 4 + u][kk];
#pragma unroll
            for (int u = 0; u < 4; u++) bb[u] = Xs[kk][tx * 4 + u];
#pragma unroll
            for (int u = 0; u < 4; u++)
#pragma unroll
                for (int v2 = 0; v2 < 4; v2++) acc[u][v2] += a[u] * bb[v2];
        }
        __syncthreads();
    }

#pragma unroll
    for (int u = 0; u < 4; u++) {
        int c = m0 + ty * 4 + u;
        float bias = pb[c];
#pragma unroll
        for (int v2 = 0; v2 < 4; v2++) {
            int p = n0 + tx * 4 + v2;
            size_t idx = ((size_t)b * CDIM + c) * TJ + p;
            x1[idx] = acc[u][v2] + bias + x[idx];
        }
    }
}

// ---------------------------------------------------------------------------
// K4: fused MLP on HMMA (mma.sync m16n8k16), fp16 activations,
// hi/lo-split fp16 weights. One CTA = 64 positions of one batch.
// GEMM1 per hidden tile: H[64x128] = Xn[64x256] @ W1t[128x256]^T (hi+lo)
// GEMM2: Y[64x256] += H[64x128] @ W2t[256x128]^T (hi+lo), Y in registers.
// ---------------------------------------------------------------------------
// smem byte offsets
#define SM_SN   0                         // float sn[256]
#define SM_TN   1024
#define SM_S2   2048
#define SM_T2   3072
#define SM_S1   4096                      // float s1[128]
#define SM_T1   4608
#define SM_XS   5120                      // [64][264] half  = 33792
#define SM_HS   (SM_XS + 33792)           // [64][136] half  = 17408
#define SM_WB   (SM_HS + 17408)           // 139264 (max of both uses)
#define SM_TOT  (SM_WB + 139264)          // 195584

#define W1_STRIDE 264
#define H_STRIDE  136
#define W1LO_OFF  67584                   // 128*264*2
#define W2LO_OFF  69632                   // 256*136*2

__global__ void __launch_bounds__(512, 1) k_mlp_mma(
    const float* x1,
    const float* __restrict__ b1g, const float* __restrict__ b1b,
    const float* __restrict__ b1m, const float* __restrict__ b1v,
    const float* __restrict__ fb1,
    const float* __restrict__ b2g, const float* __restrict__ b2b,
    const float* __restrict__ b2m, const float* __restrict__ b2v,
    const float* __restrict__ fb2,
    const float* __restrict__ n2g, const float* __restrict__ n2b,
    const float* __restrict__ n2m, const float* __restrict__ n2v,
    float* out)
{
    extern __shared__ char smem[];
    const uint32_t sbase = smem_u32(smem);
    const int tid = threadIdx.x;
    const int wid = tid >> 5;
    const int lane = tid & 31;
    const int wy = wid & 1;        // M: 2 x 32
    const int wx = wid >> 1;       // N: 8

    const int blk = blockIdx.x;
    const int b = blk / 34;
    const int p0 = (blk - b * 34) * 64;

    float* sn = (float*)(smem + SM_SN);
    float* tn = (float*)(smem + SM_TN);
    float* s2 = (float*)(smem + SM_S2);
    float* t2 = (float*)(smem + SM_T2);
    float* s1 = (float*)(smem + SM_S1);
    float* t1 = (float*)(smem + SM_T1);

    if (tid < 256) {
        float s = n2g[tid] * rsqrtf(n2v[tid] + 1e-5f);
        sn[tid] = s;
        tn[tid] = n2b[tid] - n2m[tid] * s;
    } else {
        int c = tid - 256;
        float s = b2g[c] * rsqrtf(b2v[c] + 1e-5f);
        s2[c] = s;
        t2[c] = b2b[c] - b2m[c] * s + fb2[c] * s;
    }
    __syncthreads();

    const float* xb = x1 + (size_t)b * CDIM * TJ;

    // ---- fill Xs: n2bn(x1) as fp16, [p 64][i 256] stride 264 ----
    for (int e = tid; e < 16384; e += 512) {
        int i = e >> 6, p = e & 63;
        float v = xb[(size_t)i * TJ + p0 + p] * sn[i] + tn[i];
        *(__half*)(smem + SM_XS + ((uint32_t)p * W1_STRIDE + i) * 2) = __float2half(v);
    }

    // ldmatrix lane address components
    const uint32_t a_row  = (lane & 7) + ((lane >> 3) & 1) * 8;
    const uint32_t a_koff = (lane >> 4) * 8;
    const uint32_t b_row  = (lane & 7) + (lane >> 4) * 8;
    const uint32_t b_koff = ((lane >> 3) & 1) * 8;

    const uint32_t xs_base = sbase + SM_XS;
    const uint32_t hs_base = sbase + SM_HS;
    const uint32_t wb_base = sbase + SM_WB;

    float d2[2][4][4];
#pragma unroll
    for (int i0 = 0; i0 < 2; i0++)
#pragma unroll
        for (int j0 = 0; j0 < 4; j0++)
#pragma unroll
            for (int q = 0; q < 4; q++) d2[i0][j0][q] = 0.f;

    for (int nt = 0; nt < 8; nt++) {
        __syncthreads();   // prev GEMM2 done with Wbuf & Hs

        // stage W1 hi/lo tiles: [128][256] -> stride 264
        {
            const uint4* srch = (const uint4*)(g_w1h + nt * 32768);
            const uint4* srcl = (const uint4*)(g_w1l + nt * 32768);
            for (int e = tid; e < 8192; e += 512) {
                int tile = e >> 12;
                int row = (e >> 5) & 127, col = e & 31;
                uint32_t doff = SM_WB + tile * W1LO_OFF
                              + ((uint32_t)row * W1_STRIDE + col * 8) * 2;
                *(uint4*)(smem + doff) = tile ? srcl[(e & 4095)] : srch[e];
            }
        }
        if (tid < 128) {
            int j = nt * 128 + tid;
            float s = b1g[j] * rsqrtf(b1v[j] + 1e-5f);
            s1[tid] = s;
            t1[tid] = b1b[j] - b1m[j] * s + fb1[j] * s;
        }
        __syncthreads();

        // ---- GEMM1: H = Xn @ W1t^T (hi + lo) ----
        float dH[2][2][4];
#pragma unroll
        for (int i0 = 0; i0 < 2; i0++)
#pragma unroll
            for (int j0 = 0; j0 < 2; j0++)
#pragma unroll
                for (int q = 0; q < 4; q++) dH[i0][j0][q] = 0.f;

#pragma unroll 4
        for (int k0 = 0; k0 < 256; k0 += 16) {
            uint32_t a[2][4];
#pragma unroll
            for (int mi = 0; mi < 2; mi++) {
                uint32_t addr = xs_base
                    + (((uint32_t)(wy * 32 + mi * 16) + a_row) * W1_STRIDE + k0 + a_koff) * 2;
                LDM_X4(a[mi], addr);
            }
            uint32_t bh[4], bl[4];
            {
                uint32_t roff = (((uint32_t)(wx * 16) + b_row) * W1_STRIDE + k0 + b_koff) * 2;
                LDM_X4(bh, wb_base + roff);
                LDM_X4(bl, wb_base + W1LO_OFF + roff);
            }
#pragma unroll
            for (int mi = 0; mi < 2; mi++) {
                MMA16816(dH[mi][0], a[mi], bh[0], bh[1]);
                MMA16816(dH[mi][1], a[mi], bh[2], bh[3]);
                MMA16816(dH[mi][0], a[mi], bl[0], bl[1]);
                MMA16816(dH[mi][1], a[mi], bl[2], bl[3]);
            }
        }

        // ---- epilogue1: gelu(bn1) -> Hs fp16 ----
        {
            int r = lane >> 2;
#pragma unroll
            for (int mi = 0; mi < 2; mi++) {
#pragma unroll
                for (int nf = 0; nf < 2; nf++) {
                    int c2 = wx * 16 + nf * 8 + (lane & 3) * 2;
                    float ss0 = s1[c2], tt0 = t1[c2];
                    float ss1 = s1[c2 + 1], tt1 = t1[c2 + 1];
                    int row0 = wy * 32 + mi * 16 + r;
                    float h0 = gelu_exact(dH[mi][nf][0] * ss0 + tt0);
                    float h1 = gelu_exact(dH[mi][nf][1] * ss1 + tt1);
                    float h2 = gelu_exact(dH[mi][nf][2] * ss0 + tt0);
                    float h3 = gelu_exact(dH[mi][nf][3] * ss1 + tt1);
                    *(__half2*)(smem + SM_HS + ((uint32_t)row0 * H_STRIDE + c2) * 2)
                        = __floats2half2_rn(h0, h1);
                    *(__half2*)(smem + SM_HS + ((uint32_t)(row0 + 8) * H_STRIDE + c2) * 2)
                        = __floats2half2_rn(h2, h3);
                }
            }
        }
        __syncthreads();   // Hs ready; done reading W1 tiles

        // stage W2 hi/lo tiles: [256][128] -> stride 136
        {
            const uint4* srch = (const uint4*)(g_w2h + nt * 32768);
            const uint4* srcl = (const uint4*)(g_w2l + nt * 32768);
            for (int e = tid; e < 8192; e += 512) {
                int tile = e >> 12;
                int row = (e >> 4) & 255, col = e & 15;
                uint32_t doff = SM_WB + tile * W2LO_OFF
                              + ((uint32_t)row * H_STRIDE + col * 8) * 2;
                *(uint4*)(smem + doff) = tile ? srcl[(e & 4095)] : srch[e];
            }
        }
        __syncthreads();

        // ---- GEMM2: Y += H @ W2t^T (hi + lo) ----
#pragma unroll
        for (int k0 = 0; k0 < 128; k0 += 16) {
            uint32_t a[2][4];
#pragma unroll
            for (int mi = 0; mi < 2; mi++) {
                uint32_t addr = hs_base
                    + (((uint32_t)(wy * 32 + mi * 16) + a_row) * H_STRIDE + k0 + a_koff) * 2;
                LDM_X4(a[mi], addr);
            }
#pragma unroll
            for (int nq = 0; nq < 2; nq++) {
                uint32_t roff = (((uint32_t)(wx * 32 + nq * 16) + b_row) * H_STRIDE
                                 + k0 + b_koff) * 2;
                uint32_t bh[4], bl[4];
                LDM_X4(bh, wb_base + roff);
                LDM_X4(bl, wb_base + W2LO_OFF + roff);
#pragma unroll
                for (int mi = 0; mi < 2; mi++) {
                    MMA16816(d2[mi][nq * 2 + 0], a[mi], bh[0], bh[1]);
                    MMA16816(d2[mi][nq * 2 + 1], a[mi], bh[2], bh[3]);
                    MMA16816(d2[mi][nq * 2 + 0], a[mi], bl[0], bl[1]);
                    MMA16816(d2[mi][nq * 2 + 1], a[mi], bl[2], bl[3]);
                }
            }
        }
    }

    // ---- final epilogue: stage Y in smem (reuse Wbuf), then coalesced out ----
    __syncthreads();   // everyone done reading Wbuf
    float* stage = (float*)(smem + SM_WB);   // [64][257]
    {
        int r = lane >> 2;
#pragma unroll
        for (int mi = 0; mi < 2; mi++) {
            int row0 = wy * 32 + mi * 16 + r;
#pragma unroll
            for (int j0 = 0; j0 < 4; j0++) {
                int c = wx * 32 + j0 * 8 + (lane & 3) * 2;
                stage[row0 * 257 + c]       = d2[mi][j0][0];
                stage[row0 * 257 + c + 1]   = d2[mi][j0][1];
                stage[(row0 + 8) * 257 + c]     = d2[mi][j0][2];
                stage[(row0 + 8) * 257 + c + 1] = d2[mi][j0][3];
            }
        }
    }
    __syncthreads();

    for (int e = tid; e < 16384; e += 512) {
        int c = e >> 6, p = e & 63;
        size_t idx = ((size_t)b * CDIM + c) * TJ + p0 + p;
        out[idx] = x1[idx] + stage[p * 257 + c] * s2[c] + t2[c];
    }
}

// ---------------------------------------------------------------------------
extern "C" void kernel_launch(void* const* d_in, const int* in_sizes, int n_in,
                              void* d_out, int out_size)
{
    const float* x    = (const float*)d_in[0];
    const float* n1g  = (const float*)d_in[1];
    const float* n1b  = (const float*)d_in[2];
    const float* n1m  = (const float*)d_in[3];
    const float* n1v  = (const float*)d_in[4];
    const float* qkvw = (const float*)d_in[5];
    const float* qg   = (const float*)d_in[6];
    const float* qb   = (const float*)d_in[7];
    const float* qm   = (const float*)d_in[8];
    const float* qv   = (const float*)d_in[9];
    const float* pw   = (const float*)d_in[10];
    const float* pb   = (const float*)d_in[11];
    const float* n2g  = (const float*)d_in[12];
    const float* n2b  = (const float*)d_in[13];
    const float* n2m  = (const float*)d_in[14];
    const float* n2v  = (const float*)d_in[15];
    const float* w1   = (const float*)d_in[16];
    const float* fb1  = (const float*)d_in[17];
    const float* b1g  = (const float*)d_in[18];
    const float* b1b  = (const float*)d_in[19];
    const float* b1m  = (const float*)d_in[20];
    const float* b1v  = (const float*)d_in[21];
    const float* w2   = (const float*)d_in[22];
    const float* fb2  = (const float*)d_in[23];
    const float* b2g  = (const float*)d_in[24];
    const float* b2b  = (const float*)d_in[25];
    const float* b2m  = (const float*)d_in[26];
    const float* b2v  = (const float*)d_in[27];
    float* out = (float*)d_out;

    const int attn_smem = 3 * 258 * 33 * 4;
    cudaFuncSetAttribute(k_attn,    cudaFuncAttributeMaxDynamicSharedMemorySize, attn_smem);
    cudaFuncSetAttribute(k_mlp_mma, cudaFuncAttributeMaxDynamicSharedMemorySize, SM_TOT);

    k_prep<<<2048, 256>>>(w1, w2);
    k_conv_qkv<<<dim3(12, 5, 64), 256>>>(x, qkvw, n1g, n1b, n1m, n1v, qg, qb, qm, qv);
    k_attn<<<512, 256, attn_smem>>>();
    k_proj<<<dim3(4, 34, 64), 256>>>(pw, pb, x, out);
    k_mlp_mma<<<2176, 512, SM_TOT>>>(out,
                                     b1g, b1b, b1m, b1v, fb1,
                                     b2g, b2b, b2m, b2v, fb2,
                                     n2g, n2b, n2m, n2v, out);
}

// round 4
// speedup vs baseline: 2.9223x; 1.3161x over previous
#include <cuda_runtime.h>
#include <cuda_fp16.h>
#include <math.h>
#include <stdint.h>

#define BATCH 64
#define CDIM 256
#define TDIM 128
#define JDIM 17
#define TJ 2176     // TDIM*JDIM
#define HCC 43
#define WCC 6
#define HW 258      // HCC*WCC
#define HIDDEN 1024

// scratch (static __device__ globals per harness rules)
__device__ float g_qkv[(size_t)3 * BATCH * HW * CDIM];   // [b][t(3)][hw][c]
__device__ float g_att[(size_t)BATCH * HW * CDIM];       // [b][hw][c]
// fp16 hi/lo split weights
__device__ __half g_w1h[8 * 32768];            // W1 per-tile layout
__device__ __half g_w1l[8 * 32768];
__device__ __half g_w2h[8 * 32768];            // W2 per-tile layout
__device__ __half g_w2l[8 * 32768];
__device__ __half g_qwh[768 * 2304];           // qkv conv weight row-major
__device__ __half g_qwl[768 * 2304];
__device__ __half g_pwh[256 * 256];            // proj weight row-major
__device__ __half g_pwl[256 * 256];

__device__ __forceinline__ float gelu_exact(float v) {
    return 0.5f * v * (1.0f + erff(v * 0.70710678118654752f));
}

__device__ __forceinline__ uint32_t smem_u32(const void* p) {
    uint32_t a;
    asm("{ .reg .u64 t; cvta.to.shared.u64 t, %1; cvt.u32.u64 %0, t; }" : "=r"(a) : "l"(p));
    return a;
}

#define LDM_X4(r, addr) \
    asm volatile("ldmatrix.sync.aligned.m8n8.x4.shared.b16 {%0,%1,%2,%3}, [%4];" \
        : "=r"((r)[0]), "=r"((r)[1]), "=r"((r)[2]), "=r"((r)[3]) : "r"(addr))

#define MMA16816(d, a, b0, b1) \
    asm volatile("mma.sync.aligned.m16n8k16.row.col.f32.f16.f16.f32 " \
        "{%0,%1,%2,%3}, {%4,%5,%6,%7}, {%8,%9}, {%0,%1,%2,%3};" \
        : "+f"((d)[0]), "+f"((d)[1]), "+f"((d)[2]), "+f"((d)[3]) \
        : "r"((a)[0]), "r"((a)[1]), "r"((a)[2]), "r"((a)[3]), "r"(b0), "r"(b1))

// ---------------------------------------------------------------------------
// K0: pre-convert all weights fp32 -> hi/lo fp16
// ---------------------------------------------------------------------------
__global__ void __launch_bounds__(256) k_prep(const float* __restrict__ w1,
                                              const float* __restrict__ w2,
                                              const float* __restrict__ qkvw,
                                              const float* __restrict__ pw)
{
    int idx = blockIdx.x * 256 + threadIdx.x;
    if (idx < 262144) {
        int j = idx >> 8, i = idx & 255;
        float v = w1[idx];
        __half h = __float2half(v);
        __half l = __float2half(v - __half2float(h));
        int nt = j >> 7, jl = j & 127;
        uint32_t off = (uint32_t)nt * 32768 + (uint32_t)jl * 256 + i;
        g_w1h[off] = h; g_w1l[off] = l;
    } else if (idx < 524288) {
        int t = idx - 262144;
        int c = t >> 10, j = t & 1023;
        float v = w2[t];
        __half h = __float2half(v);
        __half l = __float2half(v - __half2float(h));
        int nt = j >> 7, jl = j & 127;
        uint32_t off = (uint32_t)nt * 32768 + (uint32_t)c * 128 + jl;
        g_w2h[off] = h; g_w2l[off] = l;
    } else if (idx < 524288 + 1769472) {
        int t = idx - 524288;
        float v = qkvw[t];
        __half h = __float2half(v);
        __half l = __float2half(v - __half2float(h));
        g_qwh[t] = h; g_qwl[t] = l;
    } else {
        int t = idx - (524288 + 1769472);
        float v = pw[t];
        __half h = __float2half(v);
        __half l = __float2half(v - __half2float(h));
        g_pwh[t] = h; g_pwl[t] = l;
    }
}

// ---------------------------------------------------------------------------
// K1: conv QKV on HMMA. C[oc 768][g 16512] = W[oc][k 2304] . P[g][k]
// CTA: M=128 oc x N=128 positions, K chunks of 64. BN-folded im2col gather.
// epilogue: gelu(qbn(.)) staged in smem, coalesced write to g_qkv fp32.
// ---------------------------------------------------------------------------
#define CV_SIN   0
#define CV_TIN   1024
#define CV_SO    2048
#define CV_TO    2560
#define CV_KTAB  3072          // uint16[2304] = 4608
#define CV_GXO   7680          // int[128]
#define CV_GY    8192          // int16[128]
#define CV_GX    8448          // int16[128]
#define CV_WS    8704          // hi 128*72*2=18432, lo +18432 -> 45568
#define CV_PS    45568         // 128*72*2 = 18432 -> 64000
#define CV_STAGE CV_WS         // float[128*129] = 66048 -> 74752
#define CV_TOT   74752

__global__ void __launch_bounds__(512, 1) k_conv_mma(
    const float* __restrict__ x,
    const float* __restrict__ n1g, const float* __restrict__ n1b,
    const float* __restrict__ n1m, const float* __restrict__ n1v,
    const float* __restrict__ qg, const float* __restrict__ qb,
    const float* __restrict__ qm, const float* __restrict__ qv)
{
    extern __shared__ char smem[];
    const uint32_t sbase = smem_u32(smem);
    const int tid = threadIdx.x;
    const int wid = tid >> 5, lane = tid & 31;
    const int wy = wid & 1, wx = wid >> 1;

    const int m0 = blockIdx.x * 128;   // out-channel base (multiple of 128)
    const int n0 = blockIdx.y * 128;   // global position base

    float*    s_in = (float*)(smem + CV_SIN);
    float*    t_in = (float*)(smem + CV_TIN);
    float*    s_o  = (float*)(smem + CV_SO);
    float*    t_o  = (float*)(smem + CV_TO);
    uint16_t* ktab = (uint16_t*)(smem + CV_KTAB);
    int*      gxo  = (int*)(smem + CV_GXO);
    int16_t*  gyv  = (int16_t*)(smem + CV_GY);
    int16_t*  gxv  = (int16_t*)(smem + CV_GX);

    if (tid < 256) {
        float s = n1g[tid] * rsqrtf(n1v[tid] + 1e-5f);
        s_in[tid] = s;
        t_in[tid] = n1b[tid] - n1m[tid] * s;
    } else if (tid < 384) {
        int o = m0 + tid - 256;
        float s = qg[o] * rsqrtf(qv[o] + 1e-5f);
        s_o[tid - 256] = s;
        t_o[tid - 256] = qb[o] - qm[o] * s;
    } else if (tid < 512) {
        int gl = tid - 384;
        int g = n0 + gl;
        int b = g / HW, hw = g - b * HW;
        int y = hw / WCC, xx = hw - y * WCC;
        gxo[gl] = b * (CDIM * TJ);
        gyv[gl] = (int16_t)(3 * y - 1);
        gxv[gl] = (int16_t)(3 * xx - 1);
    }
    for (int k = tid; k < 2304; k += 512) {
        int i = k / 9, r = k - i * 9;
        int ky = r / 3, kx = r - ky * 3;
        ktab[k] = (uint16_t)((i << 4) | (ky << 2) | kx);
    }
    __syncthreads();

    const uint32_t a_row  = (lane & 7) + ((lane >> 3) & 1) * 8;
    const uint32_t a_koff = (lane >> 4) * 8;
    const uint32_t b_row  = (lane & 7) + (lane >> 4) * 8;
    const uint32_t b_koff = ((lane >> 3) & 1) * 8;

    const uint32_t ws_base = sbase + CV_WS;
    const uint32_t ps_base = sbase + CV_PS;

    float d[4][2][4];
#pragma unroll
    for (int mi = 0; mi < 4; mi++)
#pragma unroll
        for (int nf = 0; nf < 2; nf++)
#pragma unroll
            for (int q = 0; q < 4; q++) d[mi][nf][q] = 0.f;

    for (int kc = 0; kc < 2304; kc += 64) {
        // stage W hi/lo tiles [128][64] stride 72
        for (int e = tid; e < 2048; e += 512) {
            int hs = e >> 10;
            int row = (e >> 3) & 127, col = e & 7;
            const __half* src = hs ? g_qwl : g_qwh;
            *(uint4*)(smem + CV_WS + hs * 18432 + ((uint32_t)row * 72 + col * 8) * 2)
                = *(const uint4*)(src + (size_t)(m0 + row) * 2304 + kc + col * 8);
        }
        // stage P: BN-folded im2col gather [128 g][64 k] stride 72
        for (int e = tid; e < 8192; e += 512) {
            int kk = e & 63, gl = e >> 6;
            uint32_t kt = ktab[kc + kk];
            int i = kt >> 4, ky = (kt >> 2) & 3, kx = kt & 3;
            int iy = gyv[gl] + ky, ix = gxv[gl] + kx;
            float v = 0.f;
            if ((unsigned)iy < (unsigned)TDIM && (unsigned)ix < (unsigned)JDIM)
                v = x[gxo[gl] + i * TJ + iy * JDIM + ix] * s_in[i] + t_in[i];
            *(__half*)(smem + CV_PS + ((uint32_t)gl * 72 + kk) * 2) = __float2half(v);
        }
        __syncthreads();
#pragma unroll
        for (int ks = 0; ks < 4; ks++) {
            const int k0 = ks * 16;
            uint32_t bb[4];
            LDM_X4(bb, ps_base + (((uint32_t)(wx * 16) + b_row) * 72 + k0 + b_koff) * 2);
            uint32_t a[4][4];
#pragma unroll
            for (int mi = 0; mi < 4; mi++)
                LDM_X4(a[mi], ws_base + (((uint32_t)(wy * 64 + mi * 16) + a_row) * 72
                                          + k0 + a_koff) * 2);
#pragma unroll
            for (int mi = 0; mi < 4; mi++) {
                MMA16816(d[mi][0], a[mi], bb[0], bb[1]);
                MMA16816(d[mi][1], a[mi], bb[2], bb[3]);
            }
#pragma unroll
            for (int mi = 0; mi < 4; mi++)
                LDM_X4(a[mi], ws_base + 18432 + (((uint32_t)(wy * 64 + mi * 16) + a_row) * 72
                                                  + k0 + a_koff) * 2);
#pragma unroll
            for (int mi = 0; mi < 4; mi++) {
                MMA16816(d[mi][0], a[mi], bb[0], bb[1]);
                MMA16816(d[mi][1], a[mi], bb[2], bb[3]);
            }
        }
        __syncthreads();
    }

    // stage accumulators: stage[gl * 129 + cl]
    float* stage = (float*)(smem + CV_STAGE);
    {
        int r = lane >> 2, c2 = (lane & 3) * 2;
#pragma unroll
        for (int mi = 0; mi < 4; mi++) {
            int row = wy * 64 + mi * 16 + r;
#pragma unroll
            for (int nf = 0; nf < 2; nf++) {
                int col = wx * 16 + nf * 8 + c2;
                stage[col * 129 + row]           = d[mi][nf][0];
                stage[(col + 1) * 129 + row]     = d[mi][nf][1];
                stage[col * 129 + row + 8]       = d[mi][nf][2];
                stage[(col + 1) * 129 + row + 8] = d[mi][nf][3];
            }
        }
    }
    __syncthreads();

    // coalesced write: gelu(qbn(acc)) -> g_qkv[b][t][hw][c]
    const int tpart = m0 >> 8;
    const int cbase = m0 & 255;
    for (int e = tid; e < 16384; e += 512) {
        int gl = e >> 7, cl = e & 127;
        int g = n0 + gl;
        int b = g / HW, hw = g - b * HW;
        float v = stage[gl * 129 + cl] * s_o[cl] + t_o[cl];
        g_qkv[(((size_t)b * 3 + tpart) * HW + hw) * CDIM + cbase + cl] = gelu_exact(v);
    }
}

// ---------------------------------------------------------------------------
// K2: attention (fp32, unchanged)
// ---------------------------------------------------------------------------
__global__ void __launch_bounds__(256) k_attn()
{
    extern __shared__ float sm[];
    float* qs = sm;
    float* ks = sm + 258 * 33;
    float* vs = sm + 2 * 258 * 33;

    const int bh = blockIdx.x;
    const int b = bh >> 3, h = bh & 7;
    const int tid = threadIdx.x;

    const float* qg = g_qkv + (((size_t)b * 3 + 0) * HW) * CDIM + h * 32;
    const float* kg = g_qkv + (((size_t)b * 3 + 1) * HW) * CDIM + h * 32;
    const float* vg = g_qkv + (((size_t)b * 3 + 2) * HW) * CDIM + h * 32;

    for (int e = tid; e < HW * 32; e += 256) {
        int r = e >> 5, d = e & 31;
        qs[r * 33 + d] = qg[(size_t)r * CDIM + d];
        ks[r * 33 + d] = kg[(size_t)r * CDIM + d];
        vs[r * 33 + d] = vg[(size_t)r * CDIM + d];
    }
    __syncthreads();

    const float scale = 0.17677669529663687f;

    for (int r = tid; r < HW; r += 256) {
        float qr[32];
#pragma unroll
        for (int d = 0; d < 32; d++) qr[d] = qs[r * 33 + d];
        float m = -1e30f, l = 0.f;
        float acc[32];
#pragma unroll
        for (int d = 0; d < 32; d++) acc[d] = 0.f;
        for (int j = 0; j < HW; j++) {
            const float* kj = ks + j * 33;
            float s = 0.f;
#pragma unroll
            for (int d = 0; d < 32; d++) s += qr[d] * kj[d];
            s *= scale;
            float mn = fmaxf(m, s);
            float corr = __expf(m - mn);
            float p = __expf(s - mn);
            l = l * corr + p;
            const float* vj = vs + j * 33;
#pragma unroll
            for (int d = 0; d < 32; d++) acc[d] = acc[d] * corr + p * vj[d];
            m = mn;
        }
        float inv = 1.f / l;
        float* og = g_att + ((size_t)b * HW + r) * CDIM + h * 32;
#pragma unroll
        for (int d = 0; d < 32; d++) og[d] = acc[d] * inv;
    }
}

// ---------------------------------------------------------------------------
// K3: proj on HMMA. x1 = x + proj1x1(bilinear(att)). CTA: 128 ch x 128 pos.
// ---------------------------------------------------------------------------
#define PJ_PB    0             // float[128]
#define PJ_O00   512
#define PJ_O01   1024
#define PJ_O10   1536
#define PJ_O11   2048
#define PJ_WXT   2560
#define PJ_WYT   3072
#define PJ_WS    3584          // hi 18432, lo +18432 -> 40448
#define PJ_PS    40448         // 18432 -> 58880
#define PJ_STAGE PJ_WS         // 3584 + 66048 = 69632
#define PJ_TOT   69632

__global__ void __launch_bounds__(512, 1) k_proj_mma(
    const float* __restrict__ pb,
    const float* __restrict__ x, float* __restrict__ x1)
{
    extern __shared__ char smem[];
    const uint32_t sbase = smem_u32(smem);
    const int tid = threadIdx.x;
    const int wid = tid >> 5, lane = tid & 31;
    const int wy = wid & 1, wx = wid >> 1;

    const int m0 = blockIdx.x * 128;            // channel base
    const int b  = blockIdx.y / 17;
    const int p0 = (blockIdx.y - b * 17) * 128; // position base within batch

    float* pbs = (float*)(smem + PJ_PB);
    int*   o00 = (int*)(smem + PJ_O00);
    int*   o01 = (int*)(smem + PJ_O01);
    int*   o10 = (int*)(smem + PJ_O10);
    int*   o11 = (int*)(smem + PJ_O11);
    float* wxs = (float*)(smem + PJ_WXT);
    float* wys = (float*)(smem + PJ_WYT);

    if (tid < 128) {
        int p = p0 + tid;
        int t = p / JDIM, j = p - t * JDIM;
        float sy = (t + 0.5f) * (43.0f / 128.0f) - 0.5f;
        sy = fminf(fmaxf(sy, 0.f), 42.f);
        int y0 = (int)sy;
        int y1 = min(y0 + 1, 42);
        float fy = sy - y0;
        float sx = (j + 0.5f) * (6.0f / 17.0f) - 0.5f;
        sx = fminf(fmaxf(sx, 0.f), 5.f);
        int x0 = (int)sx;
        int x1i = min(x0 + 1, 5);
        float fx = sx - x0;
        o00[tid] = (y0 * WCC + x0) * CDIM;
        o01[tid] = (y0 * WCC + x1i) * CDIM;
        o10[tid] = (y1 * WCC + x0) * CDIM;
        o11[tid] = (y1 * WCC + x1i) * CDIM;
        wxs[tid] = fx;
        wys[tid] = fy;
    } else if (tid < 256) {
        pbs[tid - 128] = pb[m0 + tid - 128];
    }
    __syncthreads();

    const uint32_t a_row  = (lane & 7) + ((lane >> 3) & 1) * 8;
    const uint32_t a_koff = (lane >> 4) * 8;
    const uint32_t b_row  = (lane & 7) + (lane >> 4) * 8;
    const uint32_t b_koff = ((lane >> 3) & 1) * 8;

    const uint32_t ws_base = sbase + PJ_WS;
    const uint32_t ps_base = sbase + PJ_PS;
    const float* abase = g_att + (size_t)b * HW * CDIM;

    float d[4][2][4];
#pragma unroll
    for (int mi = 0; mi < 4; mi++)
#pragma unroll
        for (int nf = 0; nf < 2; nf++)
#pragma unroll
            for (int q = 0; q < 4; q++) d[mi][nf][q] = 0.f;

    for (int kc = 0; kc < 256; kc += 64) {
        for (int e = tid; e < 2048; e += 512) {
            int hs = e >> 10;
            int row = (e >> 3) & 127, col = e & 7;
            const __half* src = hs ? g_pwl : g_pwh;
            *(uint4*)(smem + PJ_WS + hs * 18432 + ((uint32_t)row * 72 + col * 8) * 2)
                = *(const uint4*)(src + (size_t)(m0 + row) * 256 + kc + col * 8);
        }
        for (int e = tid; e < 8192; e += 512) {
            int kk = e & 63, gl = e >> 6;
            const float* bp = abase + (kc + kk);
            float fx = wxs[gl], fy = wys[gl];
            float a00 = bp[o00[gl]];
            float a01 = bp[o01[gl]];
            float a10 = bp[o10[gl]];
            float a11 = bp[o11[gl]];
            float v = (a00 * (1.f - fx) + a01 * fx) * (1.f - fy)
                    + (a10 * (1.f - fx) + a11 * fx) * fy;
            *(__half*)(smem + PJ_PS + ((uint32_t)gl * 72 + kk) * 2) = __float2half(v);
        }
        __syncthreads();
#pragma unroll
        for (int ks = 0; ks < 4; ks++) {
            const int k0 = ks * 16;
            uint32_t bb[4];
            LDM_X4(bb, ps_base + (((uint32_t)(wx * 16) + b_row) * 72 + k0 + b_koff) * 2);
            uint32_t a[4][4];
#pragma unroll
            for (int mi = 0; mi < 4; mi++)
                LDM_X4(a[mi], ws_base + (((uint32_t)(wy * 64 + mi * 16) + a_row) * 72
                                          + k0 + a_koff) * 2);
#pragma unroll
            for (int mi = 0; mi < 4; mi++) {
                MMA16816(d[mi][0], a[mi], bb[0], bb[1]);
                MMA16816(d[mi][1], a[mi], bb[2], bb[3]);
            }
#pragma unroll
            for (int mi = 0; mi < 4; mi++)
                LDM_X4(a[mi], ws_base + 18432 + (((uint32_t)(wy * 64 + mi * 16) + a_row) * 72
                                                  + k0 + a_koff) * 2);
#pragma unroll
            for (int mi = 0; mi < 4; mi++) {
                MMA16816(d[mi][0], a[mi], bb[0], bb[1]);
                MMA16816(d[mi][1], a[mi], bb[2], bb[3]);
            }
        }
        __syncthreads();
    }

    float* stage = (float*)(smem + PJ_STAGE);
    {
        int r = lane >> 2, c2 = (lane & 3) * 2;
#pragma unroll
        for (int mi = 0; mi < 4; mi++) {
            int row = wy * 64 + mi * 16 + r;
#pragma unroll
            for (int nf = 0; nf < 2; nf++) {
                int col = wx * 16 + nf * 8 + c2;
                stage[col * 129 + row]           = d[mi][nf][0];
                stage[(col + 1) * 129 + row]     = d[mi][nf][1];
                stage[col * 129 + row + 8]       = d[mi][nf][2];
                stage[(col + 1) * 129 + row + 8] = d[mi][nf][3];
            }
        }
    }
    __syncthreads();

    for (int e = tid; e < 16384; e += 512) {
        int gl = e & 127, cl = e >> 7;
        size_t idx = ((size_t)b * CDIM + m0 + cl) * TJ + p0 + gl;
        x1[idx] = x[idx] + stage[gl * 129 + cl] + pbs[cl];
    }
}

// ---------------------------------------------------------------------------
// K4: fused MLP on HMMA (unchanged from round 3)
// ---------------------------------------------------------------------------
#define SM_SN   0
#define SM_TN   1024
#define SM_S2   2048
#define SM_T2   3072
#define SM_S1   4096
#define SM_T1   4608
#define SM_XS   5120
#define SM_HS   (SM_XS + 33792)
#define SM_WB   (SM_HS + 17408)
#define SM_TOT  (SM_WB + 139264)

#define W1_STRIDE 264
#define H_STRIDE  136
#define W1LO_OFF  67584
#define W2LO_OFF  69632

__global__ void __launch_bounds__(512, 1) k_mlp_mma(
    const float* x1,
    const float* __restrict__ b1g, const float* __restrict__ b1b,
    const float* __restrict__ b1m, const float* __restrict__ b1v,
    const float* __restrict__ fb1,
    const float* __restrict__ b2g, const float* __restrict__ b2b,
    const float* __restrict__ b2m, const float* __restrict__ b2v,
    const float* __restrict__ fb2,
    const float* __restrict__ n2g, const float* __restrict__ n2b,
    const float* __restrict__ n2m, const float* __restrict__ n2v,
    float* out)
{
    extern __shared__ char smem[];
    const uint32_t sbase = smem_u32(smem);
    const int tid = threadIdx.x;
    const int wid = tid >> 5;
    const int lane = tid & 31;
    const int wy = wid & 1;
    const int wx = wid >> 1;

    const int blk = blockIdx.x;
    const int b = blk / 34;
    const int p0 = (blk - b * 34) * 64;

    float* sn = (float*)(smem + SM_SN);
    float* tn = (float*)(smem + SM_TN);
    float* s2 = (float*)(smem + SM_S2);
    float* t2 = (float*)(smem + SM_T2);
    float* s1 = (float*)(smem + SM_S1);
    float* t1 = (float*)(smem + SM_T1);

    if (tid < 256) {
        float s = n2g[tid] * rsqrtf(n2v[tid] + 1e-5f);
        sn[tid] = s;
        tn[tid] = n2b[tid] - n2m[tid] * s;
    } else {
        int c = tid - 256;
        float s = b2g[c] * rsqrtf(b2v[c] + 1e-5f);
        s2[c] = s;
        t2[c] = b2b[c] - b2m[c] * s + fb2[c] * s;
    }
    __syncthreads();

    const float* xb = x1 + (size_t)b * CDIM * TJ;

    for (int e = tid; e < 16384; e += 512) {
        int i = e >> 6, p = e & 63;
        float v = xb[(size_t)i * TJ + p0 + p] * sn[i] + tn[i];
        *(__half*)(smem + SM_XS + ((uint32_t)p * W1_STRIDE + i) * 2) = __float2half(v);
    }

    const uint32_t a_row  = (lane & 7) + ((lane >> 3) & 1) * 8;
    const uint32_t a_koff = (lane >> 4) * 8;
    const uint32_t b_row  = (lane & 7) + (lane >> 4) * 8;
    const uint32_t b_koff = ((lane >> 3) & 1) * 8;

    const uint32_t xs_base = sbase + SM_XS;
    const uint32_t hs_base = sbase + SM_HS;
    const uint32_t wb_base = sbase + SM_WB;

    float d2[2][4][4];
#pragma unroll
    for (int i0 = 0; i0 < 2; i0++)
#pragma unroll
        for (int j0 = 0; j0 < 4; j0++)
#pragma unroll
            for (int q = 0; q < 4; q++) d2[i0][j0][q] = 0.f;

    for (int nt = 0; nt < 8; nt++) {
        __syncthreads();

        {
            const uint4* srch = (const uint4*)(g_w1h + nt * 32768);
            const uint4* srcl = (const uint4*)(g_w1l + nt * 32768);
            for (int e = tid; e < 8192; e += 512) {
                int tile = e >> 12;
                int row = (e >> 5) & 127, col = e & 31;
                uint32_t doff = SM_WB + tile * W1LO_OFF
                              + ((uint32_t)row * W1_STRIDE + col * 8) * 2;
                *(uint4*)(smem + doff) = tile ? srcl[(e & 4095)] : srch[e];
            }
        }
        if (tid < 128) {
            int j = nt * 128 + tid;
            float s = b1g[j] * rsqrtf(b1v[j] + 1e-5f);
            s1[tid] = s;
            t1[tid] = b1b[j] - b1m[j] * s + fb1[j] * s;
        }
        __syncthreads();

        float dH[2][2][4];
#pragma unroll
        for (int i0 = 0; i0 < 2; i0++)
#pragma unroll
            for (int j0 = 0; j0 < 2; j0++)
#pragma unroll
                for (int q = 0; q < 4; q++) dH[i0][j0][q] = 0.f;

#pragma unroll 4
        for (int k0 = 0; k0 < 256; k0 += 16) {
            uint32_t a[2][4];
#pragma unroll
            for (int mi = 0; mi < 2; mi++) {
                uint32_t addr = xs_base
                    + (((uint32_t)(wy * 32 + mi * 16) + a_row) * W1_STRIDE + k0 + a_koff) * 2;
                LDM_X4(a[mi], addr);
            }
            uint32_t bh[4], bl[4];
            {
                uint32_t roff = (((uint32_t)(wx * 16) + b_row) * W1_STRIDE + k0 + b_koff) * 2;
                LDM_X4(bh, wb_base + roff);
                LDM_X4(bl, wb_base + W1LO_OFF + roff);
            }
#pragma unroll
            for (int mi = 0; mi < 2; mi++) {
                MMA16816(dH[mi][0], a[mi], bh[0], bh[1]);
                MMA16816(dH[mi][1], a[mi], bh[2], bh[3]);
                MMA16816(dH[mi][0], a[mi], bl[0], bl[1]);
                MMA16816(dH[mi][1], a[mi], bl[2], bl[3]);
            }
        }

        {
            int r = lane >> 2;
#pragma unroll
            for (int mi = 0; mi < 2; mi++) {
#pragma unroll
                for (int nf = 0; nf < 2; nf++) {
                    int c2 = wx * 16 + nf * 8 + (lane & 3) * 2;
                    float ss0 = s1[c2], tt0 = t1[c2];
                    float ss1 = s1[c2 + 1], tt1 = t1[c2 + 1];
                    int row0 = wy * 32 + mi * 16 + r;
                    float h0 = gelu_exact(dH[mi][nf][0] * ss0 + tt0);
                    float h1 = gelu_exact(dH[mi][nf][1] * ss1 + tt1);
                    float h2 = gelu_exact(dH[mi][nf][2] * ss0 + tt0);
                    float h3 = gelu_exact(dH[mi][nf][3] * ss1 + tt1);
                    *(__half2*)(smem + SM_HS + ((uint32_t)row0 * H_STRIDE + c2) * 2)
                        = __floats2half2_rn(h0, h1);
                    *(__half2*)(smem + SM_HS + ((uint32_t)(row0 + 8) * H_STRIDE + c2) * 2)
                        = __floats2half2_rn(h2, h3);
                }
            }
        }
        __syncthreads();

        {
            const uint4* srch = (const uint4*)(g_w2h + nt * 32768);
            const uint4* srcl = (const uint4*)(g_w2l + nt * 32768);
            for (int e = tid; e < 8192; e += 512) {
                int tile = e >> 12;
                int row = (e >> 4) & 255, col = e & 15;
                uint32_t doff = SM_WB + tile * W2LO_OFF
                              + ((uint32_t)row * H_STRIDE + col * 8) * 2;
                *(uint4*)(smem + doff) = tile ? srcl[(e & 4095)] : srch[e];
            }
        }
        __syncthreads();

#pragma unroll
        for (int k0 = 0; k0 < 128; k0 += 16) {
            uint32_t a[2][4];
#pragma unroll
            for (int mi = 0; mi < 2; mi++) {
                uint32_t addr = hs_base
                    + (((uint32_t)(wy * 32 + mi * 16) + a_row) * H_STRIDE + k0 + a_koff) * 2;
                LDM_X4(a[mi], addr);
            }
#pragma unroll
            for (int nq = 0; nq < 2; nq++) {
                uint32_t roff = (((uint32_t)(wx * 32 + nq * 16) + b_row) * H_STRIDE
                                 + k0 + b_koff) * 2;
                uint32_t bh[4], bl[4];
                LDM_X4(bh, wb_base + roff);
                LDM_X4(bl, wb_base + W2LO_OFF + roff);
#pragma unroll
                for (int mi = 0; mi < 2; mi++) {
                    MMA16816(d2[mi][nq * 2 + 0], a[mi], bh[0], bh[1]);
                    MMA16816(d2[mi][nq * 2 + 1], a[mi], bh[2], bh[3]);
                    MMA16816(d2[mi][nq * 2 + 0], a[mi], bl[0], bl[1]);
                    MMA16816(d2[mi][nq * 2 + 1], a[mi], bl[2], bl[3]);
                }
            }
        }
    }

    __syncthreads();
    float* stage = (float*)(smem + SM_WB);
    {
        int r = lane >> 2;
#pragma unroll
        for (int mi = 0; mi < 2; mi++) {
            int row0 = wy * 32 + mi * 16 + r;
#pragma unroll
            for (int j0 = 0; j0 < 4; j0++) {
                int c = wx * 32 + j0 * 8 + (lane & 3) * 2;
                stage[row0 * 257 + c]       = d2[mi][j0][0];
                stage[row0 * 257 + c + 1]   = d2[mi][j0][1];
                stage[(row0 + 8) * 257 + c]     = d2[mi][j0][2];
                stage[(row0 + 8) * 257 + c + 1] = d2[mi][j0][3];
            }
        }
    }
    __syncthreads();

    for (int e = tid; e < 16384; e += 512) {
        int c = e >> 6, p = e & 63;
        size_t idx = ((size_t)b * CDIM + c) * TJ + p0 + p;
        out[idx] = x1[idx] + stage[p * 257 + c] * s2[c] + t2[c];
    }
}

// ---------------------------------------------------------------------------
extern "C" void kernel_launch(void* const* d_in, const int* in_sizes, int n_in,
                              void* d_out, int out_size)
{
    const float* x    = (const float*)d_in[0];
    const float* n1g  = (const float*)d_in[1];
    const float* n1b  = (const float*)d_in[2];
    const float* n1m  = (const float*)d_in[3];
    const float* n1v  = (const float*)d_in[4];
    const float* qkvw = (const float*)d_in[5];
    const float* qg   = (const float*)d_in[6];
    const float* qb   = (const float*)d_in[7];
    const float* qm   = (const float*)d_in[8];
    const float* qv   = (const float*)d_in[9];
    const float* pw   = (const float*)d_in[10];
    const float* pb   = (const float*)d_in[11];
    const float* n2g  = (const float*)d_in[12];
    const float* n2b  = (const float*)d_in[13];
    const float* n2m  = (const float*)d_in[14];
    const float* n2v  = (const float*)d_in[15];
    const float* w1   = (const float*)d_in[16];
    const float* fb1  = (const float*)d_in[17];
    const float* b1g  = (const float*)d_in[18];
    const float* b1b  = (const float*)d_in[19];
    const float* b1m  = (const float*)d_in[20];
    const float* b1v  = (const float*)d_in[21];
    const float* w2   = (const float*)d_in[22];
    const float* fb2  = (const float*)d_in[23];
    const float* b2g  = (const float*)d_in[24];
    const float* b2b  = (const float*)d_in[25];
    const float* b2m  = (const float*)d_in[26];
    const float* b2v  = (const float*)d_in[27];
    float* out = (float*)d_out;

    const int attn_smem = 3 * 258 * 33 * 4;
    cudaFuncSetAttribute(k_attn,     cudaFuncAttributeMaxDynamicSharedMemorySize, attn_smem);
    cudaFuncSetAttribute(k_conv_mma, cudaFuncAttributeMaxDynamicSharedMemorySize, CV_TOT);
    cudaFuncSetAttribute(k_proj_mma, cudaFuncAttributeMaxDynamicSharedMemorySize, PJ_TOT);
    cudaFuncSetAttribute(k_mlp_mma,  cudaFuncAttributeMaxDynamicSharedMemorySize, SM_TOT);

    k_prep<<<9216, 256>>>(w1, w2, qkvw, pw);
    k_conv_mma<<<dim3(6, 129), 512, CV_TOT>>>(x, n1g, n1b, n1m, n1v, qg, qb, qm, qv);
    k_attn<<<512, 256, attn_smem>>>();
    k_proj_mma<<<dim3(2, 1088), 512, PJ_TOT>>>(pb, x, out);
    k_mlp_mma<<<2176, 512, SM_TOT>>>(out,
                                     b1g, b1b, b1m, b1v, fb1,
                                     b2g, b2b, b2m, b2v, fb2,
                                     n2g, n2b, n2m, n2v, out);
}

// round 5
// speedup vs baseline: 5.1213x; 1.7525x over previous
#include <cuda_runtime.h>
#include <cuda_fp16.h>
#include <math.h>
#include <stdint.h>

#define BATCH 64
#define CDIM 256
#define TDIM 128
#define JDIM 17
#define TJ 2176     // TDIM*JDIM
#define HCC 43
#define WCC 6
#define HW 258      // HCC*WCC
#define HIDDEN 1024

// scratch (static __device__ globals per harness rules)
__device__ float g_qkv[(size_t)3 * BATCH * HW * CDIM];   // [b][t(3)][hw][c]
__device__ float g_att[(size_t)BATCH * HW * CDIM];       // [b][hw][c]
// fp16 weights (single precision-split dropped: activations dominate error)
__device__ __half g_w1h[8 * 32768];            // W1 per-tile layout
__device__ __half g_w2h[8 * 32768];            // W2 per-tile layout
__device__ __half g_qwh[768 * 2304];           // qkv conv weight row-major
__device__ __half g_pwh[256 * 256];            // proj weight row-major

__device__ __forceinline__ float gelu_exact(float v) {
    return 0.5f * v * (1.0f + erff(v * 0.70710678118654752f));
}

__device__ __forceinline__ uint32_t smem_u32(const void* p) {
    uint32_t a;
    asm("{ .reg .u64 t; cvta.to.shared.u64 t, %1; cvt.u32.u64 %0, t; }" : "=r"(a) : "l"(p));
    return a;
}

#define LDM_X4(r, addr) \
    asm volatile("ldmatrix.sync.aligned.m8n8.x4.shared.b16 {%0,%1,%2,%3}, [%4];" \
        : "=r"((r)[0]), "=r"((r)[1]), "=r"((r)[2]), "=r"((r)[3]) : "r"(addr))

#define MMA16816(d, a, b0, b1) \
    asm volatile("mma.sync.aligned.m16n8k16.row.col.f32.f16.f16.f32 " \
        "{%0,%1,%2,%3}, {%4,%5,%6,%7}, {%8,%9}, {%0,%1,%2,%3};" \
        : "+f"((d)[0]), "+f"((d)[1]), "+f"((d)[2]), "+f"((d)[3]) \
        : "r"((a)[0]), "r"((a)[1]), "r"((a)[2]), "r"((a)[3]), "r"(b0), "r"(b1))

// ---------------------------------------------------------------------------
// K0: pre-convert all weights fp32 -> fp16
// ---------------------------------------------------------------------------
__global__ void __launch_bounds__(256) k_prep(const float* __restrict__ w1,
                                              const float* __restrict__ w2,
                                              const float* __restrict__ qkvw,
                                              const float* __restrict__ pw)
{
    int idx = blockIdx.x * 256 + threadIdx.x;
    if (idx < 262144) {
        int j = idx >> 8, i = idx & 255;
        int nt = j >> 7, jl = j & 127;
        g_w1h[(uint32_t)nt * 32768 + (uint32_t)jl * 256 + i] = __float2half(w1[idx]);
    } else if (idx < 524288) {
        int t = idx - 262144;
        int c = t >> 10, j = t & 1023;
        int nt = j >> 7, jl = j & 127;
        g_w2h[(uint32_t)nt * 32768 + (uint32_t)c * 128 + jl] = __float2half(w2[t]);
    } else if (idx < 2293760) {
        int t = idx - 524288;
        g_qwh[t] = __float2half(qkvw[t]);
    } else {
        int t = idx - 2293760;
        g_pwh[t] = __float2half(pw[t]);
    }
}

// ---------------------------------------------------------------------------
// K1: conv QKV on HMMA, software-pipelined K loop (36 chunks of 64).
// CTA: M=128 oc x N=128 positions. BN-folded im2col gather prefetched into
// registers while MMAs run on the other smem buffer.
// ---------------------------------------------------------------------------
#define CV_SIN   0
#define CV_TIN   1024
#define CV_SO    2048
#define CV_TO    2560
#define CV_KTAB  3072          // uint16[2304] = 4608
#define CV_GXO   7680          // int[128]
#define CV_GY    8192          // int16[128]
#define CV_GX    8448          // int16[128]
#define CV_BUF   8704          // 2 x (W 18432 + P 18432) = 73728
#define CV_STAGE CV_BUF        // float[128*129] = 66048 (reuse)
#define CV_TOT   (CV_BUF + 2 * 36864)   // 82432

__global__ void __launch_bounds__(512, 1) k_conv_mma(
    const float* __restrict__ x,
    const float* __restrict__ n1g, const float* __restrict__ n1b,
    const float* __restrict__ n1m, const float* __restrict__ n1v,
    const float* __restrict__ qg, const float* __restrict__ qb,
    const float* __restrict__ qm, const float* __restrict__ qv)
{
    extern __shared__ char smem[];
    const uint32_t sbase = smem_u32(smem);
    const int tid = threadIdx.x;
    const int wid = tid >> 5, lane = tid & 31;
    const int wy = wid & 1, wx = wid >> 1;

    const int m0 = blockIdx.x * 128;   // out-channel base
    const int n0 = blockIdx.y * 128;   // global position base

    float*    s_in = (float*)(smem + CV_SIN);
    float*    t_in = (float*)(smem + CV_TIN);
    float*    s_o  = (float*)(smem + CV_SO);
    float*    t_o  = (float*)(smem + CV_TO);
    uint16_t* ktab = (uint16_t*)(smem + CV_KTAB);
    int*      gxo  = (int*)(smem + CV_GXO);
    int16_t*  gyv  = (int16_t*)(smem + CV_GY);
    int16_t*  gxv  = (int16_t*)(smem + CV_GX);

    if (tid < 256) {
        float s = n1g[tid] * rsqrtf(n1v[tid] + 1e-5f);
        s_in[tid] = s;
        t_in[tid] = n1b[tid] - n1m[tid] * s;
    } else if (tid < 384) {
        int o = m0 + tid - 256;
        float s = qg[o] * rsqrtf(qv[o] + 1e-5f);
        s_o[tid - 256] = s;
        t_o[tid - 256] = qb[o] - qm[o] * s;
    } else if (tid < 512) {
        int gl = tid - 384;
        int g = n0 + gl;
        int b = g / HW, hw = g - b * HW;
        int y = hw / WCC, xx = hw - y * WCC;
        gxo[gl] = b * (CDIM * TJ);
        gyv[gl] = (int16_t)(3 * y - 1);
        gxv[gl] = (int16_t)(3 * xx - 1);
    }
    for (int k = tid; k < 2304; k += 512) {
        int i = k / 9, r = k - i * 9;
        int ky = r / 3, kx = r - ky * 3;
        ktab[k] = (uint16_t)((i << 4) | (ky << 2) | kx);
    }
    __syncthreads();

    const uint32_t a_row  = (lane & 7) + ((lane >> 3) & 1) * 8;
    const uint32_t a_koff = (lane >> 4) * 8;
    const uint32_t b_row  = (lane & 7) + (lane >> 4) * 8;
    const uint32_t b_koff = ((lane >> 3) & 1) * 8;

    const int kk_fix = tid & 63;
    const int gl0    = tid >> 6;
    const int wrow0  = tid >> 3;
    const int wcol   = tid & 7;

    float pv[16];
    uint4 wv[2];

    auto loadW = [&](int kc) {
#pragma unroll
        for (int t = 0; t < 2; t++) {
            int row = wrow0 + 64 * t;
            wv[t] = *(const uint4*)(g_qwh + (size_t)(m0 + row) * 2304 + kc + wcol * 8);
        }
    };
    auto gatherP = [&](int kc) {
        uint32_t kt = ktab[kc + kk_fix];
        int i = kt >> 4, ky = (kt >> 2) & 3, kx = kt & 3;
        float si = s_in[i], ti = t_in[i];
#pragma unroll
        for (int t = 0; t < 16; t++) {
            int gl = gl0 + 8 * t;
            int iy = gyv[gl] + ky, ix = gxv[gl] + kx;
            float v = 0.f;
            if ((unsigned)iy < (unsigned)TDIM && (unsigned)ix < (unsigned)JDIM)
                v = x[gxo[gl] + i * TJ + iy * JDIM + ix] * si + ti;
            pv[t] = v;
        }
    };
    auto storeBuf = [&](int bsel) {
        char* wb = smem + CV_BUF + bsel * 36864;
#pragma unroll
        for (int t = 0; t < 2; t++) {
            int row = wrow0 + 64 * t;
            *(uint4*)(wb + ((uint32_t)row * 72 + wcol * 8) * 2) = wv[t];
        }
        char* pb2 = wb + 18432;
#pragma unroll
        for (int t = 0; t < 16; t++) {
            int gl = gl0 + 8 * t;
            *(__half*)(pb2 + ((uint32_t)gl * 72 + kk_fix) * 2) = __float2half(pv[t]);
        }
    };

    float d[4][2][4];
#pragma unroll
    for (int mi = 0; mi < 4; mi++)
#pragma unroll
        for (int nf = 0; nf < 2; nf++)
#pragma unroll
            for (int q = 0; q < 4; q++) d[mi][nf][q] = 0.f;

    loadW(0); gatherP(0); storeBuf(0);
    __syncthreads();

    for (int c = 0; c < 36; c++) {
        if (c < 35) { loadW((c + 1) * 64); gatherP((c + 1) * 64); }
        const uint32_t wsb = sbase + CV_BUF + (uint32_t)(c & 1) * 36864;
        const uint32_t psb = wsb + 18432;
#pragma unroll
        for (int ks = 0; ks < 4; ks++) {
            const int k0 = ks * 16;
            uint32_t bb[4];
            LDM_X4(bb, psb + (((uint32_t)(wx * 16) + b_row) * 72 + k0 + b_koff) * 2);
            uint32_t a[4][4];
#pragma unroll
            for (int mi = 0; mi < 4; mi++)
                LDM_X4(a[mi], wsb + (((uint32_t)(wy * 64 + mi * 16) + a_row) * 72
                                      + k0 + a_koff) * 2);
#pragma unroll
            for (int mi = 0; mi < 4; mi++) {
                MMA16816(d[mi][0], a[mi], bb[0], bb[1]);
                MMA16816(d[mi][1], a[mi], bb[2], bb[3]);
            }
        }
        if (c < 35) storeBuf((c + 1) & 1);
        __syncthreads();
    }

    // stage accumulators: stage[gl * 129 + cl]
    float* stage = (float*)(smem + CV_STAGE);
    {
        int r = lane >> 2, c2 = (lane & 3) * 2;
#pragma unroll
        for (int mi = 0; mi < 4; mi++) {
            int row = wy * 64 + mi * 16 + r;
#pragma unroll
            for (int nf = 0; nf < 2; nf++) {
                int col = wx * 16 + nf * 8 + c2;
                stage[col * 129 + row]           = d[mi][nf][0];
                stage[(col + 1) * 129 + row]     = d[mi][nf][1];
                stage[col * 129 + row + 8]       = d[mi][nf][2];
                stage[(col + 1) * 129 + row + 8] = d[mi][nf][3];
            }
        }
    }
    __syncthreads();

    const int tpart = m0 >> 8;
    const int cbase = m0 & 255;
    for (int e = tid; e < 16384; e += 512) {
        int gl = e >> 7, cl = e & 127;
        int g = n0 + gl;
        int b = g / HW, hw = g - b * HW;
        float v = stage[gl * 129 + cl] * s_o[cl] + t_o[cl];
        g_qkv[(((size_t)b * 3 + tpart) * HW + hw) * CDIM + cbase + cl] = gelu_exact(v);
    }
}

// ---------------------------------------------------------------------------
// K2: attention (fp32, unchanged)
// ---------------------------------------------------------------------------
__global__ void __launch_bounds__(256) k_attn()
{
    extern __shared__ float sm[];
    float* qs = sm;
    float* ks = sm + 258 * 33;
    float* vs = sm + 2 * 258 * 33;

    const int bh = blockIdx.x;
    const int b = bh >> 3, h = bh & 7;
    const int tid = threadIdx.x;

    const float* qg = g_qkv + (((size_t)b * 3 + 0) * HW) * CDIM + h * 32;
    const float* kg = g_qkv + (((size_t)b * 3 + 1) * HW) * CDIM + h * 32;
    const float* vg = g_qkv + (((size_t)b * 3 + 2) * HW) * CDIM + h * 32;

    for (int e = tid; e < HW * 32; e += 256) {
        int r = e >> 5, d = e & 31;
        qs[r * 33 + d] = qg[(size_t)r * CDIM + d];
        ks[r * 33 + d] = kg[(size_t)r * CDIM + d];
        vs[r * 33 + d] = vg[(size_t)r * CDIM + d];
    }
    __syncthreads();

    const float scale = 0.17677669529663687f;

    for (int r = tid; r < HW; r += 256) {
        float qr[32];
#pragma unroll
        for (int d = 0; d < 32; d++) qr[d] = qs[r * 33 + d];
        float m = -1e30f, l = 0.f;
        float acc[32];
#pragma unroll
        for (int d = 0; d < 32; d++) acc[d] = 0.f;
        for (int j = 0; j < HW; j++) {
            const float* kj = ks + j * 33;
            float s = 0.f;
#pragma unroll
            for (int d = 0; d < 32; d++) s += qr[d] * kj[d];
            s *= scale;
            float mn = fmaxf(m, s);
            float corr = __expf(m - mn);
            float p = __expf(s - mn);
            l = l * corr + p;
            const float* vj = vs + j * 33;
#pragma unroll
            for (int d = 0; d < 32; d++) acc[d] = acc[d] * corr + p * vj[d];
            m = mn;
        }
        float inv = 1.f / l;
        float* og = g_att + ((size_t)b * HW + r) * CDIM + h * 32;
#pragma unroll
        for (int d = 0; d < 32; d++) og[d] = acc[d] * inv;
    }
}

// ---------------------------------------------------------------------------
// K3: proj on HMMA, pipelined. x1 = x + proj1x1(bilinear(att)).
// ---------------------------------------------------------------------------
#define PJ_PB    0             // float[128]
#define PJ_O00   512
#define PJ_O01   1024
#define PJ_O10   1536
#define PJ_O11   2048
#define PJ_WXT   2560
#define PJ_WYT   3072
#define PJ_BUF   3584          // 2 x (W 18432 + P 18432) = 73728
#define PJ_STAGE PJ_BUF        // 66048 reuse
#define PJ_TOT   (PJ_BUF + 2 * 36864)   // 77312

__global__ void __launch_bounds__(512, 1) k_proj_mma(
    const float* __restrict__ pb,
    const float* __restrict__ x, float* __restrict__ x1)
{
    extern __shared__ char smem[];
    const uint32_t sbase = smem_u32(smem);
    const int tid = threadIdx.x;
    const int wid = tid >> 5, lane = tid & 31;
    const int wy = wid & 1, wx = wid >> 1;

    const int m0 = blockIdx.x * 128;            // channel base
    const int b  = blockIdx.y / 17;
    const int p0 = (blockIdx.y - b * 17) * 128; // position base within batch

    float* pbs = (float*)(smem + PJ_PB);
    int*   o00 = (int*)(smem + PJ_O00);
    int*   o01 = (int*)(smem + PJ_O01);
    int*   o10 = (int*)(smem + PJ_O10);
    int*   o11 = (int*)(smem + PJ_O11);
    float* wxs = (float*)(smem + PJ_WXT);
    float* wys = (float*)(smem + PJ_WYT);

    if (tid < 128) {
        int p = p0 + tid;
        int t = p / JDIM, j = p - t * JDIM;
        float sy = (t + 0.5f) * (43.0f / 128.0f) - 0.5f;
        sy = fminf(fmaxf(sy, 0.f), 42.f);
        int y0 = (int)sy;
        int y1 = min(y0 + 1, 42);
        float fy = sy - y0;
        float sx = (j + 0.5f) * (6.0f / 17.0f) - 0.5f;
        sx = fminf(fmaxf(sx, 0.f), 5.f);
        int x0 = (int)sx;
        int x1i = min(x0 + 1, 5);
        float fx = sx - x0;
        o00[tid] = (y0 * WCC + x0) * CDIM;
        o01[tid] = (y0 * WCC + x1i) * CDIM;
        o10[tid] = (y1 * WCC + x0) * CDIM;
        o11[tid] = (y1 * WCC + x1i) * CDIM;
        wxs[tid] = fx;
        wys[tid] = fy;
    } else if (tid < 256) {
        pbs[tid - 128] = pb[m0 + tid - 128];
    }
    __syncthreads();

    const uint32_t a_row  = (lane & 7) + ((lane >> 3) & 1) * 8;
    const uint32_t a_koff = (lane >> 4) * 8;
    const uint32_t b_row  = (lane & 7) + (lane >> 4) * 8;
    const uint32_t b_koff = ((lane >> 3) & 1) * 8;

    const int kk_fix = tid & 63;
    const int gl0    = tid >> 6;
    const int wrow0  = tid >> 3;
    const int wcol   = tid & 7;

    const float* abase = g_att + (size_t)b * HW * CDIM;

    float pv[16];
    uint4 wv[2];

    auto loadW = [&](int kc) {
#pragma unroll
        for (int t = 0; t < 2; t++) {
            int row = wrow0 + 64 * t;
            wv[t] = *(const uint4*)(g_pwh + (size_t)(m0 + row) * 256 + kc + wcol * 8);
        }
    };
    auto gatherP = [&](int kc) {
        const float* bp = abase + (kc + kk_fix);
#pragma unroll
        for (int t = 0; t < 16; t++) {
            int gl = gl0 + 8 * t;
            float fx = wxs[gl], fy = wys[gl];
            float a00 = bp[o00[gl]];
            float a01 = bp[o01[gl]];
            float a10 = bp[o10[gl]];
            float a11 = bp[o11[gl]];
            pv[t] = (a00 * (1.f - fx) + a01 * fx) * (1.f - fy)
                  + (a10 * (1.f - fx) + a11 * fx) * fy;
        }
    };
    auto storeBuf = [&](int bsel) {
        char* wb = smem + PJ_BUF + bsel * 36864;
#pragma unroll
        for (int t = 0; t < 2; t++) {
            int row = wrow0 + 64 * t;
            *(uint4*)(wb + ((uint32_t)row * 72 + wcol * 8) * 2) = wv[t];
        }
        char* pb2 = wb + 18432;
#pragma unroll
        for (int t = 0; t < 16; t++) {
            int gl = gl0 + 8 * t;
            *(__half*)(pb2 + ((uint32_t)gl * 72 + kk_fix) * 2) = __float2half(pv[t]);
        }
    };

    float d[4][2][4];
#pragma unroll
    for (int mi = 0; mi < 4; mi++)
#pragma unroll
        for (int nf = 0; nf < 2; nf++)
#pragma unroll
            for (int q = 0; q < 4; q++) d[mi][nf][q] = 0.f;

    loadW(0); gatherP(0); storeBuf(0);
    __syncthreads();

    for (int c = 0; c < 4; c++) {
        if (c < 3) { loadW((c + 1) * 64); gatherP((c + 1) * 64); }
        const uint32_t wsb = sbase + PJ_BUF + (uint32_t)(c & 1) * 36864;
        const uint32_t psb = wsb + 18432;
#pragma unroll
        for (int ks = 0; ks < 4; ks++) {
            const int k0 = ks * 16;
            uint32_t bb[4];
            LDM_X4(bb, psb + (((uint32_t)(wx * 16) + b_row) * 72 + k0 + b_koff) * 2);
            uint32_t a[4][4];
#pragma unroll
            for (int mi = 0; mi < 4; mi++)
                LDM_X4(a[mi], wsb + (((uint32_t)(wy * 64 + mi * 16) + a_row) * 72
                                      + k0 + a_koff) * 2);
#pragma unroll
            for (int mi = 0; mi < 4; mi++) {
                MMA16816(d[mi][0], a[mi], bb[0], bb[1]);
                MMA16816(d[mi][1], a[mi], bb[2], bb[3]);
            }
        }
        if (c < 3) storeBuf((c + 1) & 1);
        __syncthreads();
    }

    float* stage = (float*)(smem + PJ_STAGE);
    {
        int r = lane >> 2, c2 = (lane & 3) * 2;
#pragma unroll
        for (int mi = 0; mi < 4; mi++) {
            int row = wy * 64 + mi * 16 + r;
#pragma unroll
            for (int nf = 0; nf < 2; nf++) {
                int col = wx * 16 + nf * 8 + c2;
                stage[col * 129 + row]           = d[mi][nf][0];
                stage[(col + 1) * 129 + row]     = d[mi][nf][1];
                stage[col * 129 + row + 8]       = d[mi][nf][2];
                stage[(col + 1) * 129 + row + 8] = d[mi][nf][3];
            }
        }
    }
    __syncthreads();

    for (int e = tid; e < 16384; e += 512) {
        int gl = e & 127, cl = e >> 7;
        size_t idx = ((size_t)b * CDIM + m0 + cl) * TJ + p0 + gl;
        x1[idx] = x[idx] + stage[gl * 129 + cl] + pbs[cl];
    }
}

// ---------------------------------------------------------------------------
// K4: fused MLP on HMMA, weight prefetch pipelined into registers.
// ---------------------------------------------------------------------------
#define SM_SN   0
#define SM_TN   1024
#define SM_S2   2048
#define SM_T2   3072
#define SM_S1   4096
#define SM_T1   4608
#define SM_XS   5120
#define SM_HS   (SM_XS + 33792)
#define SM_WB   (SM_HS + 17408)           // 56320
#define SM_TOT  (SM_WB + 69632)           // 125952

#define W1_STRIDE 264
#define H_STRIDE  136

__global__ void __launch_bounds__(512, 1) k_mlp_mma(
    const float* x1,
    const float* __restrict__ b1g, const float* __restrict__ b1b,
    const float* __restrict__ b1m, const float* __restrict__ b1v,
    const float* __restrict__ fb1,
    const float* __restrict__ b2g, const float* __restrict__ b2b,
    const float* __restrict__ b2m, const float* __restrict__ b2v,
    const float* __restrict__ fb2,
    const float* __restrict__ n2g, const float* __restrict__ n2b,
    const float* __restrict__ n2m, const float* __restrict__ n2v,
    float* out)
{
    extern __shared__ char smem[];
    const uint32_t sbase = smem_u32(smem);
    const int tid = threadIdx.x;
    const int wid = tid >> 5;
    const int lane = tid & 31;
    const int wy = wid & 1;
    const int wx = wid >> 1;

    const int blk = blockIdx.x;
    const int b = blk / 34;
    const int p0 = (blk - b * 34) * 64;

    float* sn = (float*)(smem + SM_SN);
    float* tn = (float*)(smem + SM_TN);
    float* s2 = (float*)(smem + SM_S2);
    float* t2 = (float*)(smem + SM_T2);
    float* s1 = (float*)(smem + SM_S1);
    float* t1 = (float*)(smem + SM_T1);

    if (tid < 256) {
        float s = n2g[tid] * rsqrtf(n2v[tid] + 1e-5f);
        sn[tid] = s;
        tn[tid] = n2b[tid] - n2m[tid] * s;
    } else {
        int c = tid - 256;
        float s = b2g[c] * rsqrtf(b2v[c] + 1e-5f);
        s2[c] = s;
        t2[c] = b2b[c] - b2m[c] * s + fb2[c] * s;
    }

    uint4 wv[8];
    auto ldW1 = [&](int nt) {
        const uint4* s = (const uint4*)(g_w1h + nt * 32768);
#pragma unroll
        for (int t = 0; t < 8; t++) wv[t] = s[tid + t * 512];
    };
    auto stW1 = [&]() {
#pragma unroll
        for (int t = 0; t < 8; t++) {
            int e = tid + t * 512;
            int row = (e >> 5) & 127, col = e & 31;
            *(uint4*)(smem + SM_WB + ((uint32_t)row * W1_STRIDE + col * 8) * 2) = wv[t];
        }
    };
    auto ldW2 = [&](int nt) {
        const uint4* s = (const uint4*)(g_w2h + nt * 32768);
#pragma unroll
        for (int t = 0; t < 8; t++) wv[t] = s[tid + t * 512];
    };
    auto stW2 = [&]() {
#pragma unroll
        for (int t = 0; t < 8; t++) {
            int e = tid + t * 512;
            int row = (e >> 4) & 255, col = e & 15;
            *(uint4*)(smem + SM_WB + ((uint32_t)row * H_STRIDE + col * 8) * 2) = wv[t];
        }
    };
    auto ldBN1 = [&](int nt) {
        if (tid < 128) {
            int j = nt * 128 + tid;
            float s = b1g[j] * rsqrtf(b1v[j] + 1e-5f);
            s1[tid] = s;
            t1[tid] = b1b[j] - b1m[j] * s + fb1[j] * s;
        }
    };

    __syncthreads();   // sn/tn ready

    const float* xb = x1 + (size_t)b * CDIM * TJ;
    for (int e = tid; e < 16384; e += 512) {
        int i = e >> 6, p = e & 63;
        float v = xb[(size_t)i * TJ + p0 + p] * sn[i] + tn[i];
        *(__half*)(smem + SM_XS + ((uint32_t)p * W1_STRIDE + i) * 2) = __float2half(v);
    }

    const uint32_t a_row  = (lane & 7) + ((lane >> 3) & 1) * 8;
    const uint32_t a_koff = (lane >> 4) * 8;
    const uint32_t b_row  = (lane & 7) + (lane >> 4) * 8;
    const uint32_t b_koff = ((lane >> 3) & 1) * 8;

    const uint32_t xs_base = sbase + SM_XS;
    const uint32_t hs_base = sbase + SM_HS;
    const uint32_t wb_base = sbase + SM_WB;

    float d2[2][4][4];
#pragma unroll
    for (int i0 = 0; i0 < 2; i0++)
#pragma unroll
        for (int j0 = 0; j0 < 4; j0++)
#pragma unroll
            for (int q = 0; q < 4; q++) d2[i0][j0][q] = 0.f;

    // prologue: W1(0) + bn1(0)
    ldW1(0); stW1(); ldBN1(0);
    __syncthreads();

    for (int nt = 0; nt < 8; nt++) {
        ldW2(nt);   // LDGs in flight during GEMM1

        // ---- GEMM1: H = Xn @ W1t^T ----
        float dH[2][2][4];
#pragma unroll
        for (int i0 = 0; i0 < 2; i0++)
#pragma unroll
            for (int j0 = 0; j0 < 2; j0++)
#pragma unroll
                for (int q = 0; q < 4; q++) dH[i0][j0][q] = 0.f;

#pragma unroll 4
        for (int k0 = 0; k0 < 256; k0 += 16) {
            uint32_t a[2][4];
#pragma unroll
            for (int mi = 0; mi < 2; mi++) {
                uint32_t addr = xs_base
                    + (((uint32_t)(wy * 32 + mi * 16) + a_row) * W1_STRIDE + k0 + a_koff) * 2;
                LDM_X4(a[mi], addr);
            }
            uint32_t bh[4];
            LDM_X4(bh, wb_base + (((uint32_t)(wx * 16) + b_row) * W1_STRIDE + k0 + b_koff) * 2);
#pragma unroll
            for (int mi = 0; mi < 2; mi++) {
                MMA16816(dH[mi][0], a[mi], bh[0], bh[1]);
                MMA16816(dH[mi][1], a[mi], bh[2], bh[3]);
            }
        }

        // ---- epilogue1: gelu(bn1) -> Hs fp16 ----
        {
            int r = lane >> 2;
#pragma unroll
            for (int mi = 0; mi < 2; mi++) {
#pragma unroll
                for (int nf = 0; nf < 2; nf++) {
                    int c2 = wx * 16 + nf * 8 + (lane & 3) * 2;
                    float ss0 = s1[c2], tt0 = t1[c2];
                    float ss1 = s1[c2 + 1], tt1 = t1[c2 + 1];
                    int row0 = wy * 32 + mi * 16 + r;
                    float h0 = gelu_exact(dH[mi][nf][0] * ss0 + tt0);
                    float h1 = gelu_exact(dH[mi][nf][1] * ss1 + tt1);
                    float h2 = gelu_exact(dH[mi][nf][2] * ss0 + tt0);
                    float h3 = gelu_exact(dH[mi][nf][3] * ss1 + tt1);
                    *(__half2*)(smem + SM_HS + ((uint32_t)row0 * H_STRIDE + c2) * 2)
                        = __floats2half2_rn(h0, h1);
                    *(__half2*)(smem + SM_HS + ((uint32_t)(row0 + 8) * H_STRIDE + c2) * 2)
                        = __floats2half2_rn(h2, h3);
                }
            }
        }
        __syncthreads();   // Hs written; all done reading WB (W1)

        stW2();
        if (nt < 7) ldW1(nt + 1);   // LDGs in flight during GEMM2
        __syncthreads();   // WB = W2 visible

        // ---- GEMM2: Y += H @ W2t^T ----
#pragma unroll
        for (int k0 = 0; k0 < 128; k0 += 16) {
            uint32_t a[2][4];
#pragma unroll
            for (int mi = 0; mi < 2; mi++) {
                uint32_t addr = hs_base
                    + (((uint32_t)(wy * 32 + mi * 16) + a_row) * H_STRIDE + k0 + a_koff) * 2;
                LDM_X4(a[mi], addr);
            }
#pragma unroll
            for (int nq = 0; nq < 2; nq++) {
                uint32_t bh[4];
                LDM_X4(bh, wb_base + (((uint32_t)(wx * 32 + nq * 16) + b_row) * H_STRIDE
                                       + k0 + b_koff) * 2);
#pragma unroll
                for (int mi = 0; mi < 2; mi++) {
                    MMA16816(d2[mi][nq * 2 + 0], a[mi], bh[0], bh[1]);
                    MMA16816(d2[mi][nq * 2 + 1], a[mi], bh[2], bh[3]);
                }
            }
        }
        __syncthreads();   // done reading WB (W2) and Hs

        if (nt < 7) {
            stW1();
            ldBN1(nt + 1);
            __syncthreads();   // WB = W1(nt+1), s1/t1 visible
        }
    }

    // ---- final epilogue ----
    float* stage = (float*)(smem + SM_WB);
    {
        int r = lane >> 2;
#pragma unroll
        for (int mi = 0; mi < 2; mi++) {
            int row0 = wy * 32 + mi * 16 + r;
#pragma unroll
            for (int j0 = 0; j0 < 4; j0++) {
                int c = wx * 32 + j0 * 8 + (lane & 3) * 2;
                stage[row0 * 257 + c]       = d2[mi][j0][0];
                stage[row0 * 257 + c + 1]   = d2[mi][j0][1];
                stage[(row0 + 8) * 257 + c]     = d2[mi][j0][2];
                stage[(row0 + 8) * 257 + c + 1] = d2[mi][j0][3];
            }
        }
    }
    __syncthreads();

    for (int e = tid; e < 16384; e += 512) {
        int c = e >> 6, p = e & 63;
        size_t idx = ((size_t)b * CDIM + c) * TJ + p0 + p;
        out[idx] = x1[idx] + stage[p * 257 + c] * s2[c] + t2[c];
    }
}

// ---------------------------------------------------------------------------
extern "C" void kernel_launch(void* const* d_in, const int* in_sizes, int n_in,
                              void* d_out, int out_size)
{
    const float* x    = (const float*)d_in[0];
    const float* n1g  = (const float*)d_in[1];
    const float* n1b  = (const float*)d_in[2];
    const float* n1m  = (const float*)d_in[3];
    const float* n1v  = (const float*)d_in[4];
    const float* qkvw = (const float*)d_in[5];
    const float* qg   = (const float*)d_in[6];
    const float* qb   = (const float*)d_in[7];
    const float* qm   = (const float*)d_in[8];
    const float* qv   = (const float*)d_in[9];
    const float* pw   = (const float*)d_in[10];
    const float* pb   = (const float*)d_in[11];
    const float* n2g  = (const float*)d_in[12];
    const float* n2b  = (const float*)d_in[13];
    const float* n2m  = (const float*)d_in[14];
    const float* n2v  = (const float*)d_in[15];
    const float* w1   = (const float*)d_in[16];
    const float* fb1  = (const float*)d_in[17];
    const float* b1g  = (const float*)d_in[18];
    const float* b1b  = (const float*)d_in[19];
    const float* b1m  = (const float*)d_in[20];
    const float* b1v  = (const float*)d_in[21];
    const float* w2   = (const float*)d_in[22];
    const float* fb2  = (const float*)d_in[23];
    const float* b2g  = (const float*)d_in[24];
    const float* b2b  = (const float*)d_in[25];
    const float* b2m  = (const float*)d_in[26];
    const float* b2v  = (const float*)d_in[27];
    float* out = (float*)d_out;

    const int attn_smem = 3 * 258 * 33 * 4;
    cudaFuncSetAttribute(k_attn,     cudaFuncAttributeMaxDynamicSharedMemorySize, attn_smem);
    cudaFuncSetAttribute(k_conv_mma, cudaFuncAttributeMaxDynamicSharedMemorySize, CV_TOT);
    cudaFuncSetAttribute(k_proj_mma, cudaFuncAttributeMaxDynamicSharedMemorySize, PJ_TOT);
    cudaFuncSetAttribute(k_mlp_mma,  cudaFuncAttributeMaxDynamicSharedMemorySize, SM_TOT);

    k_prep<<<9216, 256>>>(w1, w2, qkvw, pw);
    k_conv_mma<<<dim3(6, 129), 512, CV_TOT>>>(x, n1g, n1b, n1m, n1v, qg, qb, qm, qv);
    k_attn<<<512, 256, attn_smem>>>();
    k_proj_mma<<<dim3(2, 1088), 512, PJ_TOT>>>(pb, x, out);
    k_mlp_mma<<<2176, 512, SM_TOT>>>(out,
                                     b1g, b1b, b1m, b1v, fb1,
                                     b2g, b2b, b2m, b2v, fb2,
                                     n2g, n2b, n2m, n2v, out);
}

// round 6
// speedup vs baseline: 7.1179x; 1.3899x over previous
#include <cuda_runtime.h>
#include <cuda_fp16.h>
#include <math.h>
#include <stdint.h>

#define BATCH 64
#define CDIM 256
#define TDIM 128
#define JDIM 17
#define TJ 2176     // TDIM*JDIM
#define HCC 43
#define WCC 6
#define HW 258      // HCC*WCC
#define HIDDEN 1024

// scratch (static __device__ globals per harness rules)
__device__ float g_qkv[(size_t)3 * BATCH * HW * CDIM];   // [b][t(3)][hw][c]
__device__ float g_att[(size_t)BATCH * HW * CDIM];       // [b][hw][c]
__device__ __half g_xn[(size_t)BATCH * CDIM * TJ];       // n1bn(x) fp16
// fp16 weights
__device__ __half g_w1h[8 * 32768];            // W1 per-tile layout
__device__ __half g_w2h[8 * 32768];            // W2 per-tile layout
__device__ __half g_qwh[768 * 2304];           // qkv conv weight row-major
__device__ __half g_pwh[256 * 256];            // proj weight row-major

__device__ __forceinline__ float gelu_exact(float v) {
    return 0.5f * v * (1.0f + erff(v * 0.70710678118654752f));
}

__device__ __forceinline__ uint32_t smem_u32(const void* p) {
    uint32_t a;
    asm("{ .reg .u64 t; cvta.to.shared.u64 t, %1; cvt.u32.u64 %0, t; }" : "=r"(a) : "l"(p));
    return a;
}

#define LDM_X4(r, addr) \
    asm volatile("ldmatrix.sync.aligned.m8n8.x4.shared.b16 {%0,%1,%2,%3}, [%4];" \
        : "=r"((r)[0]), "=r"((r)[1]), "=r"((r)[2]), "=r"((r)[3]) : "r"(addr))

#define MMA16816(d, a, b0, b1) \
    asm volatile("mma.sync.aligned.m16n8k16.row.col.f32.f16.f16.f32 " \
        "{%0,%1,%2,%3}, {%4,%5,%6,%7}, {%8,%9}, {%0,%1,%2,%3};" \
        : "+f"((d)[0]), "+f"((d)[1]), "+f"((d)[2]), "+f"((d)[3]) \
        : "r"((a)[0]), "r"((a)[1]), "r"((a)[2]), "r"((a)[3]), "r"(b0), "r"(b1))

#define CP_ASYNC16(dst, src) \
    asm volatile("cp.async.cg.shared.global [%0], [%1], 16;" :: "r"(dst), "l"(src))
#define CP_COMMIT() asm volatile("cp.async.commit_group;")
#define CP_WAIT1()  asm volatile("cp.async.wait_group 1;" ::: "memory")
#define CP_WAIT0()  asm volatile("cp.async.wait_group 0;" ::: "memory")

// ---------------------------------------------------------------------------
// K0a: pre-convert all weights fp32 -> fp16
// ---------------------------------------------------------------------------
__global__ void __launch_bounds__(256) k_prep(const float* __restrict__ w1,
                                              const float* __restrict__ w2,
                                              const float* __restrict__ qkvw,
                                              const float* __restrict__ pw)
{
    int idx = blockIdx.x * 256 + threadIdx.x;
    if (idx < 262144) {
        int j = idx >> 8, i = idx & 255;
        int nt = j >> 7, jl = j & 127;
        g_w1h[(uint32_t)nt * 32768 + (uint32_t)jl * 256 + i] = __float2half(w1[idx]);
    } else if (idx < 524288) {
        int t = idx - 262144;
        int c = t >> 10, j = t & 1023;
        int nt = j >> 7, jl = j & 127;
        g_w2h[(uint32_t)nt * 32768 + (uint32_t)c * 128 + jl] = __float2half(w2[t]);
    } else if (idx < 2293760) {
        int t = idx - 524288;
        g_qwh[t] = __float2half(qkvw[t]);
    } else {
        int t = idx - 2293760;
        g_pwh[t] = __float2half(pw[t]);
    }
}

// ---------------------------------------------------------------------------
// K0b: xn = n1bn(x) as fp16 (BN applied once; conv gather becomes 2B moves)
// one block per (b,c) row
// ---------------------------------------------------------------------------
__global__ void __launch_bounds__(512) k_prexn(
    const float* __restrict__ x,
    const float* __restrict__ n1g, const float* __restrict__ n1b,
    const float* __restrict__ n1m, const float* __restrict__ n1v)
{
    __shared__ float ss, tt;
    const int bc = blockIdx.x;
    const int c = bc & 255;
    if (threadIdx.x == 0) {
        float s = n1g[c] * rsqrtf(n1v[c] + 1e-5f);
        ss = s;
        tt = n1b[c] - n1m[c] * s;
    }
    __syncthreads();
    const float* xr = x + (size_t)bc * TJ;
    __half* xo = g_xn + (size_t)bc * TJ;
    float s = ss, t = tt;
    for (int p = threadIdx.x; p < TJ; p += 512)
        xo[p] = __float2half(xr[p] * s + t);
}

// ---------------------------------------------------------------------------
// K1: conv QKV on HMMA, merged M: one CTA = 256 out-ch x 128 positions.
// W staged via cp.async (double buffered); P (im2col fp16) prefetched into
// registers while MMAs run.
// ---------------------------------------------------------------------------
#define CV_KTAB  0                      // uint16[2304] = 4608
#define CV_GXO   4608                   // int[128]
#define CV_GY    5120                   // int16[128]
#define CV_GX    5376                   // int16[128] -> 5632
#define CV_SO    5632                   // float[256]
#define CV_TO    6656                   // float[256] -> 7680
#define CV_PBUF  7680                   // 2 x 18432 = 36864
#define CV_WBUF  (CV_PBUF + 36864)      // 44544, 2 x 36864 = 73728
#define CV_STAGE CV_PBUF                // float[128*129] = 66048 (reuse)
#define CV_TOT   (CV_WBUF + 73728)      // 118272

__global__ void __launch_bounds__(512, 1) k_conv_mma(
    const float* __restrict__ qg, const float* __restrict__ qb,
    const float* __restrict__ qm, const float* __restrict__ qv)
{
    extern __shared__ char smem[];
    const uint32_t sbase = smem_u32(smem);
    const int tid = threadIdx.x;
    const int wid = tid >> 5, lane = tid & 31;
    const int wy = wid & 3, wx = wid >> 2;

    const int m0 = blockIdx.x * 256;   // out-channel base (0/256/512)
    const int n0 = blockIdx.y * 128;   // global position base

    uint16_t* ktab = (uint16_t*)(smem + CV_KTAB);
    int*      gxo  = (int*)(smem + CV_GXO);
    int16_t*  gyv  = (int16_t*)(smem + CV_GY);
    int16_t*  gxv  = (int16_t*)(smem + CV_GX);
    float*    s_o  = (float*)(smem + CV_SO);
    float*    t_o  = (float*)(smem + CV_TO);

    if (tid < 256) {
        int o = m0 + tid;
        float s = qg[o] * rsqrtf(qv[o] + 1e-5f);
        s_o[tid] = s;
        t_o[tid] = qb[o] - qm[o] * s;
    } else if (tid < 384) {
        int gl = tid - 256;
        int g = n0 + gl;
        int b = g / HW, hw = g - b * HW;
        int y = hw / WCC, xx = hw - y * WCC;
        gxo[gl] = b * (CDIM * TJ);
        gyv[gl] = (int16_t)(3 * y - 1);
        gxv[gl] = (int16_t)(3 * xx - 1);
    }
    for (int k = tid; k < 2304; k += 512) {
        int i = k / 9, r = k - i * 9;
        int ky = r / 3, kx = r - ky * 3;
        ktab[k] = (uint16_t)((i << 4) | (ky << 2) | kx);
    }
    __syncthreads();

    const uint32_t a_row  = (lane & 7) + ((lane >> 3) & 1) * 8;
    const uint32_t a_koff = (lane >> 4) * 8;
    const uint32_t b_row  = (lane & 7) + (lane >> 4) * 8;
    const uint32_t b_koff = ((lane >> 3) & 1) * 8;

    const int kk_fix = tid & 63;
    const int gl0    = tid >> 6;

    unsigned short pv[16];

    auto cpW = [&](int kc, int bsel) {
        uint32_t dstb = sbase + CV_WBUF + (uint32_t)bsel * 36864;
#pragma unroll
        for (int t = 0; t < 4; t++) {
            int e = tid + t * 512;
            int row = e >> 3, col = e & 7;
            CP_ASYNC16(dstb + ((uint32_t)row * 72 + col * 8) * 2,
                       (const void*)(g_qwh + (size_t)(m0 + row) * 2304 + kc + col * 8));
        }
    };
    auto gatherP = [&](int kc) {
        uint32_t kt = ktab[kc + kk_fix];
        int i = kt >> 4, ky = (kt >> 2) & 3, kx = kt & 3;
#pragma unroll
        for (int t = 0; t < 16; t++) {
            int gl = gl0 + 8 * t;
            int iy = gyv[gl] + ky, ix = gxv[gl] + kx;
            unsigned short v = 0;
            if ((unsigned)iy < (unsigned)TDIM && (unsigned)ix < (unsigned)JDIM)
                v = *(const unsigned short*)&g_xn[gxo[gl] + i * TJ + iy * JDIM + ix];
            pv[t] = v;
        }
    };
    auto storeP = [&](int bsel) {
        char* pb2 = smem + CV_PBUF + bsel * 18432;
#pragma unroll
        for (int t = 0; t < 16; t++) {
            int gl = gl0 + 8 * t;
            *(unsigned short*)(pb2 + ((uint32_t)gl * 72 + kk_fix) * 2) = pv[t];
        }
    };

    float d[4][4][4];
#pragma unroll
    for (int mi = 0; mi < 4; mi++)
#pragma unroll
        for (int nf = 0; nf < 4; nf++)
#pragma unroll
            for (int q = 0; q < 4; q++) d[mi][nf][q] = 0.f;

    // prologue
    cpW(0, 0); CP_COMMIT();
    gatherP(0); storeP(0);

    for (int c = 0; c < 36; c++) {
        if (c < 35) {
            cpW((c + 1) * 64, (c + 1) & 1); CP_COMMIT();
            gatherP((c + 1) * 64);
            CP_WAIT1();
        } else {
            CP_WAIT0();
        }
        __syncthreads();   // WB(c&1), PBUF(c&1) visible

        const uint32_t wsb = sbase + CV_WBUF + (uint32_t)(c & 1) * 36864;
        const uint32_t psb = sbase + CV_PBUF + (uint32_t)(c & 1) * 18432;
#pragma unroll
        for (int ks = 0; ks < 4; ks++) {
            const int k0 = ks * 16;
            uint32_t b0[4], b1[4];
            LDM_X4(b0, psb + (((uint32_t)(wx * 32)      + b_row) * 72 + k0 + b_koff) * 2);
            LDM_X4(b1, psb + (((uint32_t)(wx * 32 + 16) + b_row) * 72 + k0 + b_koff) * 2);
            uint32_t a[4][4];
#pragma unroll
            for (int mi = 0; mi < 4; mi++)
                LDM_X4(a[mi], wsb + (((uint32_t)(wy * 64 + mi * 16) + a_row) * 72
                                      + k0 + a_koff) * 2);
#pragma unroll
            for (int mi = 0; mi < 4; mi++) {
                MMA16816(d[mi][0], a[mi], b0[0], b0[1]);
                MMA16816(d[mi][1], a[mi], b0[2], b0[3]);
                MMA16816(d[mi][2], a[mi], b1[0], b1[1]);
                MMA16816(d[mi][3], a[mi], b1[2], b1[3]);
            }
        }
        if (c < 35) storeP((c + 1) & 1);
        __syncthreads();
    }

    // epilogue in two channel-halves (stage = [pos 128][ch 128] stride 129)
    float* stage = (float*)(smem + CV_STAGE);
    const int tpart = blockIdx.x;
#pragma unroll
    for (int h = 0; h < 2; h++) {
        if ((wy >> 1) == h) {
            int r = lane >> 2, c2 = (lane & 3) * 2;
#pragma unroll
            for (int mi = 0; mi < 4; mi++) {
                int row = wy * 64 + mi * 16 + r - 128 * h;
#pragma unroll
                for (int nf = 0; nf < 4; nf++) {
                    int col = wx * 32 + nf * 8 + c2;
                    stage[col * 129 + row]           = d[mi][nf][0];
                    stage[(col + 1) * 129 + row]     = d[mi][nf][1];
                    stage[col * 129 + row + 8]       = d[mi][nf][2];
                    stage[(col + 1) * 129 + row + 8] = d[mi][nf][3];
                }
            }
        }
        __syncthreads();
        for (int e = tid; e < 16384; e += 512) {
            int gl = e >> 7, cl = e & 127;
            int g = n0 + gl;
            int b = g / HW, hw = g - b * HW;
            int ch = 128 * h + cl;
            float v = stage[gl * 129 + cl] * s_o[ch] + t_o[ch];
            g_qkv[(((size_t)b * 3 + tpart) * HW + hw) * CDIM + ch] = gelu_exact(v);
        }
        __syncthreads();
    }
}

// ---------------------------------------------------------------------------
// K2: attention, 320 threads (one row per thread), q in registers,
// k/v in smem (68KB -> 3 CTAs/SM)
// ---------------------------------------------------------------------------
__global__ void __launch_bounds__(320) k_attn()
{
    extern __shared__ float sm[];
    float* ks = sm;
    float* vs = sm + 258 * 33;

    const int bh = blockIdx.x;
    const int b = bh >> 3, h = bh & 7;
    const int tid = threadIdx.x;

    const float* qg = g_qkv + (((size_t)b * 3 + 0) * HW) * CDIM + h * 32;
    const float* kg = g_qkv + (((size_t)b * 3 + 1) * HW) * CDIM + h * 32;
    const float* vg = g_qkv + (((size_t)b * 3 + 2) * HW) * CDIM + h * 32;

    for (int e = tid; e < HW * 32; e += 320) {
        int r = e >> 5, d = e & 31;
        ks[r * 33 + d] = kg[(size_t)r * CDIM + d];
        vs[r * 33 + d] = vg[(size_t)r * CDIM + d];
    }
    __syncthreads();

    if (tid < HW) {
        const int r = tid;
        const float scale = 0.17677669529663687f;
        float qr[32];
        const float4* q4 = (const float4*)(qg + (size_t)r * CDIM);
#pragma unroll
        for (int d4 = 0; d4 < 8; d4++) {
            float4 t = q4[d4];
            qr[d4 * 4 + 0] = t.x; qr[d4 * 4 + 1] = t.y;
            qr[d4 * 4 + 2] = t.z; qr[d4 * 4 + 3] = t.w;
        }
        float m = -1e30f, l = 0.f;
        float acc[32];
#pragma unroll
        for (int d = 0; d < 32; d++) acc[d] = 0.f;
        for (int j = 0; j < HW; j++) {
            const float* kj = ks + j * 33;
            float s = 0.f;
#pragma unroll
            for (int d = 0; d < 32; d++) s += qr[d] * kj[d];
            s *= scale;
            float mn = fmaxf(m, s);
            float corr = __expf(m - mn);
            float p = __expf(s - mn);
            l = l * corr + p;
            const float* vj = vs + j * 33;
#pragma unroll
            for (int d = 0; d < 32; d++) acc[d] = acc[d] * corr + p * vj[d];
            m = mn;
        }
        float inv = 1.f / l;
        float* og = g_att + ((size_t)b * HW + r) * CDIM + h * 32;
#pragma unroll
        for (int d = 0; d < 32; d++) og[d] = acc[d] * inv;
    }
}

// ---------------------------------------------------------------------------
// K3: proj on HMMA, merged M: one CTA = 256 ch x 128 positions; gather once.
// ---------------------------------------------------------------------------
#define PJ_PB    0                      // float[256]
#define PJ_O00   1024
#define PJ_O01   1536
#define PJ_O10   2048
#define PJ_O11   2560
#define PJ_WXT   3072
#define PJ_WYT   3584                   // -> 4096
#define PJ_PS    4096                   // [128][264] half = 67584 -> 71680
#define PJ_WBUF  71680                  // 2 x 36864 = 73728 -> 145408
#define PJ_STAGE PJ_PS                  // 66048 reuse
#define PJ_TOT   145408

__global__ void __launch_bounds__(512, 1) k_proj_mma(
    const float* __restrict__ pb,
    const float* __restrict__ x, float* __restrict__ x1)
{
    extern __shared__ char smem[];
    const uint32_t sbase = smem_u32(smem);
    const int tid = threadIdx.x;
    const int wid = tid >> 5, lane = tid & 31;
    const int wy = wid & 3, wx = wid >> 2;

    const int b  = blockIdx.x / 17;
    const int p0 = (blockIdx.x - b * 17) * 128;

    float* pbs = (float*)(smem + PJ_PB);
    int*   o00 = (int*)(smem + PJ_O00);
    int*   o01 = (int*)(smem + PJ_O01);
    int*   o10 = (int*)(smem + PJ_O10);
    int*   o11 = (int*)(smem + PJ_O11);
    float* wxs = (float*)(smem + PJ_WXT);
    float* wys = (float*)(smem + PJ_WYT);

    if (tid < 128) {
        int p = p0 + tid;
        int t = p / JDIM, j = p - t * JDIM;
        float sy = (t + 0.5f) * (43.0f / 128.0f) - 0.5f;
        sy = fminf(fmaxf(sy, 0.f), 42.f);
        int y0 = (int)sy;
        int y1 = min(y0 + 1, 42);
        float fy = sy - y0;
        float sx = (j + 0.5f) * (6.0f / 17.0f) - 0.5f;
        sx = fminf(fmaxf(sx, 0.f), 5.f);
        int x0 = (int)sx;
        int x1i = min(x0 + 1, 5);
        float fx = sx - x0;
        o00[tid] = (y0 * WCC + x0) * CDIM;
        o01[tid] = (y0 * WCC + x1i) * CDIM;
        o10[tid] = (y1 * WCC + x0) * CDIM;
        o11[tid] = (y1 * WCC + x1i) * CDIM;
        wxs[tid] = fx;
        wys[tid] = fy;
    } else if (tid < 384) {
        pbs[tid - 128] = pb[tid - 128];
    }
    __syncthreads();

    // gather ALL of P once: [128 pos][256 k] fp16 stride 264
    const float* abase = g_att + (size_t)b * HW * CDIM;
    for (int e = tid; e < 32768; e += 512) {
        int k = e & 255, gl = e >> 8;
        const float* bp = abase + k;
        float fx = wxs[gl], fy = wys[gl];
        float a00 = bp[o00[gl]];
        float a01 = bp[o01[gl]];
        float a10 = bp[o10[gl]];
        float a11 = bp[o11[gl]];
        float v = (a00 * (1.f - fx) + a01 * fx) * (1.f - fy)
                + (a10 * (1.f - fx) + a11 * fx) * fy;
        *(__half*)(smem + PJ_PS + ((uint32_t)gl * 264 + k) * 2) = __float2half(v);
    }

    auto cpW = [&](int kc, int bsel) {
        uint32_t dstb = sbase + PJ_WBUF + (uint32_t)bsel * 36864;
#pragma unroll
        for (int t = 0; t < 4; t++) {
            int e = tid + t * 512;
            int row = e >> 3, col = e & 7;
            CP_ASYNC16(dstb + ((uint32_t)row * 72 + col * 8) * 2,
                       (const void*)(g_pwh + (size_t)row * 256 + kc + col * 8));
        }
    };

    const uint32_t a_row  = (lane & 7) + ((lane >> 3) & 1) * 8;
    const uint32_t a_koff = (lane >> 4) * 8;
    const uint32_t b_row  = (lane & 7) + (lane >> 4) * 8;
    const uint32_t b_koff = ((lane >> 3) & 1) * 8;
    const uint32_t ps_base = sbase + PJ_PS;

    float d[4][4][4];
#pragma unroll
    for (int mi = 0; mi < 4; mi++)
#pragma unroll
        for (int nf = 0; nf < 4; nf++)
#pragma unroll
            for (int q = 0; q < 4; q++) d[mi][nf][q] = 0.f;

    cpW(0, 0); CP_COMMIT();

    for (int c = 0; c < 4; c++) {
        if (c < 3) {
            cpW((c + 1) * 64, (c + 1) & 1); CP_COMMIT();
            CP_WAIT1();
        } else {
            CP_WAIT0();
        }
        __syncthreads();   // WB(c&1) + (first iter) PS visible

        const uint32_t wsb = sbase + PJ_WBUF + (uint32_t)(c & 1) * 36864;
#pragma unroll
        for (int ks = 0; ks < 4; ks++) {
            const int k0 = ks * 16;
            const int kg = c * 64 + k0;
            uint32_t b0[4], b1[4];
            LDM_X4(b0, ps_base + (((uint32_t)(wx * 32)      + b_row) * 264 + kg + b_koff) * 2);
            LDM_X4(b1, ps_base + (((uint32_t)(wx * 32 + 16) + b_row) * 264 + kg + b_koff) * 2);
            uint32_t a[4][4];
#pragma unroll
            for (int mi = 0; mi < 4; mi++)
                LDM_X4(a[mi], wsb + (((uint32_t)(wy * 64 + mi * 16) + a_row) * 72
                                      + k0 + a_koff) * 2);
#pragma unroll
            for (int mi = 0; mi < 4; mi++) {
                MMA16816(d[mi][0], a[mi], b0[0], b0[1]);
                MMA16816(d[mi][1], a[mi], b0[2], b0[3]);
                MMA16816(d[mi][2], a[mi], b1[0], b1[1]);
                MMA16816(d[mi][3], a[mi], b1[2], b1[3]);
            }
        }
        __syncthreads();
    }

    // epilogue in two channel-halves
    float* stage = (float*)(smem + PJ_STAGE);
#pragma unroll
    for (int h = 0; h < 2; h++) {
        if ((wy >> 1) == h) {
            int r = lane >> 2, c2 = (lane & 3) * 2;
#pragma unroll
            for (int mi = 0; mi < 4; mi++) {
                int row = wy * 64 + mi * 16 + r - 128 * h;
#pragma unroll
                for (int nf = 0; nf < 4; nf++) {
                    int col = wx * 32 + nf * 8 + c2;
                    stage[col * 129 + row]           = d[mi][nf][0];
                    stage[(col + 1) * 129 + row]     = d[mi][nf][1];
                    stage[col * 129 + row + 8]       = d[mi][nf][2];
                    stage[(col + 1) * 129 + row + 8] = d[mi][nf][3];
                }
            }
        }
        __syncthreads();
        for (int e = tid; e < 16384; e += 512) {
            int gl = e & 127, cl = e >> 7;
            int ch = 128 * h + cl;
            size_t idx = ((size_t)b * CDIM + ch) * TJ + p0 + gl;
            x1[idx] = x[idx] + stage[gl * 129 + cl] + pbs[ch];
        }
        __syncthreads();
    }
}

// ---------------------------------------------------------------------------
// K4: fused MLP on HMMA, weight prefetch pipelined into registers (round 5)
// ---------------------------------------------------------------------------
#define SM_SN   0
#define SM_TN   1024
#define SM_S2   2048
#define SM_T2   3072
#define SM_S1   4096
#define SM_T1   4608
#define SM_XS   5120
#define SM_HS   (SM_XS + 33792)
#define SM_WB   (SM_HS + 17408)           // 56320
#define SM_TOT  (SM_WB + 69632)           // 125952

#define W1_STRIDE 264
#define H_STRIDE  136

__global__ void __launch_bounds__(512, 1) k_mlp_mma(
    const float* x1,
    const float* __restrict__ b1g, const float* __restrict__ b1b,
    const float* __restrict__ b1m, const float* __restrict__ b1v,
    const float* __restrict__ fb1,
    const float* __restrict__ b2g, const float* __restrict__ b2b,
    const float* __restrict__ b2m, const float* __restrict__ b2v,
    const float* __restrict__ fb2,
    const float* __restrict__ n2g, const float* __restrict__ n2b,
    const float* __restrict__ n2m, const float* __restrict__ n2v,
    float* out)
{
    extern __shared__ char smem[];
    const uint32_t sbase = smem_u32(smem);
    const int tid = threadIdx.x;
    const int wid = tid >> 5;
    const int lane = tid & 31;
    const int wy = wid & 1;
    const int wx = wid >> 1;

    const int blk = blockIdx.x;
    const int b = blk / 34;
    const int p0 = (blk - b * 34) * 64;

    float* sn = (float*)(smem + SM_SN);
    float* tn = (float*)(smem + SM_TN);
    float* s2 = (float*)(smem + SM_S2);
    float* t2 = (float*)(smem + SM_T2);
    float* s1 = (float*)(smem + SM_S1);
    float* t1 = (float*)(smem + SM_T1);

    if (tid < 256) {
        float s = n2g[tid] * rsqrtf(n2v[tid] + 1e-5f);
        sn[tid] = s;
        tn[tid] = n2b[tid] - n2m[tid] * s;
    } else {
        int c = tid - 256;
        float s = b2g[c] * rsqrtf(b2v[c] + 1e-5f);
        s2[c] = s;
        t2[c] = b2b[c] - b2m[c] * s + fb2[c] * s;
    }

    uint4 wv[8];
    auto ldW1 = [&](int nt) {
        const uint4* s = (const uint4*)(g_w1h + nt * 32768);
#pragma unroll
        for (int t = 0; t < 8; t++) wv[t] = s[tid + t * 512];
    };
    auto stW1 = [&]() {
#pragma unroll
        for (int t = 0; t < 8; t++) {
            int e = tid + t * 512;
            int row = (e >> 5) & 127, col = e & 31;
            *(uint4*)(smem + SM_WB + ((uint32_t)row * W1_STRIDE + col * 8) * 2) = wv[t];
        }
    };
    auto ldW2 = [&](int nt) {
        const uint4* s = (const uint4*)(g_w2h + nt * 32768);
#pragma unroll
        for (int t = 0; t < 8; t++) wv[t] = s[tid + t * 512];
    };
    auto stW2 = [&]() {
#pragma unroll
        for (int t = 0; t < 8; t++) {
            int e = tid + t * 512;
            int row = (e >> 4) & 255, col = e & 15;
            *(uint4*)(smem + SM_WB + ((uint32_t)row * H_STRIDE + col * 8) * 2) = wv[t];
        }
    };
    auto ldBN1 = [&](int nt) {
        if (tid < 128) {
            int j = nt * 128 + tid;
            float s = b1g[j] * rsqrtf(b1v[j] + 1e-5f);
            s1[tid] = s;
            t1[tid] = b1b[j] - b1m[j] * s + fb1[j] * s;
        }
    };

    __syncthreads();

    const float* xb = x1 + (size_t)b * CDIM * TJ;
    for (int e = tid; e < 16384; e += 512) {
        int i = e >> 6, p = e & 63;
        float v = xb[(size_t)i * TJ + p0 + p] * sn[i] + tn[i];
        *(__half*)(smem + SM_XS + ((uint32_t)p * W1_STRIDE + i) * 2) = __float2half(v);
    }

    const uint32_t a_row  = (lane & 7) + ((lane >> 3) & 1) * 8;
    const uint32_t a_koff = (lane >> 4) * 8;
    const uint32_t b_row  = (lane & 7) + (lane >> 4) * 8;
    const uint32_t b_koff = ((lane >> 3) & 1) * 8;

    const uint32_t xs_base = sbase + SM_XS;
    const uint32_t hs_base = sbase + SM_HS;
    const uint32_t wb_base = sbase + SM_WB;

    float d2[2][4][4];
#pragma unroll
    for (int i0 = 0; i0 < 2; i0++)
#pragma unroll
        for (int j0 = 0; j0 < 4; j0++)
#pragma unroll
            for (int q = 0; q < 4; q++) d2[i0][j0][q] = 0.f;

    ldW1(0); stW1(); ldBN1(0);
    __syncthreads();

    for (int nt = 0; nt < 8; nt++) {
        ldW2(nt);

        float dH[2][2][4];
#pragma unroll
        for (int i0 = 0; i0 < 2; i0++)
#pragma unroll
            for (int j0 = 0; j0 < 2; j0++)
#pragma unroll
                for (int q = 0; q < 4; q++) dH[i0][j0][q] = 0.f;

#pragma unroll 4
        for (int k0 = 0; k0 < 256; k0 += 16) {
            uint32_t a[2][4];
#pragma unroll
            for (int mi = 0; mi < 2; mi++) {
                uint32_t addr = xs_base
                    + (((uint32_t)(wy * 32 + mi * 16) + a_row) * W1_STRIDE + k0 + a_koff) * 2;
                LDM_X4(a[mi], addr);
            }
            uint32_t bh[4];
            LDM_X4(bh, wb_base + (((uint32_t)(wx * 16) + b_row) * W1_STRIDE + k0 + b_koff) * 2);
#pragma unroll
            for (int mi = 0; mi < 2; mi++) {
                MMA16816(dH[mi][0], a[mi], bh[0], bh[1]);
                MMA16816(dH[mi][1], a[mi], bh[2], bh[3]);
            }
        }

        {
            int r = lane >> 2;
#pragma unroll
            for (int mi = 0; mi < 2; mi++) {
#pragma unroll
                for (int nf = 0; nf < 2; nf++) {
                    int c2 = wx * 16 + nf * 8 + (lane & 3) * 2;
                    float ss0 = s1[c2], tt0 = t1[c2];
                    float ss1 = s1[c2 + 1], tt1 = t1[c2 + 1];
                    int row0 = wy * 32 + mi * 16 + r;
                    float h0 = gelu_exact(dH[mi][nf][0] * ss0 + tt0);
                    float h1 = gelu_exact(dH[mi][nf][1] * ss1 + tt1);
                    float h2 = gelu_exact(dH[mi][nf][2] * ss0 + tt0);
                    float h3 = gelu_exact(dH[mi][nf][3] * ss1 + tt1);
                    *(__half2*)(smem + SM_HS + ((uint32_t)row0 * H_STRIDE + c2) * 2)
                        = __floats2half2_rn(h0, h1);
                    *(__half2*)(smem + SM_HS + ((uint32_t)(row0 + 8) * H_STRIDE + c2) * 2)
                        = __floats2half2_rn(h2, h3);
                }
            }
        }
        __syncthreads();

        stW2();
        if (nt < 7) ldW1(nt + 1);
        __syncthreads();

#pragma unroll
        for (int k0 = 0; k0 < 128; k0 += 16) {
            uint32_t a[2][4];
#pragma unroll
            for (int mi = 0; mi < 2; mi++) {
                uint32_t addr = hs_base
                    + (((uint32_t)(wy * 32 + mi * 16) + a_row) * H_STRIDE + k0 + a_koff) * 2;
                LDM_X4(a[mi], addr);
            }
#pragma unroll
            for (int nq = 0; nq < 2; nq++) {
                uint32_t bh[4];
                LDM_X4(bh, wb_base + (((uint32_t)(wx * 32 + nq * 16) + b_row) * H_STRIDE
                                       + k0 + b_koff) * 2);
#pragma unroll
                for (int mi = 0; mi < 2; mi++) {
                    MMA16816(d2[mi][nq * 2 + 0], a[mi], bh[0], bh[1]);
                    MMA16816(d2[mi][nq * 2 + 1], a[mi], bh[2], bh[3]);
                }
            }
        }
        __syncthreads();

        if (nt < 7) {
            stW1();
            ldBN1(nt + 1);
            __syncthreads();
        }
    }

    float* stage = (float*)(smem + SM_WB);
    {
        int r = lane >> 2;
#pragma unroll
        for (int mi = 0; mi < 2; mi++) {
            int row0 = wy * 32 + mi * 16 + r;
#pragma unroll
            for (int j0 = 0; j0 < 4; j0++) {
                int c = wx * 32 + j0 * 8 + (lane & 3) * 2;
                stage[row0 * 257 + c]       = d2[mi][j0][0];
                stage[row0 * 257 + c + 1]   = d2[mi][j0][1];
                stage[(row0 + 8) * 257 + c]     = d2[mi][j0][2];
                stage[(row0 + 8) * 257 + c + 1] = d2[mi][j0][3];
            }
        }
    }
    __syncthreads();

    for (int e = tid; e < 16384; e += 512) {
        int c = e >> 6, p = e & 63;
        size_t idx = ((size_t)b * CDIM + c) * TJ + p0 + p;
        out[idx] = x1[idx] + stage[p * 257 + c] * s2[c] + t2[c];
    }
}

// ---------------------------------------------------------------------------
extern "C" void kernel_launch(void* const* d_in, const int* in_sizes, int n_in,
                              void* d_out, int out_size)
{
    const float* x    = (const float*)d_in[0];
    const float* n1g  = (const float*)d_in[1];
    const float* n1b  = (const float*)d_in[2];
    const float* n1m  = (const float*)d_in[3];
    const float* n1v  = (const float*)d_in[4];
    const float* qkvw = (const float*)d_in[5];
    const float* qg   = (const float*)d_in[6];
    const float* qb   = (const float*)d_in[7];
    const float* qm   = (const float*)d_in[8];
    const float* qv   = (const float*)d_in[9];
    const float* pw   = (const float*)d_in[10];
    const float* pb   = (const float*)d_in[11];
    const float* n2g  = (const float*)d_in[12];
    const float* n2b  = (const float*)d_in[13];
    const float* n2m  = (const float*)d_in[14];
    const float* n2v  = (const float*)d_in[15];
    const float* w1   = (const float*)d_in[16];
    const float* fb1  = (const float*)d_in[17];
    const float* b1g  = (const float*)d_in[18];
    const float* b1b  = (const float*)d_in[19];
    const float* b1m  = (const float*)d_in[20];
    const float* b1v  = (const float*)d_in[21];
    const float* w2   = (const float*)d_in[22];
    const float* fb2  = (const float*)d_in[23];
    const float* b2g  = (const float*)d_in[24];
    const float* b2b  = (const float*)d_in[25];
    const float* b2m  = (const float*)d_in[26];
    const float* b2v  = (const float*)d_in[27];
    float* out = (float*)d_out;

    const int attn_smem = 2 * 258 * 33 * 4;   // 68112
    cudaFuncSetAttribute(k_attn,     cudaFuncAttributeMaxDynamicSharedMemorySize, attn_smem);
    cudaFuncSetAttribute(k_conv_mma, cudaFuncAttributeMaxDynamicSharedMemorySize, CV_TOT);
    cudaFuncSetAttribute(k_proj_mma, cudaFuncAttributeMaxDynamicSharedMemorySize, PJ_TOT);
    cudaFuncSetAttribute(k_mlp_mma,  cudaFuncAttributeMaxDynamicSharedMemorySize, SM_TOT);

    k_prep<<<9216, 256>>>(w1, w2, qkvw, pw);
    k_prexn<<<16384, 512>>>(x, n1g, n1b, n1m, n1v);
    k_conv_mma<<<dim3(3, 129), 512, CV_TOT>>>(qg, qb, qm, qv);
    k_attn<<<512, 320, attn_smem>>>();
    k_proj_mma<<<1088, 512, PJ_TOT>>>(pb, x, out);
    k_mlp_mma<<<2176, 512, SM_TOT>>>(out,
                                     b1g, b1b, b1m, b1v, fb1,
                                     b2g, b2b, b2m, b2v, fb2,
                                     n2g, n2b, n2m, n2v, out);
}

// round 8
// speedup vs baseline: 8.4475x; 1.1868x over previous
#include <cuda_runtime.h>
#include <cuda_fp16.h>
#include <math.h>
#include <stdint.h>

#define BATCH 64
#define CDIM 256
#define TDIM 128
#define JDIM 17
#define TJ 2176     // TDIM*JDIM
#define HCC 43
#define WCC 6
#define HW 258      // HCC*WCC
#define HIDDEN 1024

// scratch (static __device__ globals per harness rules)
__device__ float g_qkv[(size_t)3 * BATCH * HW * CDIM];   // [b][t(3)][hw][c]
__device__ float g_att[(size_t)BATCH * HW * CDIM];       // [b][hw][c]
__device__ __half g_xn[(size_t)BATCH * CDIM * TJ];       // n1bn(x) fp16
// fp16 weights
__device__ __half g_w1h[8 * 32768];            // W1 per-tile layout
__device__ __half g_w2h[8 * 32768];            // W2 per-tile layout
__device__ __half g_qwh[768 * 2304];           // qkv conv weight row-major
__device__ __half g_pwh[256 * 256];            // proj weight row-major

__device__ __forceinline__ float gelu_exact(float v) {
    return 0.5f * v * (1.0f + erff(v * 0.70710678118654752f));
}

__device__ __forceinline__ uint32_t smem_u32(const void* p) {
    uint32_t a;
    asm("{ .reg .u64 t; cvta.to.shared.u64 t, %1; cvt.u32.u64 %0, t; }" : "=r"(a) : "l"(p));
    return a;
}

__device__ __forceinline__ uint32_t h2_to_u32(__half2 h) {
    return *reinterpret_cast<uint32_t*>(&h);
}

#define LDM_X4(r, addr) \
    asm volatile("ldmatrix.sync.aligned.m8n8.x4.shared.b16 {%0,%1,%2,%3}, [%4];" \
        : "=r"((r)[0]), "=r"((r)[1]), "=r"((r)[2]), "=r"((r)[3]) : "r"(addr))

#define LDM_X4_T(r, addr) \
    asm volatile("ldmatrix.sync.aligned.m8n8.x4.trans.shared.b16 {%0,%1,%2,%3}, [%4];" \
        : "=r"((r)[0]), "=r"((r)[1]), "=r"((r)[2]), "=r"((r)[3]) : "r"(addr))

#define MMA16816(d, a, b0, b1) \
    asm volatile("mma.sync.aligned.m16n8k16.row.col.f32.f16.f16.f32 " \
        "{%0,%1,%2,%3}, {%4,%5,%6,%7}, {%8,%9}, {%0,%1,%2,%3};" \
        : "+f"((d)[0]), "+f"((d)[1]), "+f"((d)[2]), "+f"((d)[3]) \
        : "r"((a)[0]), "r"((a)[1]), "r"((a)[2]), "r"((a)[3]), "r"(b0), "r"(b1))

#define CP_ASYNC16(dst, src) \
    asm volatile("cp.async.cg.shared.global [%0], [%1], 16;" :: "r"(dst), "l"(src))
#define CP_COMMIT() asm volatile("cp.async.commit_group;")
#define CP_WAIT1()  asm volatile("cp.async.wait_group 1;" ::: "memory")
#define CP_WAIT0()  asm volatile("cp.async.wait_group 0;" ::: "memory")

// ---------------------------------------------------------------------------
// K0a: pre-convert all weights fp32 -> fp16
// ---------------------------------------------------------------------------
__global__ void __launch_bounds__(256) k_prep(const float* __restrict__ w1,
                                              const float* __restrict__ w2,
                                              const float* __restrict__ qkvw,
                                              const float* __restrict__ pw)
{
    int idx = blockIdx.x * 256 + threadIdx.x;
    if (idx < 262144) {
        int j = idx >> 8, i = idx & 255;
        int nt = j >> 7, jl = j & 127;
        g_w1h[(uint32_t)nt * 32768 + (uint32_t)jl * 256 + i] = __float2half(w1[idx]);
    } else if (idx < 524288) {
        int t = idx - 262144;
        int c = t >> 10, j = t & 1023;
        int nt = j >> 7, jl = j & 127;
        g_w2h[(uint32_t)nt * 32768 + (uint32_t)c * 128 + jl] = __float2half(w2[t]);
    } else if (idx < 2293760) {
        int t = idx - 524288;
        g_qwh[t] = __float2half(qkvw[t]);
    } else {
        int t = idx - 2293760;
        g_pwh[t] = __float2half(pw[t]);
    }
}

// ---------------------------------------------------------------------------
// K0b: xn = n1bn(x) as fp16
// ---------------------------------------------------------------------------
__global__ void __launch_bounds__(512) k_prexn(
    const float* __restrict__ x,
    const float* __restrict__ n1g, const float* __restrict__ n1b,
    const float* __restrict__ n1m, const float* __restrict__ n1v)
{
    __shared__ float ss, tt;
    const int bc = blockIdx.x;
    const int c = bc & 255;
    if (threadIdx.x == 0) {
        float s = n1g[c] * rsqrtf(n1v[c] + 1e-5f);
        ss = s;
        tt = n1b[c] - n1m[c] * s;
    }
    __syncthreads();
    const float* xr = x + (size_t)bc * TJ;
    __half* xo = g_xn + (size_t)bc * TJ;
    float s = ss, t = tt;
    for (int p = threadIdx.x; p < TJ; p += 512)
        xo[p] = __float2half(xr[p] * s + t);
}

// ---------------------------------------------------------------------------
// K1: conv QKV on HMMA, merged M (unchanged from round 6)
// ---------------------------------------------------------------------------
#define CV_KTAB  0
#define CV_GXO   4608
#define CV_GY    5120
#define CV_GX    5376
#define CV_SO    5632
#define CV_TO    6656
#define CV_PBUF  7680
#define CV_WBUF  (CV_PBUF + 36864)
#define CV_STAGE CV_PBUF
#define CV_TOT   (CV_WBUF + 73728)

__global__ void __launch_bounds__(512, 1) k_conv_mma(
    const float* __restrict__ qg, const float* __restrict__ qb,
    const float* __restrict__ qm, const float* __restrict__ qv)
{
    extern __shared__ char smem[];
    const uint32_t sbase = smem_u32(smem);
    const int tid = threadIdx.x;
    const int wid = tid >> 5, lane = tid & 31;
    const int wy = wid & 3, wx = wid >> 2;

    const int m0 = blockIdx.x * 256;
    const int n0 = blockIdx.y * 128;

    uint16_t* ktab = (uint16_t*)(smem + CV_KTAB);
    int*      gxo  = (int*)(smem + CV_GXO);
    int16_t*  gyv  = (int16_t*)(smem + CV_GY);
    int16_t*  gxv  = (int16_t*)(smem + CV_GX);
    float*    s_o  = (float*)(smem + CV_SO);
    float*    t_o  = (float*)(smem + CV_TO);

    if (tid < 256) {
        int o = m0 + tid;
        float s = qg[o] * rsqrtf(qv[o] + 1e-5f);
        s_o[tid] = s;
        t_o[tid] = qb[o] - qm[o] * s;
    } else if (tid < 384) {
        int gl = tid - 256;
        int g = n0 + gl;
        int b = g / HW, hw = g - b * HW;
        int y = hw / WCC, xx = hw - y * WCC;
        gxo[gl] = b * (CDIM * TJ);
        gyv[gl] = (int16_t)(3 * y - 1);
        gxv[gl] = (int16_t)(3 * xx - 1);
    }
    for (int k = tid; k < 2304; k += 512) {
        int i = k / 9, r = k - i * 9;
        int ky = r / 3, kx = r - ky * 3;
        ktab[k] = (uint16_t)((i << 4) | (ky << 2) | kx);
    }
    __syncthreads();

    const uint32_t a_row  = (lane & 7) + ((lane >> 3) & 1) * 8;
    const uint32_t a_koff = (lane >> 4) * 8;
    const uint32_t b_row  = (lane & 7) + (lane >> 4) * 8;
    const uint32_t b_koff = ((lane >> 3) & 1) * 8;

    const int kk_fix = tid & 63;
    const int gl0    = tid >> 6;

    unsigned short pv[16];

    auto cpW = [&](int kc, int bsel) {
        uint32_t dstb = sbase + CV_WBUF + (uint32_t)bsel * 36864;
#pragma unroll
        for (int t = 0; t < 4; t++) {
            int e = tid + t * 512;
            int row = e >> 3, col = e & 7;
            CP_ASYNC16(dstb + ((uint32_t)row * 72 + col * 8) * 2,
                       (const void*)(g_qwh + (size_t)(m0 + row) * 2304 + kc + col * 8));
        }
    };
    auto gatherP = [&](int kc) {
        uint32_t kt = ktab[kc + kk_fix];
        int i = kt >> 4, ky = (kt >> 2) & 3, kx = kt & 3;
#pragma unroll
        for (int t = 0; t < 16; t++) {
            int gl = gl0 + 8 * t;
            int iy = gyv[gl] + ky, ix = gxv[gl] + kx;
            unsigned short v = 0;
            if ((unsigned)iy < (unsigned)TDIM && (unsigned)ix < (unsigned)JDIM)
                v = *(const unsigned short*)&g_xn[gxo[gl] + i * TJ + iy * JDIM + ix];
            pv[t] = v;
        }
    };
    auto storeP = [&](int bsel) {
        char* pb2 = smem + CV_PBUF + bsel * 18432;
#pragma unroll
        for (int t = 0; t < 16; t++) {
            int gl = gl0 + 8 * t;
            *(unsigned short*)(pb2 + ((uint32_t)gl * 72 + kk_fix) * 2) = pv[t];
        }
    };

    float d[4][4][4];
#pragma unroll
    for (int mi = 0; mi < 4; mi++)
#pragma unroll
        for (int nf = 0; nf < 4; nf++)
#pragma unroll
            for (int q = 0; q < 4; q++) d[mi][nf][q] = 0.f;

    cpW(0, 0); CP_COMMIT();
    gatherP(0); storeP(0);

    for (int c = 0; c < 36; c++) {
        if (c < 35) {
            cpW((c + 1) * 64, (c + 1) & 1); CP_COMMIT();
            gatherP((c + 1) * 64);
            CP_WAIT1();
        } else {
            CP_WAIT0();
        }
        __syncthreads();

        const uint32_t wsb = sbase + CV_WBUF + (uint32_t)(c & 1) * 36864;
        const uint32_t psb = sbase + CV_PBUF + (uint32_t)(c & 1) * 18432;
#pragma unroll
        for (int ks = 0; ks < 4; ks++) {
            const int k0 = ks * 16;
            uint32_t b0[4], b1[4];
            LDM_X4(b0, psb + (((uint32_t)(wx * 32)      + b_row) * 72 + k0 + b_koff) * 2);
            LDM_X4(b1, psb + (((uint32_t)(wx * 32 + 16) + b_row) * 72 + k0 + b_koff) * 2);
            uint32_t a[4][4];
#pragma unroll
            for (int mi = 0; mi < 4; mi++)
                LDM_X4(a[mi], wsb + (((uint32_t)(wy * 64 + mi * 16) + a_row) * 72
                                      + k0 + a_koff) * 2);
#pragma unroll
            for (int mi = 0; mi < 4; mi++) {
                MMA16816(d[mi][0], a[mi], b0[0], b0[1]);
                MMA16816(d[mi][1], a[mi], b0[2], b0[3]);
                MMA16816(d[mi][2], a[mi], b1[0], b1[1]);
                MMA16816(d[mi][3], a[mi], b1[2], b1[3]);
            }
        }
        if (c < 35) storeP((c + 1) & 1);
        __syncthreads();
    }

    float* stage = (float*)(smem + CV_STAGE);
    const int tpart = blockIdx.x;
#pragma unroll
    for (int h = 0; h < 2; h++) {
        if ((wy >> 1) == h) {
            int r = lane >> 2, c2 = (lane & 3) * 2;
#pragma unroll
            for (int mi = 0; mi < 4; mi++) {
                int row = wy * 64 + mi * 16 + r - 128 * h;
#pragma unroll
                for (int nf = 0; nf < 4; nf++) {
                    int col = wx * 32 + nf * 8 + c2;
                    stage[col * 129 + row]           = d[mi][nf][0];
                    stage[(col + 1) * 129 + row]     = d[mi][nf][1];
                    stage[col * 129 + row + 8]       = d[mi][nf][2];
                    stage[(col + 1) * 129 + row + 8] = d[mi][nf][3];
                }
            }
        }
        __syncthreads();
        for (int e = tid; e < 16384; e += 512) {
            int gl = e >> 7, cl = e & 127;
            int g = n0 + gl;
            int b = g / HW, hw = g - b * HW;
            int ch = 128 * h + cl;
            float v = stage[gl * 129 + cl] * s_o[ch] + t_o[ch];
            g_qkv[(((size_t)b * 3 + tpart) * HW + hw) * CDIM + ch] = gelu_exact(v);
        }
        __syncthreads();
    }
}

// ---------------------------------------------------------------------------
// K2: attention on HMMA (flash-attention-2 style). One (b,h) per CTA,
// 17 warps x 16 query rows (padded 258 -> 272). Q pre-scaled by 1/sqrt(32).
// ---------------------------------------------------------------------------
#define AT_STR  40                         // half stride per row (80 B)
#define AT_Q    0
#define AT_K    21760                      // 272*40*2
#define AT_V    43520
#define AT_TOT  65280

__global__ void __launch_bounds__(544) k_attn_mma()
{
    extern __shared__ char smem[];
    const uint32_t sbase = smem_u32(smem);
    __half* qs = (__half*)(smem + AT_Q);
    __half* ks = (__half*)(smem + AT_K);
    __half* vs = (__half*)(smem + AT_V);

    const int bh = blockIdx.x;
    const int b = bh >> 3, h = bh & 7;
    const int tid = threadIdx.x;
    const int wid = tid >> 5, lane = tid & 31;

    const float* qg = g_qkv + (((size_t)b * 3 + 0) * HW) * CDIM + h * 32;
    const float* kg = g_qkv + (((size_t)b * 3 + 1) * HW) * CDIM + h * 32;
    const float* vg = g_qkv + (((size_t)b * 3 + 2) * HW) * CDIM + h * 32;

    const float scale = 0.17677669529663687f;   // 1/sqrt(32)
    for (int e = tid; e < 272 * 32; e += 544) {
        int r = e >> 5, d = e & 31;
        float qv_ = 0.f, kv_ = 0.f, vv_ = 0.f;
        if (r < HW) {
            size_t off = (size_t)r * CDIM + d;
            qv_ = qg[off] * scale;
            kv_ = kg[off];
            vv_ = vg[off];
        }
        qs[r * AT_STR + d] = __float2half(qv_);
        ks[r * AT_STR + d] = __float2half(kv_);
        vs[r * AT_STR + d] = __float2half(vv_);
    }
    __syncthreads();

    const int m0 = wid * 16;
    const uint32_t a_row  = (lane & 7) + ((lane >> 3) & 1) * 8;
    const uint32_t a_koff = (lane >> 4) * 8;
    const uint32_t b_row  = (lane & 7) + (lane >> 4) * 8;
    const uint32_t b_koff = ((lane >> 3) & 1) * 8;
    const uint32_t v_row  = (lane & 7) + ((lane >> 3) & 1) * 8;   // k index
    const uint32_t v_col  = (lane >> 4) * 8;                       // dim offset

    const uint32_t qs_base = sbase + AT_Q;
    const uint32_t ks_base = sbase + AT_K;
    const uint32_t vs_base = sbase + AT_V;

    // Q fragments (constant across key chunks): 2 k-steps
    uint32_t qa[2][4];
    LDM_X4(qa[0], qs_base + (((uint32_t)m0 + a_row) * AT_STR + 0  + a_koff) * 2);
    LDM_X4(qa[1], qs_base + (((uint32_t)m0 + a_row) * AT_STR + 16 + a_koff) * 2);

    float o[4][4];
#pragma unroll
    for (int nt = 0; nt < 4; nt++)
#pragma unroll
        for (int q = 0; q < 4; q++) o[nt][q] = 0.f;
    float mr = -1e30f, mr8 = -1e30f, lr = 0.f, lr8 = 0.f;

    const int c2 = (lane & 3) * 2;

    for (int jt = 0; jt < 17; jt++) {
        // ---- S chunk [16 rows][16 keys] ----
        float s0[4] = {0.f, 0.f, 0.f, 0.f};
        float s1[4] = {0.f, 0.f, 0.f, 0.f};
        {
            uint32_t bb[4];
            LDM_X4(bb, ks_base + (((uint32_t)(jt * 16) + b_row) * AT_STR + 0 + b_koff) * 2);
            MMA16816(s0, qa[0], bb[0], bb[1]);
            MMA16816(s1, qa[0], bb[2], bb[3]);
            LDM_X4(bb, ks_base + (((uint32_t)(jt * 16) + b_row) * AT_STR + 16 + b_koff) * 2);
            MMA16816(s0, qa[1], bb[0], bb[1]);
            MMA16816(s1, qa[1], bb[2], bb[3]);
        }
        if (jt == 16) {   // mask keys >= 258
            if (256 + c2     >= HW) { s0[0] = -1e30f; s0[2] = -1e30f; }
            if (256 + c2 + 1 >= HW) { s0[1] = -1e30f; s0[3] = -1e30f; }
            if (256 + c2 + 8 >= HW) { s1[0] = -1e30f; s1[2] = -1e30f; }
            if (256 + c2 + 9 >= HW) { s1[1] = -1e30f; s1[3] = -1e30f; }
        }

        // ---- online softmax update (rows r and r+8) ----
        float cmr  = fmaxf(fmaxf(s0[0], s0[1]), fmaxf(s1[0], s1[1]));
        float cmr8 = fmaxf(fmaxf(s0[2], s0[3]), fmaxf(s1[2], s1[3]));
        cmr  = fmaxf(cmr,  __shfl_xor_sync(0xffffffffu, cmr, 1));
        cmr  = fmaxf(cmr,  __shfl_xor_sync(0xffffffffu, cmr, 2));
        cmr8 = fmaxf(cmr8, __shfl_xor_sync(0xffffffffu, cmr8, 1));
        cmr8 = fmaxf(cmr8, __shfl_xor_sync(0xffffffffu, cmr8, 2));
        float mnr  = fmaxf(mr, cmr);
        float mnr8 = fmaxf(mr8, cmr8);
        float corr  = __expf(mr - mnr);
        float corr8 = __expf(mr8 - mnr8);
        float p00 = __expf(s0[0] - mnr),  p01 = __expf(s0[1] - mnr);
        float p02 = __expf(s1[0] - mnr),  p03 = __expf(s1[1] - mnr);
        float p80 = __expf(s0[2] - mnr8), p81 = __expf(s0[3] - mnr8);
        float p82 = __expf(s1[2] - mnr8), p83 = __expf(s1[3] - mnr8);
        float ps  = p00 + p01 + p02 + p03;
        float ps8 = p80 + p81 + p82 + p83;
        ps  += __shfl_xor_sync(0xffffffffu, ps, 1);
        ps  += __shfl_xor_sync(0xffffffffu, ps, 2);
        ps8 += __shfl_xor_sync(0xffffffffu, ps8, 1);
        ps8 += __shfl_xor_sync(0xffffffffu, ps8, 2);
        lr  = lr  * corr  + ps;
        lr8 = lr8 * corr8 + ps8;
        mr = mnr; mr8 = mnr8;

        // P as A-fragment (C-layout -> A-layout repack)
        uint32_t pa[4];
        pa[0] = h2_to_u32(__floats2half2_rn(p00, p01));
        pa[1] = h2_to_u32(__floats2half2_rn(p80, p81));
        pa[2] = h2_to_u32(__floats2half2_rn(p02, p03));
        pa[3] = h2_to_u32(__floats2half2_rn(p82, p83));

        // rescale O
#pragma unroll
        for (int nt = 0; nt < 4; nt++) {
            o[nt][0] *= corr;  o[nt][1] *= corr;
            o[nt][2] *= corr8; o[nt][3] *= corr8;
        }

        // ---- O += P @ V (V via ldmatrix.trans) ----
        {
            uint32_t vb[4];
            LDM_X4_T(vb, vs_base + (((uint32_t)(jt * 16) + v_row) * AT_STR + 0 + v_col) * 2);
            MMA16816(o[0], pa, vb[0], vb[1]);
            MMA16816(o[1], pa, vb[2], vb[3]);
            LDM_X4_T(vb, vs_base + (((uint32_t)(jt * 16) + v_row) * AT_STR + 16 + v_col) * 2);
            MMA16816(o[2], pa, vb[0], vb[1]);
            MMA16816(o[3], pa, vb[2], vb[3]);
        }
    }

    // ---- write O / l ----
    const int r0 = m0 + (lane >> 2);
    float invr  = 1.f / lr;
    float invr8 = 1.f / lr8;
    if (r0 < HW) {
        float* og = g_att + ((size_t)b * HW + r0) * CDIM + h * 32 + c2;
#pragma unroll
        for (int nt = 0; nt < 4; nt++) {
            og[nt * 8 + 0] = o[nt][0] * invr;
            og[nt * 8 + 1] = o[nt][1] * invr;
        }
    }
    if (r0 + 8 < HW) {
        float* og = g_att + ((size_t)b * HW + r0 + 8) * CDIM + h * 32 + c2;
#pragma unroll
        for (int nt = 0; nt < 4; nt++) {
            og[nt * 8 + 0] = o[nt][2] * invr8;
            og[nt * 8 + 1] = o[nt][3] * invr8;
        }
    }
}

// ---------------------------------------------------------------------------
// K3: proj on HMMA, merged M (unchanged from round 6)
// ---------------------------------------------------------------------------
#define PJ_PB    0
#define PJ_O00   1024
#define PJ_O01   1536
#define PJ_O10   2048
#define PJ_O11   2560
#define PJ_WXT   3072
#define PJ_WYT   3584
#define PJ_PS    4096
#define PJ_WBUF  71680
#define PJ_STAGE PJ_PS
#define PJ_TOT   145408

__global__ void __launch_bounds__(512, 1) k_proj_mma(
    const float* __restrict__ pb,
    const float* __restrict__ x, float* __restrict__ x1)
{
    extern __shared__ char smem[];
    const uint32_t sbase = smem_u32(smem);
    const int tid = threadIdx.x;
    const int wid = tid >> 5, lane = tid & 31;
    const int wy = wid & 3, wx = wid >> 2;

    const int b  = blockIdx.x / 17;
    const int p0 = (blockIdx.x - b * 17) * 128;

    float* pbs = (float*)(smem + PJ_PB);
    int*   o00 = (int*)(smem + PJ_O00);
    int*   o01 = (int*)(smem + PJ_O01);
    int*   o10 = (int*)(smem + PJ_O10);
    int*   o11 = (int*)(smem + PJ_O11);
    float* wxs = (float*)(smem + PJ_WXT);
    float* wys = (float*)(smem + PJ_WYT);

    if (tid < 128) {
        int p = p0 + tid;
        int t = p / JDIM, j = p - t * JDIM;
        float sy = (t + 0.5f) * (43.0f / 128.0f) - 0.5f;
        sy = fminf(fmaxf(sy, 0.f), 42.f);
        int y0 = (int)sy;
        int y1 = min(y0 + 1, 42);
        float fy = sy - y0;
        float sx = (j + 0.5f) * (6.0f / 17.0f) - 0.5f;
        sx = fminf(fmaxf(sx, 0.f), 5.f);
        int x0 = (int)sx;
        int x1i = min(x0 + 1, 5);
        float fx = sx - x0;
        o00[tid] = (y0 * WCC + x0) * CDIM;
        o01[tid] = (y0 * WCC + x1i) * CDIM;
        o10[tid] = (y1 * WCC + x0) * CDIM;
        o11[tid] = (y1 * WCC + x1i) * CDIM;
        wxs[tid] = fx;
        wys[tid] = fy;
    } else if (tid < 384) {
        pbs[tid - 128] = pb[tid - 128];
    }
    __syncthreads();

    const float* abase = g_att + (size_t)b * HW * CDIM;
    for (int e = tid; e < 32768; e += 512) {
        int k = e & 255, gl = e >> 8;
        const float* bp = abase + k;
        float fx = wxs[gl], fy = wys[gl];
        float a00 = bp[o00[gl]];
        float a01 = bp[o01[gl]];
        float a10 = bp[o10[gl]];
        float a11 = bp[o11[gl]];
        float v = (a00 * (1.f - fx) + a01 * fx) * (1.f - fy)
                + (a10 * (1.f - fx) + a11 * fx) * fy;
        *(__half*)(smem + PJ_PS + ((uint32_t)gl * 264 + k) * 2) = __float2half(v);
    }

    auto cpW = [&](int kc, int bsel) {
        uint32_t dstb = sbase + PJ_WBUF + (uint32_t)bsel * 36864;
#pragma unroll
        for (int t = 0; t < 4; t++) {
            int e = tid + t * 512;
            int row = e >> 3, col = e & 7;
            CP_ASYNC16(dstb + ((uint32_t)row * 72 + col * 8) * 2,
                       (const void*)(g_pwh + (size_t)row * 256 + kc + col * 8));
        }
    };

    const uint32_t a_row  = (lane & 7) + ((lane >> 3) & 1) * 8;
    const uint32_t a_koff = (lane >> 4) * 8;
    const uint32_t b_row  = (lane & 7) + (lane >> 4) * 8;
    const uint32_t b_koff = ((lane >> 3) & 1) * 8;
    const uint32_t ps_base = sbase + PJ_PS;

    float d[4][4][4];
#pragma unroll
    for (int mi = 0; mi < 4; mi++)
#pragma unroll
        for (int nf = 0; nf < 4; nf++)
#pragma unroll
            for (int q = 0; q < 4; q++) d[mi][nf][q] = 0.f;

    cpW(0, 0); CP_COMMIT();

    for (int c = 0; c < 4; c++) {
        if (c < 3) {
            cpW((c + 1) * 64, (c + 1) & 1); CP_COMMIT();
            CP_WAIT1();
        } else {
            CP_WAIT0();
        }
        __syncthreads();

        const uint32_t wsb = sbase + PJ_WBUF + (uint32_t)(c & 1) * 36864;
#pragma unroll
        for (int ks = 0; ks < 4; ks++) {
            const int k0 = ks * 16;
            const int kg = c * 64 + k0;
            uint32_t b0[4], b1[4];
            LDM_X4(b0, ps_base + (((uint32_t)(wx * 32)      + b_row) * 264 + kg + b_koff) * 2);
            LDM_X4(b1, ps_base + (((uint32_t)(wx * 32 + 16) + b_row) * 264 + kg + b_koff) * 2);
            uint32_t a[4][4];
#pragma unroll
            for (int mi = 0; mi < 4; mi++)
                LDM_X4(a[mi], wsb + (((uint32_t)(wy * 64 + mi * 16) + a_row) * 72
                                      + k0 + a_koff) * 2);
#pragma unroll
            for (int mi = 0; mi < 4; mi++) {
                MMA16816(d[mi][0], a[mi], b0[0], b0[1]);
                MMA16816(d[mi][1], a[mi], b0[2], b0[3]);
                MMA16816(d[mi][2], a[mi], b1[0], b1[1]);
                MMA16816(d[mi][3], a[mi], b1[2], b1[3]);
            }
        }
        __syncthreads();
    }

    float* stage = (float*)(smem + PJ_STAGE);
#pragma unroll
    for (int h = 0; h < 2; h++) {
        if ((wy >> 1) == h) {
            int r = lane >> 2, c2 = (lane & 3) * 2;
#pragma unroll
            for (int mi = 0; mi < 4; mi++) {
                int row = wy * 64 + mi * 16 + r - 128 * h;
#pragma unroll
                for (int nf = 0; nf < 4; nf++) {
                    int col = wx * 32 + nf * 8 + c2;
                    stage[col * 129 + row]           = d[mi][nf][0];
                    stage[(col + 1) * 129 + row]     = d[mi][nf][1];
                    stage[col * 129 + row + 8]       = d[mi][nf][2];
                    stage[(col + 1) * 129 + row + 8] = d[mi][nf][3];
                }
            }
        }
        __syncthreads();
        for (int e = tid; e < 16384; e += 512) {
            int gl = e & 127, cl = e >> 7;
            int ch = 128 * h + cl;
            size_t idx = ((size_t)b * CDIM + ch) * TJ + p0 + gl;
            x1[idx] = x[idx] + stage[gl * 129 + cl] + pbs[ch];
        }
        __syncthreads();
    }
}

// ---------------------------------------------------------------------------
// K4: fused MLP on HMMA (unchanged from round 6)
// ---------------------------------------------------------------------------
#define SM_SN   0
#define SM_TN   1024
#define SM_S2   2048
#define SM_T2   3072
#define SM_S1   4096
#define SM_T1   4608
#define SM_XS   5120
#define SM_HS   (SM_XS + 33792)
#define SM_WB   (SM_HS + 17408)
#define SM_TOT  (SM_WB + 69632)

#define W1_STRIDE 264
#define H_STRIDE  136

__global__ void __launch_bounds__(512, 1) k_mlp_mma(
    const float* x1,
    const float* __restrict__ b1g, const float* __restrict__ b1b,
    const float* __restrict__ b1m, const float* __restrict__ b1v,
    const float* __restrict__ fb1,
    const float* __restrict__ b2g, const float* __restrict__ b2b,
    const float* __restrict__ b2m, const float* __restrict__ b2v,
    const float* __restrict__ fb2,
    const float* __restrict__ n2g, const float* __restrict__ n2b,
    const float* __restrict__ n2m, const float* __restrict__ n2v,
    float* out)
{
    extern __shared__ char smem[];
    const uint32_t sbase = smem_u32(smem);
    const int tid = threadIdx.x;
    const int wid = tid >> 5;
    const int lane = tid & 31;
    const int wy = wid & 1;
    const int wx = wid >> 1;

    const int blk = blockIdx.x;
    const int b = blk / 34;
    const int p0 = (blk - b * 34) * 64;

    float* sn = (float*)(smem + SM_SN);
    float* tn = (float*)(smem + SM_TN);
    float* s2 = (float*)(smem + SM_S2);
    float* t2 = (float*)(smem + SM_T2);
    float* s1 = (float*)(smem + SM_S1);
    float* t1 = (float*)(smem + SM_T1);

    if (tid < 256) {
        float s = n2g[tid] * rsqrtf(n2v[tid] + 1e-5f);
        sn[tid] = s;
        tn[tid] = n2b[tid] - n2m[tid] * s;
    } else {
        int c = tid - 256;
        float s = b2g[c] * rsqrtf(b2v[c] + 1e-5f);
        s2[c] = s;
        t2[c] = b2b[c] - b2m[c] * s + fb2[c] * s;
    }

    uint4 wv[8];
    auto ldW1 = [&](int nt) {
        const uint4* s = (const uint4*)(g_w1h + nt * 32768);
#pragma unroll
        for (int t = 0; t < 8; t++) wv[t] = s[tid + t * 512];
    };
    auto stW1 = [&]() {
#pragma unroll
        for (int t = 0; t < 8; t++) {
            int e = tid + t * 512;
            int row = (e >> 5) & 127, col = e & 31;
            *(uint4*)(smem + SM_WB + ((uint32_t)row * W1_STRIDE + col * 8) * 2) = wv[t];
        }
    };
    auto ldW2 = [&](int nt) {
        const uint4* s = (const uint4*)(g_w2h + nt * 32768);
#pragma unroll
        for (int t = 0; t < 8; t++) wv[t] = s[tid + t * 512];
    };
    auto stW2 = [&]() {
#pragma unroll
        for (int t = 0; t < 8; t++) {
            int e = tid + t * 512;
            int row = (e >> 4) & 255, col = e & 15;
            *(uint4*)(smem + SM_WB + ((uint32_t)row * H_STRIDE + col * 8) * 2) = wv[t];
        }
    };
    auto ldBN1 = [&](int nt) {
        if (tid < 128) {
            int j = nt * 128 + tid;
            float s = b1g[j] * rsqrtf(b1v[j] + 1e-5f);
            s1[tid] = s;
            t1[tid] = b1b[j] - b1m[j] * s + fb1[j] * s;
        }
    };

    __syncthreads();

    const float* xb = x1 + (size_t)b * CDIM * TJ;
    for (int e = tid; e < 16384; e += 512) {
        int i = e >> 6, p = e & 63;
        float v = xb[(size_t)i * TJ + p0 + p] * sn[i] + tn[i];
        *(__half*)(smem + SM_XS + ((uint32_t)p * W1_STRIDE + i) * 2) = __float2half(v);
    }

    const uint32_t a_row  = (lane & 7) + ((lane >> 3) & 1) * 8;
    const uint32_t a_koff = (lane >> 4) * 8;
    const uint32_t b_row  = (lane & 7) + (lane >> 4) * 8;
    const uint32_t b_koff = ((lane >> 3) & 1) * 8;

    const uint32_t xs_base = sbase + SM_XS;
    const uint32_t hs_base = sbase + SM_HS;
    const uint32_t wb_base = sbase + SM_WB;

    float d2[2][4][4];
#pragma unroll
    for (int i0 = 0; i0 < 2; i0++)
#pragma unroll
        for (int j0 = 0; j0 < 4; j0++)
#pragma unroll
            for (int q = 0; q < 4; q++) d2[i0][j0][q] = 0.f;

    ldW1(0); stW1(); ldBN1(0);
    __syncthreads();

    for (int nt = 0; nt < 8; nt++) {
        ldW2(nt);

        float dH[2][2][4];
#pragma unroll
        for (int i0 = 0; i0 < 2; i0++)
#pragma unroll
            for (int j0 = 0; j0 < 2; j0++)
#pragma unroll
                for (int q = 0; q < 4; q++) dH[i0][j0][q] = 0.f;

#pragma unroll 4
        for (int k0 = 0; k0 < 256; k0 += 16) {
            uint32_t a[2][4];
#pragma unroll
            for (int mi = 0; mi < 2; mi++) {
                uint32_t addr = xs_base
                    + (((uint32_t)(wy * 32 + mi * 16) + a_row) * W1_STRIDE + k0 + a_koff) * 2;
                LDM_X4(a[mi], addr);
            }
            uint32_t bh[4];
            LDM_X4(bh, wb_base + (((uint32_t)(wx * 16) + b_row) * W1_STRIDE + k0 + b_koff) * 2);
#pragma unroll
            for (int mi = 0; mi < 2; mi++) {
                MMA16816(dH[mi][0], a[mi], bh[0], bh[1]);
                MMA16816(dH[mi][1], a[mi], bh[2], bh[3]);
            }
        }

        {
            int r = lane >> 2;
#pragma unroll
            for (int mi = 0; mi < 2; mi++) {
#pragma unroll
                for (int nf = 0; nf < 2; nf++) {
                    int c2 = wx * 16 + nf * 8 + (lane & 3) * 2;
                    float ss0 = s1[c2], tt0 = t1[c2];
                    float ss1 = s1[c2 + 1], tt1 = t1[c2 + 1];
                    int row0 = wy * 32 + mi * 16 + r;
                    float h0 = gelu_exact(dH[mi][nf][0] * ss0 + tt0);
                    float h1 = gelu_exact(dH[mi][nf][1] * ss1 + tt1);
                    float h2 = gelu_exact(dH[mi][nf][2] * ss0 + tt0);
                    float h3 = gelu_exact(dH[mi][nf][3] * ss1 + tt1);
                    *(__half2*)(smem + SM_HS + ((uint32_t)row0 * H_STRIDE + c2) * 2)
                        = __floats2half2_rn(h0, h1);
                    *(__half2*)(smem + SM_HS + ((uint32_t)(row0 + 8) * H_STRIDE + c2) * 2)
                        = __floats2half2_rn(h2, h3);
                }
            }
        }
        __syncthreads();

        stW2();
        if (nt < 7) ldW1(nt + 1);
        __syncthreads();

#pragma unroll
        for (int k0 = 0; k0 < 128; k0 += 16) {
            uint32_t a[2][4];
#pragma unroll
            for (int mi = 0; mi < 2; mi++) {
                uint32_t addr = hs_base
                    + (((uint32_t)(wy * 32 + mi * 16) + a_row) * H_STRIDE + k0 + a_koff) * 2;
                LDM_X4(a[mi], addr);
            }
#pragma unroll
            for (int nq = 0; nq < 2; nq++) {
                uint32_t bh[4];
                LDM_X4(bh, wb_base + (((uint32_t)(wx * 32 + nq * 16) + b_row) * H_STRIDE
                                       + k0 + b_koff) * 2);
#pragma unroll
                for (int mi = 0; mi < 2; mi++) {
                    MMA16816(d2[mi][nq * 2 + 0], a[mi], bh[0], bh[1]);
                    MMA16816(d2[mi][nq * 2 + 1], a[mi], bh[2], bh[3]);
                }
            }
        }
        __syncthreads();

        if (nt < 7) {
            stW1();
            ldBN1(nt + 1);
            __syncthreads();
        }
    }

    float* stage = (float*)(smem + SM_WB);
    {
        int r = lane >> 2;
#pragma unroll
        for (int mi = 0; mi < 2; mi++) {
            int row0 = wy * 32 + mi * 16 + r;
#pragma unroll
            for (int j0 = 0; j0 < 4; j0++) {
                int c = wx * 32 + j0 * 8 + (lane & 3) * 2;
                stage[row0 * 257 + c]       = d2[mi][j0][0];
                stage[row0 * 257 + c + 1]   = d2[mi][j0][1];
                stage[(row0 + 8) * 257 + c]     = d2[mi][j0][2];
                stage[(row0 + 8) * 257 + c + 1] = d2[mi][j0][3];
            }
        }
    }
    __syncthreads();

    for (int e = tid; e < 16384; e += 512) {
        int c = e >> 6, p = e & 63;
        size_t idx = ((size_t)b * CDIM + c) * TJ + p0 + p;
        out[idx] = x1[idx] + stage[p * 257 + c] * s2[c] + t2[c];
    }
}

// ---------------------------------------------------------------------------
extern "C" void kernel_launch(void* const* d_in, const int* in_sizes, int n_in,
                              void* d_out, int out_size)
{
    const float* x    = (const float*)d_in[0];
    const float* n1g  = (const float*)d_in[1];
    const float* n1b  = (const float*)d_in[2];
    const float* n1m  = (const float*)d_in[3];
    const float* n1v  = (const float*)d_in[4];
    const float* qkvw = (const float*)d_in[5];
    const float* qg   = (const float*)d_in[6];
    const float* qb   = (const float*)d_in[7];
    const float* qm   = (const float*)d_in[8];
    const float* qv   = (const float*)d_in[9];
    const float* pw   = (const float*)d_in[10];
    const float* pb   = (const float*)d_in[11];
    const float* n2g  = (const float*)d_in[12];
    const float* n2b  = (const float*)d_in[13];
    const float* n2m  = (const float*)d_in[14];
    const float* n2v  = (const float*)d_in[15];
    const float* w1   = (const float*)d_in[16];
    const float* fb1  = (const float*)d_in[17];
    const float* b1g  = (const float*)d_in[18];
    const float* b1b  = (const float*)d_in[19];
    const float* b1m  = (const float*)d_in[20];
    const float* b1v  = (const float*)d_in[21];
    const float* w2   = (const float*)d_in[22];
    const float* fb2  = (const float*)d_in[23];
    const float* b2g  = (const float*)d_in[24];
    const float* b2b  = (const float*)d_in[25];
    const float* b2m  = (const float*)d_in[26];
    const float* b2v  = (const float*)d_in[27];
    float* out = (float*)d_out;

    cudaFuncSetAttribute(k_attn_mma, cudaFuncAttributeMaxDynamicSharedMemorySize, AT_TOT);
    cudaFuncSetAttribute(k_conv_mma, cudaFuncAttributeMaxDynamicSharedMemorySize, CV_TOT);
    cudaFuncSetAttribute(k_proj_mma, cudaFuncAttributeMaxDynamicSharedMemorySize, PJ_TOT);
    cudaFuncSetAttribute(k_mlp_mma,  cudaFuncAttributeMaxDynamicSharedMemorySize, SM_TOT);

    k_prep<<<9216, 256>>>(w1, w2, qkvw, pw);
    k_prexn<<<16384, 512>>>(x, n1g, n1b, n1m, n1v);
    k_conv_mma<<<dim3(3, 129), 512, CV_TOT>>>(qg, qb, qm, qv);
    k_attn_mma<<<512, 544, AT_TOT>>>();
    k_proj_mma<<<1088, 512, PJ_TOT>>>(pb, x, out);
    k_mlp_mma<<<2176, 512, SM_TOT>>>(out,
                                     b1g, b1b, b1m, b1v, fb1,
                                     b2g, b2b, b2m, b2v, fb2,
                                     n2g, n2b, n2m, n2v, out);
}

// round 9
// speedup vs baseline: 8.7157x; 1.0317x over previous
#include <cuda_runtime.h>
#include <cuda_fp16.h>
#include <math.h>
#include <stdint.h>

#define BATCH 64
#define CDIM 256
#define TDIM 128
#define JDIM 17
#define TJ 2176     // TDIM*JDIM
#define HCC 43
#define WCC 6
#define HW 258      // HCC*WCC
#define HIDDEN 1024

// scratch (static __device__ globals per harness rules)
__device__ float g_qkv[(size_t)3 * BATCH * HW * CDIM];   // [b][t(3)][hw][c]
__device__ float g_att[(size_t)BATCH * HW * CDIM];       // [b][hw][c]
__device__ __half g_xn[(size_t)BATCH * CDIM * TJ];       // n1bn(x) fp16
// fp16 weights
__device__ __half g_w1h[8 * 32768];            // W1 per-tile [128 j][256 i]
__device__ __half g_w2h[8 * 32768];            // W2 per-tile [256 c][128 j]
__device__ __half g_qwh[768 * 2304];           // qkv conv weight row-major
__device__ __half g_pwh[256 * 256];            // proj weight row-major

__device__ __forceinline__ float gelu_exact(float v) {
    return 0.5f * v * (1.0f + erff(v * 0.70710678118654752f));
}

__device__ __forceinline__ uint32_t smem_u32(const void* p) {
    uint32_t a;
    asm("{ .reg .u64 t; cvta.to.shared.u64 t, %1; cvt.u32.u64 %0, t; }" : "=r"(a) : "l"(p));
    return a;
}

__device__ __forceinline__ uint32_t h2_to_u32(__half2 h) {
    return *reinterpret_cast<uint32_t*>(&h);
}

#define LDM_X4(r, addr) \
    asm volatile("ldmatrix.sync.aligned.m8n8.x4.shared.b16 {%0,%1,%2,%3}, [%4];" \
        : "=r"((r)[0]), "=r"((r)[1]), "=r"((r)[2]), "=r"((r)[3]) : "r"(addr))

#define LDM_X4_T(r, addr) \
    asm volatile("ldmatrix.sync.aligned.m8n8.x4.trans.shared.b16 {%0,%1,%2,%3}, [%4];" \
        : "=r"((r)[0]), "=r"((r)[1]), "=r"((r)[2]), "=r"((r)[3]) : "r"(addr))

#define MMA16816(d, a, b0, b1) \
    asm volatile("mma.sync.aligned.m16n8k16.row.col.f32.f16.f16.f32 " \
        "{%0,%1,%2,%3}, {%4,%5,%6,%7}, {%8,%9}, {%0,%1,%2,%3};" \
        : "+f"((d)[0]), "+f"((d)[1]), "+f"((d)[2]), "+f"((d)[3]) \
        : "r"((a)[0]), "r"((a)[1]), "r"((a)[2]), "r"((a)[3]), "r"(b0), "r"(b1))

#define CP_ASYNC16(dst, src) \
    asm volatile("cp.async.cg.shared.global [%0], [%1], 16;" :: "r"(dst), "l"(src))
#define CP_COMMIT() asm volatile("cp.async.commit_group;")
#define CP_WAIT1()  asm volatile("cp.async.wait_group 1;" ::: "memory")
#define CP_WAIT0()  asm volatile("cp.async.wait_group 0;" ::: "memory")

// ---------------------------------------------------------------------------
// K0a: pre-convert all weights fp32 -> fp16
// ---------------------------------------------------------------------------
__global__ void __launch_bounds__(256) k_prep(const float* __restrict__ w1,
                                              const float* __restrict__ w2,
                                              const float* __restrict__ qkvw,
                                              const float* __restrict__ pw)
{
    int idx = blockIdx.x * 256 + threadIdx.x;
    if (idx < 262144) {
        int j = idx >> 8, i = idx & 255;
        int nt = j >> 7, jl = j & 127;
        g_w1h[(uint32_t)nt * 32768 + (uint32_t)jl * 256 + i] = __float2half(w1[idx]);
    } else if (idx < 524288) {
        int t = idx - 262144;
        int c = t >> 10, j = t & 1023;
        int nt = j >> 7, jl = j & 127;
        g_w2h[(uint32_t)nt * 32768 + (uint32_t)c * 128 + jl] = __float2half(w2[t]);
    } else if (idx < 2293760) {
        int t = idx - 524288;
        g_qwh[t] = __float2half(qkvw[t]);
    } else {
        int t = idx - 2293760;
        g_pwh[t] = __float2half(pw[t]);
    }
}

// ---------------------------------------------------------------------------
// K0b: xn = n1bn(x) as fp16
// ---------------------------------------------------------------------------
__global__ void __launch_bounds__(512) k_prexn(
    const float* __restrict__ x,
    const float* __restrict__ n1g, const float* __restrict__ n1b,
    const float* __restrict__ n1m, const float* __restrict__ n1v)
{
    __shared__ float ss, tt;
    const int bc = blockIdx.x;
    const int c = bc & 255;
    if (threadIdx.x == 0) {
        float s = n1g[c] * rsqrtf(n1v[c] + 1e-5f);
        ss = s;
        tt = n1b[c] - n1m[c] * s;
    }
    __syncthreads();
    const float* xr = x + (size_t)bc * TJ;
    __half* xo = g_xn + (size_t)bc * TJ;
    float s = ss, t = tt;
    for (int p = threadIdx.x; p < TJ; p += 512)
        xo[p] = __float2half(xr[p] * s + t);
}

// ---------------------------------------------------------------------------
// K1: conv QKV on HMMA, merged M (unchanged)
// ---------------------------------------------------------------------------
#define CV_KTAB  0
#define CV_GXO   4608
#define CV_GY    5120
#define CV_GX    5376
#define CV_SO    5632
#define CV_TO    6656
#define CV_PBUF  7680
#define CV_WBUF  (CV_PBUF + 36864)
#define CV_STAGE CV_PBUF
#define CV_TOT   (CV_WBUF + 73728)

__global__ void __launch_bounds__(512, 1) k_conv_mma(
    const float* __restrict__ qg, const float* __restrict__ qb,
    const float* __restrict__ qm, const float* __restrict__ qv)
{
    extern __shared__ char smem[];
    const uint32_t sbase = smem_u32(smem);
    const int tid = threadIdx.x;
    const int wid = tid >> 5, lane = tid & 31;
    const int wy = wid & 3, wx = wid >> 2;

    const int m0 = blockIdx.x * 256;
    const int n0 = blockIdx.y * 128;

    uint16_t* ktab = (uint16_t*)(smem + CV_KTAB);
    int*      gxo  = (int*)(smem + CV_GXO);
    int16_t*  gyv  = (int16_t*)(smem + CV_GY);
    int16_t*  gxv  = (int16_t*)(smem + CV_GX);
    float*    s_o  = (float*)(smem + CV_SO);
    float*    t_o  = (float*)(smem + CV_TO);

    if (tid < 256) {
        int o = m0 + tid;
        float s = qg[o] * rsqrtf(qv[o] + 1e-5f);
        s_o[tid] = s;
        t_o[tid] = qb[o] - qm[o] * s;
    } else if (tid < 384) {
        int gl = tid - 256;
        int g = n0 + gl;
        int b = g / HW, hw = g - b * HW;
        int y = hw / WCC, xx = hw - y * WCC;
        gxo[gl] = b * (CDIM * TJ);
        gyv[gl] = (int16_t)(3 * y - 1);
        gxv[gl] = (int16_t)(3 * xx - 1);
    }
    for (int k = tid; k < 2304; k += 512) {
        int i = k / 9, r = k - i * 9;
        int ky = r / 3, kx = r - ky * 3;
        ktab[k] = (uint16_t)((i << 4) | (ky << 2) | kx);
    }
    __syncthreads();

    const uint32_t a_row  = (lane & 7) + ((lane >> 3) & 1) * 8;
    const uint32_t a_koff = (lane >> 4) * 8;
    const uint32_t b_row  = (lane & 7) + (lane >> 4) * 8;
    const uint32_t b_koff = ((lane >> 3) & 1) * 8;

    const int kk_fix = tid & 63;
    const int gl0    = tid >> 6;

    unsigned short pv[16];

    auto cpW = [&](int kc, int bsel) {
        uint32_t dstb = sbase + CV_WBUF + (uint32_t)bsel * 36864;
#pragma unroll
        for (int t = 0; t < 4; t++) {
            int e = tid + t * 512;
            int row = e >> 3, col = e & 7;
            CP_ASYNC16(dstb + ((uint32_t)row * 72 + col * 8) * 2,
                       (const void*)(g_qwh + (size_t)(m0 + row) * 2304 + kc + col * 8));
        }
    };
    auto gatherP = [&](int kc) {
        uint32_t kt = ktab[kc + kk_fix];
        int i = kt >> 4, ky = (kt >> 2) & 3, kx = kt & 3;
#pragma unroll
        for (int t = 0; t < 16; t++) {
            int gl = gl0 + 8 * t;
            int iy = gyv[gl] + ky, ix = gxv[gl] + kx;
            unsigned short v = 0;
            if ((unsigned)iy < (unsigned)TDIM && (unsigned)ix < (unsigned)JDIM)
                v = *(const unsigned short*)&g_xn[gxo[gl] + i * TJ + iy * JDIM + ix];
            pv[t] = v;
        }
    };
    auto storeP = [&](int bsel) {
        char* pb2 = smem + CV_PBUF + bsel * 18432;
#pragma unroll
        for (int t = 0; t < 16; t++) {
            int gl = gl0 + 8 * t;
            *(unsigned short*)(pb2 + ((uint32_t)gl * 72 + kk_fix) * 2) = pv[t];
        }
    };

    float d[4][4][4];
#pragma unroll
    for (int mi = 0; mi < 4; mi++)
#pragma unroll
        for (int nf = 0; nf < 4; nf++)
#pragma unroll
            for (int q = 0; q < 4; q++) d[mi][nf][q] = 0.f;

    cpW(0, 0); CP_COMMIT();
    gatherP(0); storeP(0);

    for (int c = 0; c < 36; c++) {
        if (c < 35) {
            cpW((c + 1) * 64, (c + 1) & 1); CP_COMMIT();
            gatherP((c + 1) * 64);
            CP_WAIT1();
        } else {
            CP_WAIT0();
        }
        __syncthreads();

        const uint32_t wsb = sbase + CV_WBUF + (uint32_t)(c & 1) * 36864;
        const uint32_t psb = sbase + CV_PBUF + (uint32_t)(c & 1) * 18432;
#pragma unroll
        for (int ks = 0; ks < 4; ks++) {
            const int k0 = ks * 16;
            uint32_t b0[4], b1[4];
            LDM_X4(b0, psb + (((uint32_t)(wx * 32)      + b_row) * 72 + k0 + b_koff) * 2);
            LDM_X4(b1, psb + (((uint32_t)(wx * 32 + 16) + b_row) * 72 + k0 + b_koff) * 2);
            uint32_t a[4][4];
#pragma unroll
            for (int mi = 0; mi < 4; mi++)
                LDM_X4(a[mi], wsb + (((uint32_t)(wy * 64 + mi * 16) + a_row) * 72
                                      + k0 + a_koff) * 2);
#pragma unroll
            for (int mi = 0; mi < 4; mi++) {
                MMA16816(d[mi][0], a[mi], b0[0], b0[1]);
                MMA16816(d[mi][1], a[mi], b0[2], b0[3]);
                MMA16816(d[mi][2], a[mi], b1[0], b1[1]);
                MMA16816(d[mi][3], a[mi], b1[2], b1[3]);
            }
        }
        if (c < 35) storeP((c + 1) & 1);
        __syncthreads();
    }

    float* stage = (float*)(smem + CV_STAGE);
    const int tpart = blockIdx.x;
#pragma unroll
    for (int h = 0; h < 2; h++) {
        if ((wy >> 1) == h) {
            int r = lane >> 2, c2 = (lane & 3) * 2;
#pragma unroll
            for (int mi = 0; mi < 4; mi++) {
                int row = wy * 64 + mi * 16 + r - 128 * h;
#pragma unroll
                for (int nf = 0; nf < 4; nf++) {
                    int col = wx * 32 + nf * 8 + c2;
                    stage[col * 129 + row]           = d[mi][nf][0];
                    stage[(col + 1) * 129 + row]     = d[mi][nf][1];
                    stage[col * 129 + row + 8]       = d[mi][nf][2];
                    stage[(col + 1) * 129 + row + 8] = d[mi][nf][3];
                }
            }
        }
        __syncthreads();
        for (int e = tid; e < 16384; e += 512) {
            int gl = e >> 7, cl = e & 127;
            int g = n0 + gl;
            int b = g / HW, hw = g - b * HW;
            int ch = 128 * h + cl;
            float v = stage[gl * 129 + cl] * s_o[ch] + t_o[ch];
            g_qkv[(((size_t)b * 3 + tpart) * HW + hw) * CDIM + ch] = gelu_exact(v);
        }
        __syncthreads();
    }
}

// ---------------------------------------------------------------------------
// K2: attention on HMMA (unchanged from round 8)
// ---------------------------------------------------------------------------
#define AT_STR  40
#define AT_Q    0
#define AT_K    21760
#define AT_V    43520
#define AT_TOT  65280

__global__ void __launch_bounds__(544) k_attn_mma()
{
    extern __shared__ char smem[];
    const uint32_t sbase = smem_u32(smem);
    __half* qs = (__half*)(smem + AT_Q);
    __half* ks = (__half*)(smem + AT_K);
    __half* vs = (__half*)(smem + AT_V);

    const int bh = blockIdx.x;
    const int b = bh >> 3, h = bh & 7;
    const int tid = threadIdx.x;
    const int wid = tid >> 5, lane = tid & 31;

    const float* qg = g_qkv + (((size_t)b * 3 + 0) * HW) * CDIM + h * 32;
    const float* kg = g_qkv + (((size_t)b * 3 + 1) * HW) * CDIM + h * 32;
    const float* vg = g_qkv + (((size_t)b * 3 + 2) * HW) * CDIM + h * 32;

    const float scale = 0.17677669529663687f;
    for (int e = tid; e < 272 * 32; e += 544) {
        int r = e >> 5, d = e & 31;
        float qv_ = 0.f, kv_ = 0.f, vv_ = 0.f;
        if (r < HW) {
            size_t off = (size_t)r * CDIM + d;
            qv_ = qg[off] * scale;
            kv_ = kg[off];
            vv_ = vg[off];
        }
        qs[r * AT_STR + d] = __float2half(qv_);
        ks[r * AT_STR + d] = __float2half(kv_);
        vs[r * AT_STR + d] = __float2half(vv_);
    }
    __syncthreads();

    const int m0 = wid * 16;
    const uint32_t a_row  = (lane & 7) + ((lane >> 3) & 1) * 8;
    const uint32_t a_koff = (lane >> 4) * 8;
    const uint32_t b_row  = (lane & 7) + (lane >> 4) * 8;
    const uint32_t b_koff = ((lane >> 3) & 1) * 8;
    const uint32_t v_row  = (lane & 7) + ((lane >> 3) & 1) * 8;
    const uint32_t v_col  = (lane >> 4) * 8;

    const uint32_t qs_base = sbase + AT_Q;
    const uint32_t ks_base = sbase + AT_K;
    const uint32_t vs_base = sbase + AT_V;

    uint32_t qa[2][4];
    LDM_X4(qa[0], qs_base + (((uint32_t)m0 + a_row) * AT_STR + 0  + a_koff) * 2);
    LDM_X4(qa[1], qs_base + (((uint32_t)m0 + a_row) * AT_STR + 16 + a_koff) * 2);

    float o[4][4];
#pragma unroll
    for (int nt = 0; nt < 4; nt++)
#pragma unroll
        for (int q = 0; q < 4; q++) o[nt][q] = 0.f;
    float mr = -1e30f, mr8 = -1e30f, lr = 0.f, lr8 = 0.f;

    const int c2 = (lane & 3) * 2;

    for (int jt = 0; jt < 17; jt++) {
        float s0[4] = {0.f, 0.f, 0.f, 0.f};
        float s1[4] = {0.f, 0.f, 0.f, 0.f};
        {
            uint32_t bb[4];
            LDM_X4(bb, ks_base + (((uint32_t)(jt * 16) + b_row) * AT_STR + 0 + b_koff) * 2);
            MMA16816(s0, qa[0], bb[0], bb[1]);
            MMA16816(s1, qa[0], bb[2], bb[3]);
            LDM_X4(bb, ks_base + (((uint32_t)(jt * 16) + b_row) * AT_STR + 16 + b_koff) * 2);
            MMA16816(s0, qa[1], bb[0], bb[1]);
            MMA16816(s1, qa[1], bb[2], bb[3]);
        }
        if (jt == 16) {
            if (256 + c2     >= HW) { s0[0] = -1e30f; s0[2] = -1e30f; }
            if (256 + c2 + 1 >= HW) { s0[1] = -1e30f; s0[3] = -1e30f; }
            if (256 + c2 + 8 >= HW) { s1[0] = -1e30f; s1[2] = -1e30f; }
            if (256 + c2 + 9 >= HW) { s1[1] = -1e30f; s1[3] = -1e30f; }
        }

        float cmr  = fmaxf(fmaxf(s0[0], s0[1]), fmaxf(s1[0], s1[1]));
        float cmr8 = fmaxf(fmaxf(s0[2], s0[3]), fmaxf(s1[2], s1[3]));
        cmr  = fmaxf(cmr,  __shfl_xor_sync(0xffffffffu, cmr, 1));
        cmr  = fmaxf(cmr,  __shfl_xor_sync(0xffffffffu, cmr, 2));
        cmr8 = fmaxf(cmr8, __shfl_xor_sync(0xffffffffu, cmr8, 1));
        cmr8 = fmaxf(cmr8, __shfl_xor_sync(0xffffffffu, cmr8, 2));
        float mnr  = fmaxf(mr, cmr);
        float mnr8 = fmaxf(mr8, cmr8);
        float corr  = __expf(mr - mnr);
        float corr8 = __expf(mr8 - mnr8);
        float p00 = __expf(s0[0] - mnr),  p01 = __expf(s0[1] - mnr);
        float p02 = __expf(s1[0] - mnr),  p03 = __expf(s1[1] - mnr);
        float p80 = __expf(s0[2] - mnr8), p81 = __expf(s0[3] - mnr8);
        float p82 = __expf(s1[2] - mnr8), p83 = __expf(s1[3] - mnr8);
        float ps  = p00 + p01 + p02 + p03;
        float ps8 = p80 + p81 + p82 + p83;
        ps  += __shfl_xor_sync(0xffffffffu, ps, 1);
        ps  += __shfl_xor_sync(0xffffffffu, ps, 2);
        ps8 += __shfl_xor_sync(0xffffffffu, ps8, 1);
        ps8 += __shfl_xor_sync(0xffffffffu, ps8, 2);
        lr  = lr  * corr  + ps;
        lr8 = lr8 * corr8 + ps8;
        mr = mnr; mr8 = mnr8;

        uint32_t pa[4];
        pa[0] = h2_to_u32(__floats2half2_rn(p00, p01));
        pa[1] = h2_to_u32(__floats2half2_rn(p80, p81));
        pa[2] = h2_to_u32(__floats2half2_rn(p02, p03));
        pa[3] = h2_to_u32(__floats2half2_rn(p82, p83));

#pragma unroll
        for (int nt = 0; nt < 4; nt++) {
            o[nt][0] *= corr;  o[nt][1] *= corr;
            o[nt][2] *= corr8; o[nt][3] *= corr8;
        }

        {
            uint32_t vb[4];
            LDM_X4_T(vb, vs_base + (((uint32_t)(jt * 16) + v_row) * AT_STR + 0 + v_col) * 2);
            MMA16816(o[0], pa, vb[0], vb[1]);
            MMA16816(o[1], pa, vb[2], vb[3]);
            LDM_X4_T(vb, vs_base + (((uint32_t)(jt * 16) + v_row) * AT_STR + 16 + v_col) * 2);
            MMA16816(o[2], pa, vb[0], vb[1]);
            MMA16816(o[3], pa, vb[2], vb[3]);
        }
    }

    const int r0 = m0 + (lane >> 2);
    float invr  = 1.f / lr;
    float invr8 = 1.f / lr8;
    if (r0 < HW) {
        float* og = g_att + ((size_t)b * HW + r0) * CDIM + h * 32 + c2;
#pragma unroll
        for (int nt = 0; nt < 4; nt++) {
            og[nt * 8 + 0] = o[nt][0] * invr;
            og[nt * 8 + 1] = o[nt][1] * invr;
        }
    }
    if (r0 + 8 < HW) {
        float* og = g_att + ((size_t)b * HW + r0 + 8) * CDIM + h * 32 + c2;
#pragma unroll
        for (int nt = 0; nt < 4; nt++) {
            og[nt * 8 + 0] = o[nt][2] * invr8;
            og[nt * 8 + 1] = o[nt][3] * invr8;
        }
    }
}

// ---------------------------------------------------------------------------
// K3: proj on HMMA, merged M (first cp.async now issued before gather)
// ---------------------------------------------------------------------------
#define PJ_PB    0
#define PJ_O00   1024
#define PJ_O01   1536
#define PJ_O10   2048
#define PJ_O11   2560
#define PJ_WXT   3072
#define PJ_WYT   3584
#define PJ_PS    4096
#define PJ_WBUF  71680
#define PJ_STAGE PJ_PS
#define PJ_TOT   145408

__global__ void __launch_bounds__(512, 1) k_proj_mma(
    const float* __restrict__ pb,
    const float* __restrict__ x, float* __restrict__ x1)
{
    extern __shared__ char smem[];
    const uint32_t sbase = smem_u32(smem);
    const int tid = threadIdx.x;
    const int wid = tid >> 5, lane = tid & 31;
    const int wy = wid & 3, wx = wid >> 2;

    const int b  = blockIdx.x / 17;
    const int p0 = (blockIdx.x - b * 17) * 128;

    float* pbs = (float*)(smem + PJ_PB);
    int*   o00 = (int*)(smem + PJ_O00);
    int*   o01 = (int*)(smem + PJ_O01);
    int*   o10 = (int*)(smem + PJ_O10);
    int*   o11 = (int*)(smem + PJ_O11);
    float* wxs = (float*)(smem + PJ_WXT);
    float* wys = (float*)(smem + PJ_WYT);

    auto cpW = [&](int kc, int bsel) {
        uint32_t dstb = sbase + PJ_WBUF + (uint32_t)bsel * 36864;
#pragma unroll
        for (int t = 0; t < 4; t++) {
            int e = tid + t * 512;
            int row = e >> 3, col = e & 7;
            CP_ASYNC16(dstb + ((uint32_t)row * 72 + col * 8) * 2,
                       (const void*)(g_pwh + (size_t)row * 256 + kc + col * 8));
        }
    };

    cpW(0, 0); CP_COMMIT();   // overlap with gather below

    if (tid < 128) {
        int p = p0 + tid;
        int t = p / JDIM, j = p - t * JDIM;
        float sy = (t + 0.5f) * (43.0f / 128.0f) - 0.5f;
        sy = fminf(fmaxf(sy, 0.f), 42.f);
        int y0 = (int)sy;
        int y1 = min(y0 + 1, 42);
        float fy = sy - y0;
        float sx = (j + 0.5f) * (6.0f / 17.0f) - 0.5f;
        sx = fminf(fmaxf(sx, 0.f), 5.f);
        int x0 = (int)sx;
        int x1i = min(x0 + 1, 5);
        float fx = sx - x0;
        o00[tid] = (y0 * WCC + x0) * CDIM;
        o01[tid] = (y0 * WCC + x1i) * CDIM;
        o10[tid] = (y1 * WCC + x0) * CDIM;
        o11[tid] = (y1 * WCC + x1i) * CDIM;
        wxs[tid] = fx;
        wys[tid] = fy;
    } else if (tid < 384) {
        pbs[tid - 128] = pb[tid - 128];
    }
    __syncthreads();

    const float* abase = g_att + (size_t)b * HW * CDIM;
    for (int e = tid; e < 32768; e += 512) {
        int k = e & 255, gl = e >> 8;
        const float* bp = abase + k;
        float fx = wxs[gl], fy = wys[gl];
        float a00 = bp[o00[gl]];
        float a01 = bp[o01[gl]];
        float a10 = bp[o10[gl]];
        float a11 = bp[o11[gl]];
        float v = (a00 * (1.f - fx) + a01 * fx) * (1.f - fy)
                + (a10 * (1.f - fx) + a11 * fx) * fy;
        *(__half*)(smem + PJ_PS + ((uint32_t)gl * 264 + k) * 2) = __float2half(v);
    }

    const uint32_t a_row  = (lane & 7) + ((lane >> 3) & 1) * 8;
    const uint32_t a_koff = (lane >> 4) * 8;
    const uint32_t b_row  = (lane & 7) + (lane >> 4) * 8;
    const uint32_t b_koff = ((lane >> 3) & 1) * 8;
    const uint32_t ps_base = sbase + PJ_PS;

    float d[4][4][4];
#pragma unroll
    for (int mi = 0; mi < 4; mi++)
#pragma unroll
        for (int nf = 0; nf < 4; nf++)
#pragma unroll
            for (int q = 0; q < 4; q++) d[mi][nf][q] = 0.f;

    for (int c = 0; c < 4; c++) {
        if (c < 3) {
            cpW((c + 1) * 64, (c + 1) & 1); CP_COMMIT();
            CP_WAIT1();
        } else {
            CP_WAIT0();
        }
        __syncthreads();

        const uint32_t wsb = sbase + PJ_WBUF + (uint32_t)(c & 1) * 36864;
#pragma unroll
        for (int ks = 0; ks < 4; ks++) {
            const int k0 = ks * 16;
            const int kg = c * 64 + k0;
            uint32_t b0[4], b1[4];
            LDM_X4(b0, ps_base + (((uint32_t)(wx * 32)      + b_row) * 264 + kg + b_koff) * 2);
            LDM_X4(b1, ps_base + (((uint32_t)(wx * 32 + 16) + b_row) * 264 + kg + b_koff) * 2);
            uint32_t a[4][4];
#pragma unroll
            for (int mi = 0; mi < 4; mi++)
                LDM_X4(a[mi], wsb + (((uint32_t)(wy * 64 + mi * 16) + a_row) * 72
                                      + k0 + a_koff) * 2);
#pragma unroll
            for (int mi = 0; mi < 4; mi++) {
                MMA16816(d[mi][0], a[mi], b0[0], b0[1]);
                MMA16816(d[mi][1], a[mi], b0[2], b0[3]);
                MMA16816(d[mi][2], a[mi], b1[0], b1[1]);
                MMA16816(d[mi][3], a[mi], b1[2], b1[3]);
            }
        }
        __syncthreads();
    }

    float* stage = (float*)(smem + PJ_STAGE);
#pragma unroll
    for (int h = 0; h < 2; h++) {
        if ((wy >> 1) == h) {
            int r = lane >> 2, c2 = (lane & 3) * 2;
#pragma unroll
            for (int mi = 0; mi < 4; mi++) {
                int row = wy * 64 + mi * 16 + r - 128 * h;
#pragma unroll
                for (int nf = 0; nf < 4; nf++) {
                    int col = wx * 32 + nf * 8 + c2;
                    stage[col * 129 + row]           = d[mi][nf][0];
                    stage[(col + 1) * 129 + row]     = d[mi][nf][1];
                    stage[col * 129 + row + 8]       = d[mi][nf][2];
                    stage[(col + 1) * 129 + row + 8] = d[mi][nf][3];
                }
            }
        }
        __syncthreads();
        for (int e = tid; e < 16384; e += 512) {
            int gl = e & 127, cl = e >> 7;
            int ch = 128 * h + cl;
            size_t idx = ((size_t)b * CDIM + ch) * TJ + p0 + gl;
            x1[idx] = x[idx] + stage[gl * 129 + cl] + pbs[ch];
        }
        __syncthreads();
    }
}

// ---------------------------------------------------------------------------
// K4: fused MLP on HMMA, big-tile (proj-style): one CTA = 128 positions.
// Per hidden tile (128 j, 8 tiles): GEMM1 [128j x 128pos x K256],
// epilogue gelu->Hs, GEMM2 [256c x 128pos x K128] accumulated in regs.
// Continuous cp.async double-buffer pipeline across all W1/W2 chunks.
// ---------------------------------------------------------------------------
#define M2_SN   0
#define M2_TN   1024
#define M2_S2   2048
#define M2_T2   3072
#define M2_S1   4096
#define M2_T1   4608
#define M2_XS   5120                     // [128 pos][264] half = 67584
#define M2_HS   72704                    // [128 pos][136] half = 34816
#define M2_WB   107520                   // 2 x 36864 = 73728
#define M2_ST   M2_XS                    // stage floats 66048 (reuse Xn)
#define M2_TOT  181248

__global__ void __launch_bounds__(512, 1) k_mlp_mma2(
    const float* x1,
    const float* __restrict__ b1g, const float* __restrict__ b1b,
    const float* __restrict__ b1m, const float* __restrict__ b1v,
    const float* __restrict__ fb1,
    const float* __restrict__ b2g, const float* __restrict__ b2b,
    const float* __restrict__ b2m, const float* __restrict__ b2v,
    const float* __restrict__ fb2,
    const float* __restrict__ n2g, const float* __restrict__ n2b,
    const float* __restrict__ n2m, const float* __restrict__ n2v,
    float* out)
{
    extern __shared__ char smem[];
    const uint32_t sbase = smem_u32(smem);
    const int tid = threadIdx.x;
    const int wid = tid >> 5, lane = tid & 31;
    const int wy = wid & 3, wx = wid >> 2;

    const int b  = blockIdx.x / 17;
    const int p0 = (blockIdx.x - b * 17) * 128;

    float* sn = (float*)(smem + M2_SN);
    float* tn = (float*)(smem + M2_TN);
    float* s2 = (float*)(smem + M2_S2);
    float* t2 = (float*)(smem + M2_T2);
    float* s1 = (float*)(smem + M2_S1);
    float* t1 = (float*)(smem + M2_T1);

    auto cpW1 = [&](int nt, int c, int bsel) {
        uint32_t dstb = sbase + M2_WB + (uint32_t)bsel * 36864;
        const __half* src = g_w1h + nt * 32768 + c * 64;
#pragma unroll
        for (int t = 0; t < 2; t++) {
            int e = tid + t * 512;
            int row = e >> 3, col = e & 7;
            CP_ASYNC16(dstb + ((uint32_t)row * 72 + col * 8) * 2,
                       (const void*)(src + (size_t)row * 256 + col * 8));
        }
    };
    auto cpW2 = [&](int nt, int c, int bsel) {
        uint32_t dstb = sbase + M2_WB + (uint32_t)bsel * 36864;
        const __half* src = g_w2h + nt * 32768 + c * 64;
#pragma unroll
        for (int t = 0; t < 4; t++) {
            int e = tid + t * 512;
            int row = e >> 3, col = e & 7;
            CP_ASYNC16(dstb + ((uint32_t)row * 72 + col * 8) * 2,
                       (const void*)(src + (size_t)row * 128 + col * 8));
        }
    };

    cpW1(0, 0, 0); CP_COMMIT();   // overlap with const + Xn fill

    if (tid < 256) {
        float s = n2g[tid] * rsqrtf(n2v[tid] + 1e-5f);
        sn[tid] = s;
        tn[tid] = n2b[tid] - n2m[tid] * s;
    } else {
        int c = tid - 256;
        float s = b2g[c] * rsqrtf(b2v[c] + 1e-5f);
        s2[c] = s;
        t2[c] = b2b[c] - b2m[c] * s + fb2[c] * s;
    }
    __syncthreads();

    // fill Xn: [pos 128][i 256] fp16 stride 264
    const float* xb = x1 + (size_t)b * CDIM * TJ;
    for (int e = tid; e < 32768; e += 512) {
        int i = e & 255, p = e >> 8;
        float v = xb[(size_t)i * TJ + p0 + p] * sn[i] + tn[i];
        *(__half*)(smem + M2_XS + ((uint32_t)p * 264 + i) * 2) = __float2half(v);
    }

    const uint32_t a_row  = (lane & 7) + ((lane >> 3) & 1) * 8;
    const uint32_t a_koff = (lane >> 4) * 8;
    const uint32_t b_row  = (lane & 7) + (lane >> 4) * 8;
    const uint32_t b_koff = ((lane >> 3) & 1) * 8;

    const uint32_t xs_base = sbase + M2_XS;
    const uint32_t hs_base = sbase + M2_HS;

    float d2[4][4][4];
#pragma unroll
    for (int mi = 0; mi < 4; mi++)
#pragma unroll
        for (int nf = 0; nf < 4; nf++)
#pragma unroll
            for (int q = 0; q < 4; q++) d2[mi][nf][q] = 0.f;

    int buf = 0;

    for (int nt = 0; nt < 8; nt++) {
        if (tid < 128) {
            int j = nt * 128 + tid;
            float s = b1g[j] * rsqrtf(b1v[j] + 1e-5f);
            s1[tid] = s;
            t1[tid] = b1b[j] - b1m[j] * s + fb1[j] * s;
        }

        float d1[2][4][4];
#pragma unroll
        for (int mi = 0; mi < 2; mi++)
#pragma unroll
            for (int nf = 0; nf < 4; nf++)
#pragma unroll
                for (int q = 0; q < 4; q++) d1[mi][nf][q] = 0.f;

        // ---- GEMM1: 4 K-chunks of 64 i ----
        for (int c = 0; c < 4; c++) {
            if (c < 3) cpW1(nt, c + 1, buf ^ 1);
            else       cpW2(nt, 0, buf ^ 1);
            CP_COMMIT(); CP_WAIT1();
            __syncthreads();

            const uint32_t wsb = sbase + M2_WB + (uint32_t)buf * 36864;
#pragma unroll
            for (int ks = 0; ks < 4; ks++) {
                const int k0 = ks * 16;
                const int kg = c * 64 + k0;
                uint32_t b0[4], b1[4];
                LDM_X4(b0, xs_base + (((uint32_t)(wx * 32)      + b_row) * 264 + kg + b_koff) * 2);
                LDM_X4(b1, xs_base + (((uint32_t)(wx * 32 + 16) + b_row) * 264 + kg + b_koff) * 2);
                uint32_t a[2][4];
#pragma unroll
                for (int mi = 0; mi < 2; mi++)
                    LDM_X4(a[mi], wsb + (((uint32_t)(wy * 32 + mi * 16) + a_row) * 72
                                          + k0 + a_koff) * 2);
#pragma unroll
                for (int mi = 0; mi < 2; mi++) {
                    MMA16816(d1[mi][0], a[mi], b0[0], b0[1]);
                    MMA16816(d1[mi][1], a[mi], b0[2], b0[3]);
                    MMA16816(d1[mi][2], a[mi], b1[0], b1[1]);
                    MMA16816(d1[mi][3], a[mi], b1[2], b1[3]);
                }
            }
            buf ^= 1;
            __syncthreads();
        }

        // ---- epilogue1: gelu(bn1(d1)) -> Hs[pos][j] fp16 ----
        {
            int r = lane >> 2, c2l = (lane & 3) * 2;
#pragma unroll
            for (int mi = 0; mi < 2; mi++) {
                int j = wy * 32 + mi * 16 + r;
                float sj0 = s1[j],     tj0 = t1[j];
                float sj8 = s1[j + 8], tj8 = t1[j + 8];
#pragma unroll
                for (int nf = 0; nf < 4; nf++) {
                    int pos = wx * 32 + nf * 8 + c2l;
                    __half* h0 = (__half*)(smem + M2_HS + ((uint32_t)pos * 136 + j) * 2);
                    __half* h1 = (__half*)(smem + M2_HS + ((uint32_t)(pos + 1) * 136 + j) * 2);
                    h0[0] = __float2half(gelu_exact(d1[mi][nf][0] * sj0 + tj0));
                    h1[0] = __float2half(gelu_exact(d1[mi][nf][1] * sj0 + tj0));
                    h0[8] = __float2half(gelu_exact(d1[mi][nf][2] * sj8 + tj8));
                    h1[8] = __float2half(gelu_exact(d1[mi][nf][3] * sj8 + tj8));
                }
            }
        }

        // ---- GEMM2: 2 K-chunks of 64 j ----
        for (int c = 0; c < 2; c++) {
            if (c == 0)        { cpW2(nt, 1, buf ^ 1); CP_COMMIT(); CP_WAIT1(); }
            else if (nt < 7)   { cpW1(nt + 1, 0, buf ^ 1); CP_COMMIT(); CP_WAIT1(); }
            else               { CP_WAIT0(); }
            __syncthreads();

            const uint32_t wsb = sbase + M2_WB + (uint32_t)buf * 36864;
#pragma unroll
            for (int ks = 0; ks < 4; ks++) {
                const int k0 = ks * 16;
                const int kg = c * 64 + k0;
                uint32_t b0[4], b1[4];
                LDM_X4(b0, hs_base + (((uint32_t)(wx * 32)      + b_row) * 136 + kg + b_koff) * 2);
                LDM_X4(b1, hs_base + (((uint32_t)(wx * 32 + 16) + b_row) * 136 + kg + b_koff) * 2);
                uint32_t a[4][4];
#pragma unroll
                for (int mi = 0; mi < 4; mi++)
                    LDM_X4(a[mi], wsb + (((uint32_t)(wy * 64 + mi * 16) + a_row) * 72
                                          + k0 + a_koff) * 2);
#pragma unroll
                for (int mi = 0; mi < 4; mi++) {
                    MMA16816(d2[mi][0], a[mi], b0[0], b0[1]);
                    MMA16816(d2[mi][1], a[mi], b0[2], b0[3]);
                    MMA16816(d2[mi][2], a[mi], b1[0], b1[1]);
                    MMA16816(d2[mi][3], a[mi], b1[2], b1[3]);
                }
            }
            buf ^= 1;
            __syncthreads();
        }
    }

    // ---- final epilogue: out = x1 + bn2(fc2) (two channel-halves) ----
    float* stage = (float*)(smem + M2_ST);
#pragma unroll
    for (int h = 0; h < 2; h++) {
        if ((wy >> 1) == h) {
            int r = lane >> 2, c2l = (lane & 3) * 2;
#pragma unroll
            for (int mi = 0; mi < 4; mi++) {
                int row = wy * 64 + mi * 16 + r - 128 * h;
#pragma unroll
                for (int nf = 0; nf < 4; nf++) {
                    int col = wx * 32 + nf * 8 + c2l;
                    stage[col * 129 + row]           = d2[mi][nf][0];
                    stage[(col + 1) * 129 + row]     = d2[mi][nf][1];
                    stage[col * 129 + row + 8]       = d2[mi][nf][2];
                    stage[(col + 1) * 129 + row + 8] = d2[mi][nf][3];
                }
            }
        }
        __syncthreads();
        for (int e = tid; e < 16384; e += 512) {
            int gl = e & 127, cl = e >> 7;
            int ch = 128 * h + cl;
            size_t idx = ((size_t)b * CDIM + ch) * TJ + p0 + gl;
            out[idx] = x1[idx] + stage[gl * 129 + cl] * s2[ch] + t2[ch];
        }
        __syncthreads();
    }
}

// ---------------------------------------------------------------------------
extern "C" void kernel_launch(void* const* d_in, const int* in_sizes, int n_in,
                              void* d_out, int out_size)
{
    const float* x    = (const float*)d_in[0];
    const float* n1g  = (const float*)d_in[1];
    const float* n1b  = (const float*)d_in[2];
    const float* n1m  = (const float*)d_in[3];
    const float* n1v  = (const float*)d_in[4];
    const float* qkvw = (const float*)d_in[5];
    const float* qg   = (const float*)d_in[6];
    const float* qb   = (const float*)d_in[7];
    const float* qm   = (const float*)d_in[8];
    const float* qv   = (const float*)d_in[9];
    const float* pw   = (const float*)d_in[10];
    const float* pb   = (const float*)d_in[11];
    const float* n2g  = (const float*)d_in[12];
    const float* n2b  = (const float*)d_in[13];
    const float* n2m  = (const float*)d_in[14];
    const float* n2v  = (const float*)d_in[15];
    const float* w1   = (const float*)d_in[16];
    const float* fb1  = (const float*)d_in[17];
    const float* b1g  = (const float*)d_in[18];
    const float* b1b  = (const float*)d_in[19];
    const float* b1m  = (const float*)d_in[20];
    const float* b1v  = (const float*)d_in[21];
    const float* w2   = (const float*)d_in[22];
    const float* fb2  = (const float*)d_in[23];
    const float* b2g  = (const float*)d_in[24];
    const float* b2b  = (const float*)d_in[25];
    const float* b2m  = (const float*)d_in[26];
    const float* b2v  = (const float*)d_in[27];
    float* out = (float*)d_out;

    cudaFuncSetAttribute(k_attn_mma, cudaFuncAttributeMaxDynamicSharedMemorySize, AT_TOT);
    cudaFuncSetAttribute(k_conv_mma, cudaFuncAttributeMaxDynamicSharedMemorySize, CV_TOT);
    cudaFuncSetAttribute(k_proj_mma, cudaFuncAttributeMaxDynamicSharedMemorySize, PJ_TOT);
    cudaFuncSetAttribute(k_mlp_mma2, cudaFuncAttributeMaxDynamicSharedMemorySize, M2_TOT);

    k_prep<<<9216, 256>>>(w1, w2, qkvw, pw);
    k_prexn<<<16384, 512>>>(x, n1g, n1b, n1m, n1v);
    k_conv_mma<<<dim3(3, 129), 512, CV_TOT>>>(qg, qb, qm, qv);
    k_attn_mma<<<512, 544, AT_TOT>>>();
    k_proj_mma<<<1088, 512, PJ_TOT>>>(pb, x, out);
    k_mlp_mma2<<<1088, 512, M2_TOT>>>(out,
                                      b1g, b1b, b1m, b1v, fb1,
                                      b2g, b2b, b2m, b2v, fb2,
                                      n2g, n2b, n2m, n2v, out);
}

// round 10
// speedup vs baseline: 8.7552x; 1.0045x over previous
#include <cuda_runtime.h>
#include <cuda_fp16.h>
#include <math.h>
#include <stdint.h>

#define BATCH 64
#define CDIM 256
#define TDIM 128
#define JDIM 17
#define TJ 2176     // TDIM*JDIM
#define HCC 43
#define WCC 6
#define HW 258      // HCC*WCC
#define HIDDEN 1024

// scratch (static __device__ globals per harness rules)
__device__ float g_qkv[(size_t)3 * BATCH * HW * CDIM];   // [b][t(3)][hw][c]
__device__ float g_att[(size_t)BATCH * HW * CDIM];       // [b][hw][c]
__device__ __half g_xn[(size_t)BATCH * CDIM * TJ];       // n1bn(x) fp16
// fp16 weights
__device__ __half g_w1h[8 * 32768];            // W1 per-tile [128 j][256 i]
__device__ __half g_w2h[8 * 32768];            // W2 per-tile [256 c][128 j]
__device__ __half g_qwh[768 * 2304];           // qkv conv weight row-major
__device__ __half g_pwh[256 * 256];            // proj weight row-major

__device__ __forceinline__ float gelu_exact(float v) {
    return 0.5f * v * (1.0f + erff(v * 0.70710678118654752f));
}

__device__ __forceinline__ uint32_t smem_u32(const void* p) {
    uint32_t a;
    asm("{ .reg .u64 t; cvta.to.shared.u64 t, %1; cvt.u32.u64 %0, t; }" : "=r"(a) : "l"(p));
    return a;
}

__device__ __forceinline__ uint32_t h2_to_u32(__half2 h) {
    return *reinterpret_cast<uint32_t*>(&h);
}

#define LDM_X4(r, addr) \
    asm volatile("ldmatrix.sync.aligned.m8n8.x4.shared.b16 {%0,%1,%2,%3}, [%4];" \
        : "=r"((r)[0]), "=r"((r)[1]), "=r"((r)[2]), "=r"((r)[3]) : "r"(addr))

#define LDM_X4_T(r, addr) \
    asm volatile("ldmatrix.sync.aligned.m8n8.x4.trans.shared.b16 {%0,%1,%2,%3}, [%4];" \
        : "=r"((r)[0]), "=r"((r)[1]), "=r"((r)[2]), "=r"((r)[3]) : "r"(addr))

#define MMA16816(d, a, b0, b1) \
    asm volatile("mma.sync.aligned.m16n8k16.row.col.f32.f16.f16.f32 " \
        "{%0,%1,%2,%3}, {%4,%5,%6,%7}, {%8,%9}, {%0,%1,%2,%3};" \
        : "+f"((d)[0]), "+f"((d)[1]), "+f"((d)[2]), "+f"((d)[3]) \
        : "r"((a)[0]), "r"((a)[1]), "r"((a)[2]), "r"((a)[3]), "r"(b0), "r"(b1))

#define CP_ASYNC16(dst, src) \
    asm volatile("cp.async.cg.shared.global [%0], [%1], 16;" :: "r"(dst), "l"(src))
#define CP_COMMIT() asm volatile("cp.async.commit_group;")
#define CP_WAIT1()  asm volatile("cp.async.wait_group 1;" ::: "memory")
#define CP_WAIT0()  asm volatile("cp.async.wait_group 0;" ::: "memory")

// ---------------------------------------------------------------------------
// K0a: pre-convert all weights fp32 -> fp16
// ---------------------------------------------------------------------------
__global__ void __launch_bounds__(256) k_prep(const float* __restrict__ w1,
                                              const float* __restrict__ w2,
                                              const float* __restrict__ qkvw,
                                              const float* __restrict__ pw)
{
    int idx = blockIdx.x * 256 + threadIdx.x;
    if (idx < 262144) {
        int j = idx >> 8, i = idx & 255;
        int nt = j >> 7, jl = j & 127;
        g_w1h[(uint32_t)nt * 32768 + (uint32_t)jl * 256 + i] = __float2half(w1[idx]);
    } else if (idx < 524288) {
        int t = idx - 262144;
        int c = t >> 10, j = t & 1023;
        int nt = j >> 7, jl = j & 127;
        g_w2h[(uint32_t)nt * 32768 + (uint32_t)c * 128 + jl] = __float2half(w2[t]);
    } else if (idx < 2293760) {
        int t = idx - 524288;
        g_qwh[t] = __float2half(qkvw[t]);
    } else {
        int t = idx - 2293760;
        g_pwh[t] = __float2half(pw[t]);
    }
}

// ---------------------------------------------------------------------------
// K0b: xn = n1bn(x) as fp16
// ---------------------------------------------------------------------------
__global__ void __launch_bounds__(512) k_prexn(
    const float* __restrict__ x,
    const float* __restrict__ n1g, const float* __restrict__ n1b,
    const float* __restrict__ n1m, const float* __restrict__ n1v)
{
    __shared__ float ss, tt;
    const int bc = blockIdx.x;
    const int c = bc & 255;
    if (threadIdx.x == 0) {
        float s = n1g[c] * rsqrtf(n1v[c] + 1e-5f);
        ss = s;
        tt = n1b[c] - n1m[c] * s;
    }
    __syncthreads();
    const float* xr = x + (size_t)bc * TJ;
    __half* xo = g_xn + (size_t)bc * TJ;
    float s = ss, t = tt;
    for (int p = threadIdx.x; p < TJ; p += 512)
        xo[p] = __float2half(xr[p] * s + t);
}

// ---------------------------------------------------------------------------
// K1: conv QKV on HMMA, merged M. Position-major im2col gather:
// lane = position (coalesced same-k loads), 16 consecutive k per thread,
// vectorized uint4 stores into the P buffer.
// ---------------------------------------------------------------------------
#define CV_KTAB  0
#define CV_SO    4608
#define CV_TO    5632
#define CV_PBUF  6656                   // 2 x 18432 = 36864
#define CV_WBUF  (CV_PBUF + 36864)      // 2 x 36864 = 73728
#define CV_STAGE CV_PBUF                // float[128*129] = 66048 (reuse)
#define CV_TOT   (CV_WBUF + 73728)      // 117248

__global__ void __launch_bounds__(512, 1) k_conv_mma(
    const float* __restrict__ qg, const float* __restrict__ qb,
    const float* __restrict__ qm, const float* __restrict__ qv)
{
    extern __shared__ char smem[];
    const uint32_t sbase = smem_u32(smem);
    const int tid = threadIdx.x;
    const int wid = tid >> 5, lane = tid & 31;
    const int wy = wid & 3, wx = wid >> 2;

    const int m0 = blockIdx.x * 256;
    const int n0 = blockIdx.y * 128;

    uint16_t* ktab = (uint16_t*)(smem + CV_KTAB);
    float*    s_o  = (float*)(smem + CV_SO);
    float*    t_o  = (float*)(smem + CV_TO);

    if (tid < 256) {
        int o = m0 + tid;
        float s = qg[o] * rsqrtf(qv[o] + 1e-5f);
        s_o[tid] = s;
        t_o[tid] = qb[o] - qm[o] * s;
    }
    for (int k = tid; k < 2304; k += 512) {
        int i = k / 9, r = k - i * 9;
        int ky = r / 3, kx = r - ky * 3;
        ktab[k] = (uint16_t)((i << 4) | (ky << 2) | kx);
    }
    __syncthreads();

    // per-thread position descriptor (gl fixed per thread)
    const int gl    = tid & 127;
    const int kslot = tid >> 7;            // 0..3, owns k = kc + kslot*16 + t
    int p_xo, p_iy, p_ix;
    {
        int g = n0 + gl;
        int b = g / HW, hw = g - b * HW;
        int y = hw / WCC, xx = hw - y * WCC;
        p_xo = b * (CDIM * TJ);
        p_iy = 3 * y - 1;
        p_ix = 3 * xx - 1;
    }

    const uint32_t a_row  = (lane & 7) + ((lane >> 3) & 1) * 8;
    const uint32_t a_koff = (lane >> 4) * 8;
    const uint32_t b_row  = (lane & 7) + (lane >> 4) * 8;
    const uint32_t b_koff = ((lane >> 3) & 1) * 8;

    __align__(16) unsigned short pv[16];

    auto cpW = [&](int kc, int bsel) {
        uint32_t dstb = sbase + CV_WBUF + (uint32_t)bsel * 36864;
#pragma unroll
        for (int t = 0; t < 4; t++) {
            int e = tid + t * 512;
            int row = e >> 3, col = e & 7;
            CP_ASYNC16(dstb + ((uint32_t)row * 72 + col * 8) * 2,
                       (const void*)(g_qwh + (size_t)(m0 + row) * 2304 + kc + col * 8));
        }
    };
    auto gatherP = [&](int kc) {
        const int kb = kc + kslot * 16;
#pragma unroll
        for (int t = 0; t < 16; t++) {
            uint32_t kt = ktab[kb + t];          // warp-uniform
            int i = kt >> 4, ky = (kt >> 2) & 3, kx = kt & 3;
            int iy = p_iy + ky, ix = p_ix + kx;
            unsigned short v = 0;
            if ((unsigned)iy < (unsigned)TDIM && (unsigned)ix < (unsigned)JDIM)
                v = *(const unsigned short*)&g_xn[p_xo + i * TJ + iy * JDIM + ix];
            pv[t] = v;
        }
    };
    auto storeP = [&](int bsel) {
        char* pb2 = smem + CV_PBUF + bsel * 18432;
        uint32_t off = ((uint32_t)gl * 72 + kslot * 16) * 2;
        *(uint4*)(pb2 + off)      = ((const uint4*)pv)[0];
        *(uint4*)(pb2 + off + 16) = ((const uint4*)pv)[1];
    };

    float d[4][4][4];
#pragma unroll
    for (int mi = 0; mi < 4; mi++)
#pragma unroll
        for (int nf = 0; nf < 4; nf++)
#pragma unroll
            for (int q = 0; q < 4; q++) d[mi][nf][q] = 0.f;

    cpW(0, 0); CP_COMMIT();
    gatherP(0); storeP(0);

    for (int c = 0; c < 36; c++) {
        if (c < 35) {
            cpW((c + 1) * 64, (c + 1) & 1); CP_COMMIT();
            gatherP((c + 1) * 64);
            CP_WAIT1();
        } else {
            CP_WAIT0();
        }
        __syncthreads();

        const uint32_t wsb = sbase + CV_WBUF + (uint32_t)(c & 1) * 36864;
        const uint32_t psb = sbase + CV_PBUF + (uint32_t)(c & 1) * 18432;
#pragma unroll
        for (int ks = 0; ks < 4; ks++) {
            const int k0 = ks * 16;
            uint32_t b0[4], b1[4];
            LDM_X4(b0, psb + (((uint32_t)(wx * 32)      + b_row) * 72 + k0 + b_koff) * 2);
            LDM_X4(b1, psb + (((uint32_t)(wx * 32 + 16) + b_row) * 72 + k0 + b_koff) * 2);
            uint32_t a[4][4];
#pragma unroll
            for (int mi = 0; mi < 4; mi++)
                LDM_X4(a[mi], wsb + (((uint32_t)(wy * 64 + mi * 16) + a_row) * 72
                                      + k0 + a_koff) * 2);
#pragma unroll
            for (int mi = 0; mi < 4; mi++) {
                MMA16816(d[mi][0], a[mi], b0[0], b0[1]);
                MMA16816(d[mi][1], a[mi], b0[2], b0[3]);
                MMA16816(d[mi][2], a[mi], b1[0], b1[1]);
                MMA16816(d[mi][3], a[mi], b1[2], b1[3]);
            }
        }
        if (c < 35) storeP((c + 1) & 1);
        __syncthreads();
    }

    float* stage = (float*)(smem + CV_STAGE);
    const int tpart = blockIdx.x;
#pragma unroll
    for (int h = 0; h < 2; h++) {
        if ((wy >> 1) == h) {
            int r = lane >> 2, c2 = (lane & 3) * 2;
#pragma unroll
            for (int mi = 0; mi < 4; mi++) {
                int row = wy * 64 + mi * 16 + r - 128 * h;
#pragma unroll
                for (int nf = 0; nf < 4; nf++) {
                    int col = wx * 32 + nf * 8 + c2;
                    stage[col * 129 + row]           = d[mi][nf][0];
                    stage[(col + 1) * 129 + row]     = d[mi][nf][1];
                    stage[col * 129 + row + 8]       = d[mi][nf][2];
                    stage[(col + 1) * 129 + row + 8] = d[mi][nf][3];
                }
            }
        }
        __syncthreads();
        for (int e = tid; e < 16384; e += 512) {
            int gl2 = e >> 7, cl = e & 127;
            int g = n0 + gl2;
            int b = g / HW, hw = g - b * HW;
            int ch = 128 * h + cl;
            float v = stage[gl2 * 129 + cl] * s_o[ch] + t_o[ch];
            g_qkv[(((size_t)b * 3 + tpart) * HW + hw) * CDIM + ch] = gelu_exact(v);
        }
        __syncthreads();
    }
}

// ---------------------------------------------------------------------------
// K2: attention on HMMA (unchanged from round 8)
// ---------------------------------------------------------------------------
#define AT_STR  40
#define AT_Q    0
#define AT_K    21760
#define AT_V    43520
#define AT_TOT  65280

__global__ void __launch_bounds__(544) k_attn_mma()
{
    extern __shared__ char smem[];
    const uint32_t sbase = smem_u32(smem);
    __half* qs = (__half*)(smem + AT_Q);
    __half* ks = (__half*)(smem + AT_K);
    __half* vs = (__half*)(smem + AT_V);

    const int bh = blockIdx.x;
    const int b = bh >> 3, h = bh & 7;
    const int tid = threadIdx.x;
    const int wid = tid >> 5, lane = tid & 31;

    const float* qg = g_qkv + (((size_t)b * 3 + 0) * HW) * CDIM + h * 32;
    const float* kg = g_qkv + (((size_t)b * 3 + 1) * HW) * CDIM + h * 32;
    const float* vg = g_qkv + (((size_t)b * 3 + 2) * HW) * CDIM + h * 32;

    const float scale = 0.17677669529663687f;
    for (int e = tid; e < 272 * 32; e += 544) {
        int r = e >> 5, d = e & 31;
        float qv_ = 0.f, kv_ = 0.f, vv_ = 0.f;
        if (r < HW) {
            size_t off = (size_t)r * CDIM + d;
            qv_ = qg[off] * scale;
            kv_ = kg[off];
            vv_ = vg[off];
        }
        qs[r * AT_STR + d] = __float2half(qv_);
        ks[r * AT_STR + d] = __float2half(kv_);
        vs[r * AT_STR + d] = __float2half(vv_);
    }
    __syncthreads();

    const int m0 = wid * 16;
    const uint32_t a_row  = (lane & 7) + ((lane >> 3) & 1) * 8;
    const uint32_t a_koff = (lane >> 4) * 8;
    const uint32_t b_row  = (lane & 7) + (lane >> 4) * 8;
    const uint32_t b_koff = ((lane >> 3) & 1) * 8;
    const uint32_t v_row  = (lane & 7) + ((lane >> 3) & 1) * 8;
    const uint32_t v_col  = (lane >> 4) * 8;

    const uint32_t qs_base = sbase + AT_Q;
    const uint32_t ks_base = sbase + AT_K;
    const uint32_t vs_base = sbase + AT_V;

    uint32_t qa[2][4];
    LDM_X4(qa[0], qs_base + (((uint32_t)m0 + a_row) * AT_STR + 0  + a_koff) * 2);
    LDM_X4(qa[1], qs_base + (((uint32_t)m0 + a_row) * AT_STR + 16 + a_koff) * 2);

    float o[4][4];
#pragma unroll
    for (int nt = 0; nt < 4; nt++)
#pragma unroll
        for (int q = 0; q < 4; q++) o[nt][q] = 0.f;
    float mr = -1e30f, mr8 = -1e30f, lr = 0.f, lr8 = 0.f;

    const int c2 = (lane & 3) * 2;

    for (int jt = 0; jt < 17; jt++) {
        float s0[4] = {0.f, 0.f, 0.f, 0.f};
        float s1[4] = {0.f, 0.f, 0.f, 0.f};
        {
            uint32_t bb[4];
            LDM_X4(bb, ks_base + (((uint32_t)(jt * 16) + b_row) * AT_STR + 0 + b_koff) * 2);
            MMA16816(s0, qa[0], bb[0], bb[1]);
            MMA16816(s1, qa[0], bb[2], bb[3]);
            LDM_X4(bb, ks_base + (((uint32_t)(jt * 16) + b_row) * AT_STR + 16 + b_koff) * 2);
            MMA16816(s0, qa[1], bb[0], bb[1]);
            MMA16816(s1, qa[1], bb[2], bb[3]);
        }
        if (jt == 16) {
            if (256 + c2     >= HW) { s0[0] = -1e30f; s0[2] = -1e30f; }
            if (256 + c2 + 1 >= HW) { s0[1] = -1e30f; s0[3] = -1e30f; }
            if (256 + c2 + 8 >= HW) { s1[0] = -1e30f; s1[2] = -1e30f; }
            if (256 + c2 + 9 >= HW) { s1[1] = -1e30f; s1[3] = -1e30f; }
        }

        float cmr  = fmaxf(fmaxf(s0[0], s0[1]), fmaxf(s1[0], s1[1]));
        float cmr8 = fmaxf(fmaxf(s0[2], s0[3]), fmaxf(s1[2], s1[3]));
        cmr  = fmaxf(cmr,  __shfl_xor_sync(0xffffffffu, cmr, 1));
        cmr  = fmaxf(cmr,  __shfl_xor_sync(0xffffffffu, cmr, 2));
        cmr8 = fmaxf(cmr8, __shfl_xor_sync(0xffffffffu, cmr8, 1));
        cmr8 = fmaxf(cmr8, __shfl_xor_sync(0xffffffffu, cmr8, 2));
        float mnr  = fmaxf(mr, cmr);
        float mnr8 = fmaxf(mr8, cmr8);
        float corr  = __expf(mr - mnr);
        float corr8 = __expf(mr8 - mnr8);
        float p00 = __expf(s0[0] - mnr),  p01 = __expf(s0[1] - mnr);
        float p02 = __expf(s1[0] - mnr),  p03 = __expf(s1[1] - mnr);
        float p80 = __expf(s0[2] - mnr8), p81 = __expf(s0[3] - mnr8);
        float p82 = __expf(s1[2] - mnr8), p83 = __expf(s1[3] - mnr8);
        float ps  = p00 + p01 + p02 + p03;
        float ps8 = p80 + p81 + p82 + p83;
        ps  += __shfl_xor_sync(0xffffffffu, ps, 1);
        ps  += __shfl_xor_sync(0xffffffffu, ps, 2);
        ps8 += __shfl_xor_sync(0xffffffffu, ps8, 1);
        ps8 += __shfl_xor_sync(0xffffffffu, ps8, 2);
        lr  = lr  * corr  + ps;
        lr8 = lr8 * corr8 + ps8;
        mr = mnr; mr8 = mnr8;

        uint32_t pa[4];
        pa[0] = h2_to_u32(__floats2half2_rn(p00, p01));
        pa[1] = h2_to_u32(__floats2half2_rn(p80, p81));
        pa[2] = h2_to_u32(__floats2half2_rn(p02, p03));
        pa[3] = h2_to_u32(__floats2half2_rn(p82, p83));

#pragma unroll
        for (int nt = 0; nt < 4; nt++) {
            o[nt][0] *= corr;  o[nt][1] *= corr;
            o[nt][2] *= corr8; o[nt][3] *= corr8;
        }

        {
            uint32_t vb[4];
            LDM_X4_T(vb, vs_base + (((uint32_t)(jt * 16) + v_row) * AT_STR + 0 + v_col) * 2);
            MMA16816(o[0], pa, vb[0], vb[1]);
            MMA16816(o[1], pa, vb[2], vb[3]);
            LDM_X4_T(vb, vs_base + (((uint32_t)(jt * 16) + v_row) * AT_STR + 16 + v_col) * 2);
            MMA16816(o[2], pa, vb[0], vb[1]);
            MMA16816(o[3], pa, vb[2], vb[3]);
        }
    }

    const int r0 = m0 + (lane >> 2);
    float invr  = 1.f / lr;
    float invr8 = 1.f / lr8;
    if (r0 < HW) {
        float* og = g_att + ((size_t)b * HW + r0) * CDIM + h * 32 + c2;
#pragma unroll
        for (int nt = 0; nt < 4; nt++) {
            og[nt * 8 + 0] = o[nt][0] * invr;
            og[nt * 8 + 1] = o[nt][1] * invr;
        }
    }
    if (r0 + 8 < HW) {
        float* og = g_att + ((size_t)b * HW + r0 + 8) * CDIM + h * 32 + c2;
#pragma unroll
        for (int nt = 0; nt < 4; nt++) {
            og[nt * 8 + 0] = o[nt][2] * invr8;
            og[nt * 8 + 1] = o[nt][3] * invr8;
        }
    }
}

// ---------------------------------------------------------------------------
// K3: proj on HMMA, merged M (unchanged from round 9)
// ---------------------------------------------------------------------------
#define PJ_PB    0
#define PJ_O00   1024
#define PJ_O01   1536
#define PJ_O10   2048
#define PJ_O11   2560
#define PJ_WXT   3072
#define PJ_WYT   3584
#define PJ_PS    4096
#define PJ_WBUF  71680
#define PJ_STAGE PJ_PS
#define PJ_TOT   145408

__global__ void __launch_bounds__(512, 1) k_proj_mma(
    const float* __restrict__ pb,
    const float* __restrict__ x, float* __restrict__ x1)
{
    extern __shared__ char smem[];
    const uint32_t sbase = smem_u32(smem);
    const int tid = threadIdx.x;
    const int wid = tid >> 5, lane = tid & 31;
    const int wy = wid & 3, wx = wid >> 2;

    const int b  = blockIdx.x / 17;
    const int p0 = (blockIdx.x - b * 17) * 128;

    float* pbs = (float*)(smem + PJ_PB);
    int*   o00 = (int*)(smem + PJ_O00);
    int*   o01 = (int*)(smem + PJ_O01);
    int*   o10 = (int*)(smem + PJ_O10);
    int*   o11 = (int*)(smem + PJ_O11);
    float* wxs = (float*)(smem + PJ_WXT);
    float* wys = (float*)(smem + PJ_WYT);

    auto cpW = [&](int kc, int bsel) {
        uint32_t dstb = sbase + PJ_WBUF + (uint32_t)bsel * 36864;
#pragma unroll
        for (int t = 0; t < 4; t++) {
            int e = tid + t * 512;
            int row = e >> 3, col = e & 7;
            CP_ASYNC16(dstb + ((uint32_t)row * 72 + col * 8) * 2,
                       (const void*)(g_pwh + (size_t)row * 256 + kc + col * 8));
        }
    };

    cpW(0, 0); CP_COMMIT();

    if (tid < 128) {
        int p = p0 + tid;
        int t = p / JDIM, j = p - t * JDIM;
        float sy = (t + 0.5f) * (43.0f / 128.0f) - 0.5f;
        sy = fminf(fmaxf(sy, 0.f), 42.f);
        int y0 = (int)sy;
        int y1 = min(y0 + 1, 42);
        float fy = sy - y0;
        float sx = (j + 0.5f) * (6.0f / 17.0f) - 0.5f;
        sx = fminf(fmaxf(sx, 0.f), 5.f);
        int x0 = (int)sx;
        int x1i = min(x0 + 1, 5);
        float fx = sx - x0;
        o00[tid] = (y0 * WCC + x0) * CDIM;
        o01[tid] = (y0 * WCC + x1i) * CDIM;
        o10[tid] = (y1 * WCC + x0) * CDIM;
        o11[tid] = (y1 * WCC + x1i) * CDIM;
        wxs[tid] = fx;
        wys[tid] = fy;
    } else if (tid < 384) {
        pbs[tid - 128] = pb[tid - 128];
    }
    __syncthreads();

    const float* abase = g_att + (size_t)b * HW * CDIM;
    for (int e = tid; e < 32768; e += 512) {
        int k = e & 255, gl = e >> 8;
        const float* bp = abase + k;
        float fx = wxs[gl], fy = wys[gl];
        float a00 = bp[o00[gl]];
        float a01 = bp[o01[gl]];
        float a10 = bp[o10[gl]];
        float a11 = bp[o11[gl]];
        float v = (a00 * (1.f - fx) + a01 * fx) * (1.f - fy)
                + (a10 * (1.f - fx) + a11 * fx) * fy;
        *(__half*)(smem + PJ_PS + ((uint32_t)gl * 264 + k) * 2) = __float2half(v);
    }

    const uint32_t a_row  = (lane & 7) + ((lane >> 3) & 1) * 8;
    const uint32_t a_koff = (lane >> 4) * 8;
    const uint32_t b_row  = (lane & 7) + (lane >> 4) * 8;
    const uint32_t b_koff = ((lane >> 3) & 1) * 8;
    const uint32_t ps_base = sbase + PJ_PS;

    float d[4][4][4];
#pragma unroll
    for (int mi = 0; mi < 4; mi++)
#pragma unroll
        for (int nf = 0; nf < 4; nf++)
#pragma unroll
            for (int q = 0; q < 4; q++) d[mi][nf][q] = 0.f;

    for (int c = 0; c < 4; c++) {
        if (c < 3) {
            cpW((c + 1) * 64, (c + 1) & 1); CP_COMMIT();
            CP_WAIT1();
        } else {
            CP_WAIT0();
        }
        __syncthreads();

        const uint32_t wsb = sbase + PJ_WBUF + (uint32_t)(c & 1) * 36864;
#pragma unroll
        for (int ks = 0; ks < 4; ks++) {
            const int k0 = ks * 16;
            const int kg = c * 64 + k0;
            uint32_t b0[4], b1[4];
            LDM_X4(b0, ps_base + (((uint32_t)(wx * 32)      + b_row) * 264 + kg + b_koff) * 2);
            LDM_X4(b1, ps_base + (((uint32_t)(wx * 32 + 16) + b_row) * 264 + kg + b_koff) * 2);
            uint32_t a[4][4];
#pragma unroll
            for (int mi = 0; mi < 4; mi++)
                LDM_X4(a[mi], wsb + (((uint32_t)(wy * 64 + mi * 16) + a_row) * 72
                                      + k0 + a_koff) * 2);
#pragma unroll
            for (int mi = 0; mi < 4; mi++) {
                MMA16816(d[mi][0], a[mi], b0[0], b0[1]);
                MMA16816(d[mi][1], a[mi], b0[2], b0[3]);
                MMA16816(d[mi][2], a[mi], b1[0], b1[1]);
                MMA16816(d[mi][3], a[mi], b1[2], b1[3]);
            }
        }
        __syncthreads();
    }

    float* stage = (float*)(smem + PJ_STAGE);
#pragma unroll
    for (int h = 0; h < 2; h++) {
        if ((wy >> 1) == h) {
            int r = lane >> 2, c2 = (lane & 3) * 2;
#pragma unroll
            for (int mi = 0; mi < 4; mi++) {
                int row = wy * 64 + mi * 16 + r - 128 * h;
#pragma unroll
                for (int nf = 0; nf < 4; nf++) {
                    int col = wx * 32 + nf * 8 + c2;
                    stage[col * 129 + row]           = d[mi][nf][0];
                    stage[(col + 1) * 129 + row]     = d[mi][nf][1];
                    stage[col * 129 + row + 8]       = d[mi][nf][2];
                    stage[(col + 1) * 129 + row + 8] = d[mi][nf][3];
                }
            }
        }
        __syncthreads();
        for (int e = tid; e < 16384; e += 512) {
            int gl = e & 127, cl = e >> 7;
            int ch = 128 * h + cl;
            size_t idx = ((size_t)b * CDIM + ch) * TJ + p0 + gl;
            x1[idx] = x[idx] + stage[gl * 129 + cl] + pbs[ch];
        }
        __syncthreads();
    }
}

// ---------------------------------------------------------------------------
// K4: fused MLP on HMMA, big-tile (unchanged from round 9)
// ---------------------------------------------------------------------------
#define M2_SN   0
#define M2_TN   1024
#define M2_S2   2048
#define M2_T2   3072
#define M2_S1   4096
#define M2_T1   4608
#define M2_XS   5120
#define M2_HS   72704
#define M2_WB   107520
#define M2_ST   M2_XS
#define M2_TOT  181248

__global__ void __launch_bounds__(512, 1) k_mlp_mma2(
    const float* x1,
    const float* __restrict__ b1g, const float* __restrict__ b1b,
    const float* __restrict__ b1m, const float* __restrict__ b1v,
    const float* __restrict__ fb1,
    const float* __restrict__ b2g, const float* __restrict__ b2b,
    const float* __restrict__ b2m, const float* __restrict__ b2v,
    const float* __restrict__ fb2,
    const float* __restrict__ n2g, const float* __restrict__ n2b,
    const float* __restrict__ n2m, const float* __restrict__ n2v,
    float* out)
{
    extern __shared__ char smem[];
    const uint32_t sbase = smem_u32(smem);
    const int tid = threadIdx.x;
    const int wid = tid >> 5, lane = tid & 31;
    const int wy = wid & 3, wx = wid >> 2;

    const int b  = blockIdx.x / 17;
    const int p0 = (blockIdx.x - b * 17) * 128;

    float* sn = (float*)(smem + M2_SN);
    float* tn = (float*)(smem + M2_TN);
    float* s2 = (float*)(smem + M2_S2);
    float* t2 = (float*)(smem + M2_T2);
    float* s1 = (float*)(smem + M2_S1);
    float* t1 = (float*)(smem + M2_T1);

    auto cpW1 = [&](int nt, int c, int bsel) {
        uint32_t dstb = sbase + M2_WB + (uint32_t)bsel * 36864;
        const __half* src = g_w1h + nt * 32768 + c * 64;
#pragma unroll
        for (int t = 0; t < 2; t++) {
            int e = tid + t * 512;
            int row = e >> 3, col = e & 7;
            CP_ASYNC16(dstb + ((uint32_t)row * 72 + col * 8) * 2,
                       (const void*)(src + (size_t)row * 256 + col * 8));
        }
    };
    auto cpW2 = [&](int nt, int c, int bsel) {
        uint32_t dstb = sbase + M2_WB + (uint32_t)bsel * 36864;
        const __half* src = g_w2h + nt * 32768 + c * 64;
#pragma unroll
        for (int t = 0; t < 4; t++) {
            int e = tid + t * 512;
            int row = e >> 3, col = e & 7;
            CP_ASYNC16(dstb + ((uint32_t)row * 72 + col * 8) * 2,
                       (const void*)(src + (size_t)row * 128 + col * 8));
        }
    };

    cpW1(0, 0, 0); CP_COMMIT();

    if (tid < 256) {
        float s = n2g[tid] * rsqrtf(n2v[tid] + 1e-5f);
        sn[tid] = s;
        tn[tid] = n2b[tid] - n2m[tid] * s;
    } else {
        int c = tid - 256;
        float s = b2g[c] * rsqrtf(b2v[c] + 1e-5f);
        s2[c] = s;
        t2[c] = b2b[c] - b2m[c] * s + fb2[c] * s;
    }
    __syncthreads();

    const float* xb = x1 + (size_t)b * CDIM * TJ;
    for (int e = tid; e < 32768; e += 512) {
        int i = e & 255, p = e >> 8;
        float v = xb[(size_t)i * TJ + p0 + p] * sn[i] + tn[i];
        *(__half*)(smem + M2_XS + ((uint32_t)p * 264 + i) * 2) = __float2half(v);
    }

    const uint32_t a_row  = (lane & 7) + ((lane >> 3) & 1) * 8;
    const uint32_t a_koff = (lane >> 4) * 8;
    const uint32_t b_row  = (lane & 7) + (lane >> 4) * 8;
    const uint32_t b_koff = ((lane >> 3) & 1) * 8;

    const uint32_t xs_base = sbase + M2_XS;
    const uint32_t hs_base = sbase + M2_HS;

    float d2[4][4][4];
#pragma unroll
    for (int mi = 0; mi < 4; mi++)
#pragma unroll
        for (int nf = 0; nf < 4; nf++)
#pragma unroll
            for (int q = 0; q < 4; q++) d2[mi][nf][q] = 0.f;

    int buf = 0;

    for (int nt = 0; nt < 8; nt++) {
        if (tid < 128) {
            int j = nt * 128 + tid;
            float s = b1g[j] * rsqrtf(b1v[j] + 1e-5f);
            s1[tid] = s;
            t1[tid] = b1b[j] - b1m[j] * s + fb1[j] * s;
        }

        float d1[2][4][4];
#pragma unroll
        for (int mi = 0; mi < 2; mi++)
#pragma unroll
            for (int nf = 0; nf < 4; nf++)
#pragma unroll
                for (int q = 0; q < 4; q++) d1[mi][nf][q] = 0.f;

        for (int c = 0; c < 4; c++) {
            if (c < 3) cpW1(nt, c + 1, buf ^ 1);
            else       cpW2(nt, 0, buf ^ 1);
            CP_COMMIT(); CP_WAIT1();
            __syncthreads();

            const uint32_t wsb = sbase + M2_WB + (uint32_t)buf * 36864;
#pragma unroll
            for (int ks = 0; ks < 4; ks++) {
                const int k0 = ks * 16;
                const int kg = c * 64 + k0;
                uint32_t b0[4], b1[4];
                LDM_X4(b0, xs_base + (((uint32_t)(wx * 32)      + b_row) * 264 + kg + b_koff) * 2);
                LDM_X4(b1, xs_base + (((uint32_t)(wx * 32 + 16) + b_row) * 264 + kg + b_koff) * 2);
                uint32_t a[2][4];
#pragma unroll
                for (int mi = 0; mi < 2; mi++)
                    LDM_X4(a[mi], wsb + (((uint32_t)(wy * 32 + mi * 16) + a_row) * 72
                                          + k0 + a_koff) * 2);
#pragma unroll
                for (int mi = 0; mi < 2; mi++) {
                    MMA16816(d1[mi][0], a[mi], b0[0], b0[1]);
                    MMA16816(d1[mi][1], a[mi], b0[2], b0[3]);
                    MMA16816(d1[mi][2], a[mi], b1[0], b1[1]);
                    MMA16816(d1[mi][3], a[mi], b1[2], b1[3]);
                }
            }
            buf ^= 1;
            __syncthreads();
        }

        {
            int r = lane >> 2, c2l = (lane & 3) * 2;
#pragma unroll
            for (int mi = 0; mi < 2; mi++) {
                int j = wy * 32 + mi * 16 + r;
                float sj0 = s1[j],     tj0 = t1[j];
                float sj8 = s1[j + 8], tj8 = t1[j + 8];
#pragma unroll
                for (int nf = 0; nf < 4; nf++) {
                    int pos = wx * 32 + nf * 8 + c2l;
                    __half* h0 = (__half*)(smem + M2_HS + ((uint32_t)pos * 136 + j) * 2);
                    __half* h1 = (__half*)(smem + M2_HS + ((uint32_t)(pos + 1) * 136 + j) * 2);
                    h0[0] = __float2half(gelu_exact(d1[mi][nf][0] * sj0 + tj0));
                    h1[0] = __float2half(gelu_exact(d1[mi][nf][1] * sj0 + tj0));
                    h0[8] = __float2half(gelu_exact(d1[mi][nf][2] * sj8 + tj8));
                    h1[8] = __float2half(gelu_exact(d1[mi][nf][3] * sj8 + tj8));
                }
            }
        }

        for (int c = 0; c < 2; c++) {
            if (c == 0)        { cpW2(nt, 1, buf ^ 1); CP_COMMIT(); CP_WAIT1(); }
            else if (nt < 7)   { cpW1(nt + 1, 0, buf ^ 1); CP_COMMIT(); CP_WAIT1(); }
            else               { CP_WAIT0(); }
            __syncthreads();

            const uint32_t wsb = sbase + M2_WB + (uint32_t)buf * 36864;
#pragma unroll
            for (int ks = 0; ks < 4; ks++) {
                const int k0 = ks * 16;
                const int kg = c * 64 + k0;
                uint32_t b0[4], b1[4];
                LDM_X4(b0, hs_base + (((uint32_t)(wx * 32)      + b_row) * 136 + kg + b_koff) * 2);
                LDM_X4(b1, hs_base + (((uint32_t)(wx * 32 + 16) + b_row) * 136 + kg + b_koff) * 2);
                uint32_t a[4][4];
#pragma unroll
                for (int mi = 0; mi < 4; mi++)
                    LDM_X4(a[mi], wsb + (((uint32_t)(wy * 64 + mi * 16) + a_row) * 72
                                          + k0 + a_koff) * 2);
#pragma unroll
                for (int mi = 0; mi < 4; mi++) {
                    MMA16816(d2[mi][0], a[mi], b0[0], b0[1]);
                    MMA16816(d2[mi][1], a[mi], b0[2], b0[3]);
                    MMA16816(d2[mi][2], a[mi], b1[0], b1[1]);
                    MMA16816(d2[mi][3], a[mi], b1[2], b1[3]);
                }
            }
            buf ^= 1;
            __syncthreads();
        }
    }

    float* stage = (float*)(smem + M2_ST);
#pragma unroll
    for (int h = 0; h < 2; h++) {
        if ((wy >> 1) == h) {
            int r = lane >> 2, c2l = (lane & 3) * 2;
#pragma unroll
            for (int mi = 0; mi < 4; mi++) {
                int row = wy * 64 + mi * 16 + r - 128 * h;
#pragma unroll
                for (int nf = 0; nf < 4; nf++) {
                    int col = wx * 32 + nf * 8 + c2l;
                    stage[col * 129 + row]           = d2[mi][nf][0];
                    stage[(col + 1) * 129 + row]     = d2[mi][nf][1];
                    stage[col * 129 + row + 8]       = d2[mi][nf][2];
                    stage[(col + 1) * 129 + row + 8] = d2[mi][nf][3];
                }
            }
        }
        __syncthreads();
        for (int e = tid; e < 16384; e += 512) {
            int gl = e & 127, cl = e >> 7;
            int ch = 128 * h + cl;
            size_t idx = ((size_t)b * CDIM + ch) * TJ + p0 + gl;
            out[idx] = x1[idx] + stage[gl * 129 + cl] * s2[ch] + t2[ch];
        }
        __syncthreads();
    }
}

// ---------------------------------------------------------------------------
extern "C" void kernel_launch(void* const* d_in, const int* in_sizes, int n_in,
                              void* d_out, int out_size)
{
    const float* x    = (const float*)d_in[0];
    const float* n1g  = (const float*)d_in[1];
    const float* n1b  = (const float*)d_in[2];
    const float* n1m  = (const float*)d_in[3];
    const float* n1v  = (const float*)d_in[4];
    const float* qkvw = (const float*)d_in[5];
    const float* qg   = (const float*)d_in[6];
    const float* qb   = (const float*)d_in[7];
    const float* qm   = (const float*)d_in[8];
    const float* qv   = (const float*)d_in[9];
    const float* pw   = (const float*)d_in[10];
    const float* pb   = (const float*)d_in[11];
    const float* n2g  = (const float*)d_in[12];
    const float* n2b  = (const float*)d_in[13];
    const float* n2m  = (const float*)d_in[14];
    const float* n2v  = (const float*)d_in[15];
    const float* w1   = (const float*)d_in[16];
    const float* fb1  = (const float*)d_in[17];
    const float* b1g  = (const float*)d_in[18];
    const float* b1b  = (const float*)d_in[19];
    const float* b1m  = (const float*)d_in[20];
    const float* b1v  = (const float*)d_in[21];
    const float* w2   = (const float*)d_in[22];
    const float* fb2  = (const float*)d_in[23];
    const float* b2g  = (const float*)d_in[24];
    const float* b2b  = (const float*)d_in[25];
    const float* b2m  = (const float*)d_in[26];
    const float* b2v  = (const float*)d_in[27];
    float* out = (float*)d_out;

    cudaFuncSetAttribute(k_attn_mma, cudaFuncAttributeMaxDynamicSharedMemorySize, AT_TOT);
    cudaFuncSetAttribute(k_conv_mma, cudaFuncAttributeMaxDynamicSharedMemorySize, CV_TOT);
    cudaFuncSetAttribute(k_proj_mma, cudaFuncAttributeMaxDynamicSharedMemorySize, PJ_TOT);
    cudaFuncSetAttribute(k_mlp_mma2, cudaFuncAttributeMaxDynamicSharedMemorySize, M2_TOT);

    k_prep<<<9216, 256>>>(w1, w2, qkvw, pw);
    k_prexn<<<16384, 512>>>(x, n1g, n1b, n1m, n1v);
    k_conv_mma<<<dim3(3, 129), 512, CV_TOT>>>(qg, qb, qm, qv);
    k_attn_mma<<<512, 544, AT_TOT>>>();
    k_proj_mma<<<1088, 512, PJ_TOT>>>(pb, x, out);
    k_mlp_mma2<<<1088, 512, M2_TOT>>>(out,
                                      b1g, b1b, b1m, b1v, fb1,
                                      b2g, b2b, b2m, b2v, fb2,
                                      n2g, n2b, n2m, n2v, out);
}

// round 11
// speedup vs baseline: 8.7966x; 1.0047x over previous
#include <cuda_runtime.h>
#include <cuda_fp16.h>
#include <math.h>
#include <stdint.h>

#define BATCH 64
#define CDIM 256
#define TDIM 128
#define JDIM 17
#define TJ 2176     // TDIM*JDIM
#define HCC 43
#define WCC 6
#define HW 258      // HCC*WCC
#define HIDDEN 1024

// scratch (static __device__ globals per harness rules)
__device__ __half g_qkv[(size_t)3 * BATCH * HW * CDIM];  // fp16 [b][t][hw][c]
__device__ __half g_att[(size_t)BATCH * HW * CDIM];      // fp16 [b][hw][c]
__device__ __half g_xn[(size_t)BATCH * CDIM * TJ];       // n1bn(x) fp16
// fp16 weights
__device__ __half g_w1h[8 * 32768];            // W1 per-tile [128 j][256 i]
__device__ __half g_w2h[8 * 32768];            // W2 per-tile [256 c][128 j]
__device__ __half g_qwh[768 * 2304];           // qkv conv weight row-major
__device__ __half g_pwh[256 * 256];            // proj weight row-major

__device__ __forceinline__ float gelu_exact(float v) {
    return 0.5f * v * (1.0f + erff(v * 0.70710678118654752f));
}

__device__ __forceinline__ uint32_t smem_u32(const void* p) {
    uint32_t a;
    asm("{ .reg .u64 t; cvta.to.shared.u64 t, %1; cvt.u32.u64 %0, t; }" : "=r"(a) : "l"(p));
    return a;
}

__device__ __forceinline__ uint32_t h2_to_u32(__half2 h) {
    return *reinterpret_cast<uint32_t*>(&h);
}

#define LDM_X4(r, addr) \
    asm volatile("ldmatrix.sync.aligned.m8n8.x4.shared.b16 {%0,%1,%2,%3}, [%4];" \
        : "=r"((r)[0]), "=r"((r)[1]), "=r"((r)[2]), "=r"((r)[3]) : "r"(addr))

#define LDM_X4_T(r, addr) \
    asm volatile("ldmatrix.sync.aligned.m8n8.x4.trans.shared.b16 {%0,%1,%2,%3}, [%4];" \
        : "=r"((r)[0]), "=r"((r)[1]), "=r"((r)[2]), "=r"((r)[3]) : "r"(addr))

#define MMA16816(d, a, b0, b1) \
    asm volatile("mma.sync.aligned.m16n8k16.row.col.f32.f16.f16.f32 " \
        "{%0,%1,%2,%3}, {%4,%5,%6,%7}, {%8,%9}, {%0,%1,%2,%3};" \
        : "+f"((d)[0]), "+f"((d)[1]), "+f"((d)[2]), "+f"((d)[3]) \
        : "r"((a)[0]), "r"((a)[1]), "r"((a)[2]), "r"((a)[3]), "r"(b0), "r"(b1))

#define CP_ASYNC16(dst, src) \
    asm volatile("cp.async.cg.shared.global [%0], [%1], 16;" :: "r"(dst), "l"(src))
#define CP_COMMIT() asm volatile("cp.async.commit_group;")
#define CP_WAIT1()  asm volatile("cp.async.wait_group 1;" ::: "memory")
#define CP_WAIT0()  asm volatile("cp.async.wait_group 0;" ::: "memory")

// ---------------------------------------------------------------------------
// K0: merged prep — blocks [0,16384): xn = n1bn(x) fp16; rest: weight convert
// ---------------------------------------------------------------------------
__global__ void __launch_bounds__(512) k_prep_all(
    const float* __restrict__ w1, const float* __restrict__ w2,
    const float* __restrict__ qkvw, const float* __restrict__ pw,
    const float* __restrict__ x,
    const float* __restrict__ n1g, const float* __restrict__ n1b,
    const float* __restrict__ n1m, const float* __restrict__ n1v)
{
    const int blk = blockIdx.x;
    if (blk < 16384) {
        __shared__ float ss, tt;
        const int c = blk & 255;
        if (threadIdx.x == 0) {
            float s = n1g[c] * rsqrtf(n1v[c] + 1e-5f);
            ss = s;
            tt = n1b[c] - n1m[c] * s;
        }
        __syncthreads();
        const float* xr = x + (size_t)blk * TJ;
        __half* xo = g_xn + (size_t)blk * TJ;
        float s = ss, t = tt;
        for (int p = threadIdx.x; p < TJ; p += 512)
            xo[p] = __float2half(xr[p] * s + t);
        return;
    }
    int idx = (blk - 16384) * 512 + threadIdx.x;
    if (idx < 262144) {
        int j = idx >> 8, i = idx & 255;
        int nt = j >> 7, jl = j & 127;
        g_w1h[(uint32_t)nt * 32768 + (uint32_t)jl * 256 + i] = __float2half(w1[idx]);
    } else if (idx < 524288) {
        int t = idx - 262144;
        int c = t >> 10, j = t & 1023;
        int nt = j >> 7, jl = j & 127;
        g_w2h[(uint32_t)nt * 32768 + (uint32_t)c * 128 + jl] = __float2half(w2[t]);
    } else if (idx < 2293760) {
        int t = idx - 524288;
        g_qwh[t] = __float2half(qkvw[t]);
    } else {
        int t = idx - 2293760;
        g_pwh[t] = __float2half(pw[t]);
    }
}

// ---------------------------------------------------------------------------
// K1: conv QKV on HMMA, merged M (round-10 layout; fp16 output)
// ---------------------------------------------------------------------------
#define CV_KTAB  0
#define CV_SO    4608
#define CV_TO    5632
#define CV_PBUF  6656
#define CV_WBUF  (CV_PBUF + 36864)
#define CV_STAGE CV_PBUF
#define CV_TOT   (CV_WBUF + 73728)

__global__ void __launch_bounds__(512, 1) k_conv_mma(
    const float* __restrict__ qg, const float* __restrict__ qb,
    const float* __restrict__ qm, const float* __restrict__ qv)
{
    extern __shared__ char smem[];
    const uint32_t sbase = smem_u32(smem);
    const int tid = threadIdx.x;
    const int wid = tid >> 5, lane = tid & 31;
    const int wy = wid & 3, wx = wid >> 2;

    const int m0 = blockIdx.x * 256;
    const int n0 = blockIdx.y * 128;

    uint16_t* ktab = (uint16_t*)(smem + CV_KTAB);
    float*    s_o  = (float*)(smem + CV_SO);
    float*    t_o  = (float*)(smem + CV_TO);

    if (tid < 256) {
        int o = m0 + tid;
        float s = qg[o] * rsqrtf(qv[o] + 1e-5f);
        s_o[tid] = s;
        t_o[tid] = qb[o] - qm[o] * s;
    }
    for (int k = tid; k < 2304; k += 512) {
        int i = k / 9, r = k - i * 9;
        int ky = r / 3, kx = r - ky * 3;
        ktab[k] = (uint16_t)((i << 4) | (ky << 2) | kx);
    }
    __syncthreads();

    const int gl    = tid & 127;
    const int kslot = tid >> 7;
    int p_xo, p_iy, p_ix;
    {
        int g = n0 + gl;
        int b = g / HW, hw = g - b * HW;
        int y = hw / WCC, xx = hw - y * WCC;
        p_xo = b * (CDIM * TJ);
        p_iy = 3 * y - 1;
        p_ix = 3 * xx - 1;
    }

    const uint32_t a_row  = (lane & 7) + ((lane >> 3) & 1) * 8;
    const uint32_t a_koff = (lane >> 4) * 8;
    const uint32_t b_row  = (lane & 7) + (lane >> 4) * 8;
    const uint32_t b_koff = ((lane >> 3) & 1) * 8;

    __align__(16) unsigned short pv[16];

    auto cpW = [&](int kc, int bsel) {
        uint32_t dstb = sbase + CV_WBUF + (uint32_t)bsel * 36864;
#pragma unroll
        for (int t = 0; t < 4; t++) {
            int e = tid + t * 512;
            int row = e >> 3, col = e & 7;
            CP_ASYNC16(dstb + ((uint32_t)row * 72 + col * 8) * 2,
                       (const void*)(g_qwh + (size_t)(m0 + row) * 2304 + kc + col * 8));
        }
    };
    auto gatherP = [&](int kc) {
        const int kb = kc + kslot * 16;
#pragma unroll
        for (int t = 0; t < 16; t++) {
            uint32_t kt = ktab[kb + t];
            int i = kt >> 4, ky = (kt >> 2) & 3, kx = kt & 3;
            int iy = p_iy + ky, ix = p_ix + kx;
            unsigned short v = 0;
            if ((unsigned)iy < (unsigned)TDIM && (unsigned)ix < (unsigned)JDIM)
                v = *(const unsigned short*)&g_xn[p_xo + i * TJ + iy * JDIM + ix];
            pv[t] = v;
        }
    };
    auto storeP = [&](int bsel) {
        char* pb2 = smem + CV_PBUF + bsel * 18432;
        uint32_t off = ((uint32_t)gl * 72 + kslot * 16) * 2;
        *(uint4*)(pb2 + off)      = ((const uint4*)pv)[0];
        *(uint4*)(pb2 + off + 16) = ((const uint4*)pv)[1];
    };

    float d[4][4][4];
#pragma unroll
    for (int mi = 0; mi < 4; mi++)
#pragma unroll
        for (int nf = 0; nf < 4; nf++)
#pragma unroll
            for (int q = 0; q < 4; q++) d[mi][nf][q] = 0.f;

    cpW(0, 0); CP_COMMIT();
    gatherP(0); storeP(0);

    for (int c = 0; c < 36; c++) {
        if (c < 35) {
            cpW((c + 1) * 64, (c + 1) & 1); CP_COMMIT();
            gatherP((c + 1) * 64);
            CP_WAIT1();
        } else {
            CP_WAIT0();
        }
        __syncthreads();

        const uint32_t wsb = sbase + CV_WBUF + (uint32_t)(c & 1) * 36864;
        const uint32_t psb = sbase + CV_PBUF + (uint32_t)(c & 1) * 18432;
#pragma unroll
        for (int ks = 0; ks < 4; ks++) {
            const int k0 = ks * 16;
            uint32_t b0[4], b1[4];
            LDM_X4(b0, psb + (((uint32_t)(wx * 32)      + b_row) * 72 + k0 + b_koff) * 2);
            LDM_X4(b1, psb + (((uint32_t)(wx * 32 + 16) + b_row) * 72 + k0 + b_koff) * 2);
            uint32_t a[4][4];
#pragma unroll
            for (int mi = 0; mi < 4; mi++)
                LDM_X4(a[mi], wsb + (((uint32_t)(wy * 64 + mi * 16) + a_row) * 72
                                      + k0 + a_koff) * 2);
#pragma unroll
            for (int mi = 0; mi < 4; mi++) {
                MMA16816(d[mi][0], a[mi], b0[0], b0[1]);
                MMA16816(d[mi][1], a[mi], b0[2], b0[3]);
                MMA16816(d[mi][2], a[mi], b1[0], b1[1]);
                MMA16816(d[mi][3], a[mi], b1[2], b1[3]);
            }
        }
        if (c < 35) storeP((c + 1) & 1);
        __syncthreads();
    }

    float* stage = (float*)(smem + CV_STAGE);
    const int tpart = blockIdx.x;
#pragma unroll
    for (int h = 0; h < 2; h++) {
        if ((wy >> 1) == h) {
            int r = lane >> 2, c2 = (lane & 3) * 2;
#pragma unroll
            for (int mi = 0; mi < 4; mi++) {
                int row = wy * 64 + mi * 16 + r - 128 * h;
#pragma unroll
                for (int nf = 0; nf < 4; nf++) {
                    int col = wx * 32 + nf * 8 + c2;
                    stage[col * 129 + row]           = d[mi][nf][0];
                    stage[(col + 1) * 129 + row]     = d[mi][nf][1];
                    stage[col * 129 + row + 8]       = d[mi][nf][2];
                    stage[(col + 1) * 129 + row + 8] = d[mi][nf][3];
                }
            }
        }
        __syncthreads();
        for (int e = tid; e < 16384; e += 512) {
            int gl2 = e >> 7, cl = e & 127;
            int g = n0 + gl2;
            int b = g / HW, hw = g - b * HW;
            int ch = 128 * h + cl;
            float v = stage[gl2 * 129 + cl] * s_o[ch] + t_o[ch];
            g_qkv[(((size_t)b * 3 + tpart) * HW + hw) * CDIM + ch]
                = __float2half(gelu_exact(v));
        }
        __syncthreads();
    }
}

// ---------------------------------------------------------------------------
// K2: attention on HMMA; fp16 q/k/v in, fp16 out; vectorized smem fill
// ---------------------------------------------------------------------------
#define AT_STR  40
#define AT_Q    0
#define AT_K    21760
#define AT_V    43520
#define AT_TOT  65280

__global__ void __launch_bounds__(544) k_attn_mma()
{
    extern __shared__ char smem[];
    const uint32_t sbase = smem_u32(smem);
    __half* qs = (__half*)(smem + AT_Q);
    __half* ks = (__half*)(smem + AT_K);
    __half* vs = (__half*)(smem + AT_V);

    const int bh = blockIdx.x;
    const int b = bh >> 3, h = bh & 7;
    const int tid = threadIdx.x;
    const int wid = tid >> 5, lane = tid & 31;

    const __half* qg = g_qkv + (((size_t)b * 3 + 0) * HW) * CDIM + h * 32;
    const __half* kg = g_qkv + (((size_t)b * 3 + 1) * HW) * CDIM + h * 32;
    const __half* vg = g_qkv + (((size_t)b * 3 + 2) * HW) * CDIM + h * 32;

    const __half2 sc2 = __float2half2_rn(0.17677669529663687f);
    for (int e = tid; e < 272 * 4; e += 544) {
        int r = e >> 2, d8 = (e & 3) * 8;
        uint4 q4 = make_uint4(0, 0, 0, 0), k4 = q4, v4 = q4;
        if (r < HW) {
            size_t off = (size_t)r * CDIM + d8;
            q4 = *(const uint4*)(qg + off);
            k4 = *(const uint4*)(kg + off);
            v4 = *(const uint4*)(vg + off);
        }
        __half2* qh = (__half2*)&q4;
#pragma unroll
        for (int j = 0; j < 4; j++) qh[j] = __hmul2(qh[j], sc2);
        *(uint4*)(qs + r * AT_STR + d8) = q4;
        *(uint4*)(ks + r * AT_STR + d8) = k4;
        *(uint4*)(vs + r * AT_STR + d8) = v4;
    }
    __syncthreads();

    const int m0 = wid * 16;
    const uint32_t a_row  = (lane & 7) + ((lane >> 3) & 1) * 8;
    const uint32_t a_koff = (lane >> 4) * 8;
    const uint32_t b_row  = (lane & 7) + (lane >> 4) * 8;
    const uint32_t b_koff = ((lane >> 3) & 1) * 8;
    const uint32_t v_row  = (lane & 7) + ((lane >> 3) & 1) * 8;
    const uint32_t v_col  = (lane >> 4) * 8;

    const uint32_t qs_base = sbase + AT_Q;
    const uint32_t ks_base = sbase + AT_K;
    const uint32_t vs_base = sbase + AT_V;

    uint32_t qa[2][4];
    LDM_X4(qa[0], qs_base + (((uint32_t)m0 + a_row) * AT_STR + 0  + a_koff) * 2);
    LDM_X4(qa[1], qs_base + (((uint32_t)m0 + a_row) * AT_STR + 16 + a_koff) * 2);

    float o[4][4];
#pragma unroll
    for (int nt = 0; nt < 4; nt++)
#pragma unroll
        for (int q = 0; q < 4; q++) o[nt][q] = 0.f;
    float mr = -1e30f, mr8 = -1e30f, lr = 0.f, lr8 = 0.f;

    const int c2 = (lane & 3) * 2;

    for (int jt = 0; jt < 17; jt++) {
        float s0[4] = {0.f, 0.f, 0.f, 0.f};
        float s1[4] = {0.f, 0.f, 0.f, 0.f};
        {
            uint32_t bb[4];
            LDM_X4(bb, ks_base + (((uint32_t)(jt * 16) + b_row) * AT_STR + 0 + b_koff) * 2);
            MMA16816(s0, qa[0], bb[0], bb[1]);
            MMA16816(s1, qa[0], bb[2], bb[3]);
            LDM_X4(bb, ks_base + (((uint32_t)(jt * 16) + b_row) * AT_STR + 16 + b_koff) * 2);
            MMA16816(s0, qa[1], bb[0], bb[1]);
            MMA16816(s1, qa[1], bb[2], bb[3]);
        }
        if (jt == 16) {
            if (256 + c2     >= HW) { s0[0] = -1e30f; s0[2] = -1e30f; }
            if (256 + c2 + 1 >= HW) { s0[1] = -1e30f; s0[3] = -1e30f; }
            if (256 + c2 + 8 >= HW) { s1[0] = -1e30f; s1[2] = -1e30f; }
            if (256 + c2 + 9 >= HW) { s1[1] = -1e30f; s1[3] = -1e30f; }
        }

        float cmr  = fmaxf(fmaxf(s0[0], s0[1]), fmaxf(s1[0], s1[1]));
        float cmr8 = fmaxf(fmaxf(s0[2], s0[3]), fmaxf(s1[2], s1[3]));
        cmr  = fmaxf(cmr,  __shfl_xor_sync(0xffffffffu, cmr, 1));
        cmr  = fmaxf(cmr,  __shfl_xor_sync(0xffffffffu, cmr, 2));
        cmr8 = fmaxf(cmr8, __shfl_xor_sync(0xffffffffu, cmr8, 1));
        cmr8 = fmaxf(cmr8, __shfl_xor_sync(0xffffffffu, cmr8, 2));
        float mnr  = fmaxf(mr, cmr);
        float mnr8 = fmaxf(mr8, cmr8);
        float corr  = __expf(mr - mnr);
        float corr8 = __expf(mr8 - mnr8);
        float p00 = __expf(s0[0] - mnr),  p01 = __expf(s0[1] - mnr);
        float p02 = __expf(s1[0] - mnr),  p03 = __expf(s1[1] - mnr);
        float p80 = __expf(s0[2] - mnr8), p81 = __expf(s0[3] - mnr8);
        float p82 = __expf(s1[2] - mnr8), p83 = __expf(s1[3] - mnr8);
        float ps  = p00 + p01 + p02 + p03;
        float ps8 = p80 + p81 + p82 + p83;
        ps  += __shfl_xor_sync(0xffffffffu, ps, 1);
        ps  += __shfl_xor_sync(0xffffffffu, ps, 2);
        ps8 += __shfl_xor_sync(0xffffffffu, ps8, 1);
        ps8 += __shfl_xor_sync(0xffffffffu, ps8, 2);
        lr  = lr  * corr  + ps;
        lr8 = lr8 * corr8 + ps8;
        mr = mnr; mr8 = mnr8;

        uint32_t pa[4];
        pa[0] = h2_to_u32(__floats2half2_rn(p00, p01));
        pa[1] = h2_to_u32(__floats2half2_rn(p80, p81));
        pa[2] = h2_to_u32(__floats2half2_rn(p02, p03));
        pa[3] = h2_to_u32(__floats2half2_rn(p82, p83));

#pragma unroll
        for (int nt = 0; nt < 4; nt++) {
            o[nt][0] *= corr;  o[nt][1] *= corr;
            o[nt][2] *= corr8; o[nt][3] *= corr8;
        }

        {
            uint32_t vb[4];
            LDM_X4_T(vb, vs_base + (((uint32_t)(jt * 16) + v_row) * AT_STR + 0 + v_col) * 2);
            MMA16816(o[0], pa, vb[0], vb[1]);
            MMA16816(o[1], pa, vb[2], vb[3]);
            LDM_X4_T(vb, vs_base + (((uint32_t)(jt * 16) + v_row) * AT_STR + 16 + v_col) * 2);
            MMA16816(o[2], pa, vb[0], vb[1]);
            MMA16816(o[3], pa, vb[2], vb[3]);
        }
    }

    const int r0 = m0 + (lane >> 2);
    float invr  = 1.f / lr;
    float invr8 = 1.f / lr8;
    if (r0 < HW) {
        __half* og = g_att + ((size_t)b * HW + r0) * CDIM + h * 32 + c2;
#pragma unroll
        for (int nt = 0; nt < 4; nt++)
            *(__half2*)(og + nt * 8) = __floats2half2_rn(o[nt][0] * invr, o[nt][1] * invr);
    }
    if (r0 + 8 < HW) {
        __half* og = g_att + ((size_t)b * HW + r0 + 8) * CDIM + h * 32 + c2;
#pragma unroll
        for (int nt = 0; nt < 4; nt++)
            *(__half2*)(og + nt * 8) = __floats2half2_rn(o[nt][2] * invr8, o[nt][3] * invr8);
    }
}

// ---------------------------------------------------------------------------
// K3: proj on HMMA, merged M (g_att now fp16)
// ---------------------------------------------------------------------------
#define PJ_PB    0
#define PJ_O00   1024
#define PJ_O01   1536
#define PJ_O10   2048
#define PJ_O11   2560
#define PJ_WXT   3072
#define PJ_WYT   3584
#define PJ_PS    4096
#define PJ_WBUF  71680
#define PJ_STAGE PJ_PS
#define PJ_TOT   145408

__global__ void __launch_bounds__(512, 1) k_proj_mma(
    const float* __restrict__ pb,
    const float* __restrict__ x, float* __restrict__ x1)
{
    extern __shared__ char smem[];
    const uint32_t sbase = smem_u32(smem);
    const int tid = threadIdx.x;
    const int wid = tid >> 5, lane = tid & 31;
    const int wy = wid & 3, wx = wid >> 2;

    const int b  = blockIdx.x / 17;
    const int p0 = (blockIdx.x - b * 17) * 128;

    float* pbs = (float*)(smem + PJ_PB);
    int*   o00 = (int*)(smem + PJ_O00);
    int*   o01 = (int*)(smem + PJ_O01);
    int*   o10 = (int*)(smem + PJ_O10);
    int*   o11 = (int*)(smem + PJ_O11);
    float* wxs = (float*)(smem + PJ_WXT);
    float* wys = (float*)(smem + PJ_WYT);

    auto cpW = [&](int kc, int bsel) {
        uint32_t dstb = sbase + PJ_WBUF + (uint32_t)bsel * 36864;
#pragma unroll
        for (int t = 0; t < 4; t++) {
            int e = tid + t * 512;
            int row = e >> 3, col = e & 7;
            CP_ASYNC16(dstb + ((uint32_t)row * 72 + col * 8) * 2,
                       (const void*)(g_pwh + (size_t)row * 256 + kc + col * 8));
        }
    };

    cpW(0, 0); CP_COMMIT();

    if (tid < 128) {
        int p = p0 + tid;
        int t = p / JDIM, j = p - t * JDIM;
        float sy = (t + 0.5f) * (43.0f / 128.0f) - 0.5f;
        sy = fminf(fmaxf(sy, 0.f), 42.f);
        int y0 = (int)sy;
        int y1 = min(y0 + 1, 42);
        float fy = sy - y0;
        float sx = (j + 0.5f) * (6.0f / 17.0f) - 0.5f;
        sx = fminf(fmaxf(sx, 0.f), 5.f);
        int x0 = (int)sx;
        int x1i = min(x0 + 1, 5);
        float fx = sx - x0;
        o00[tid] = (y0 * WCC + x0) * CDIM;
        o01[tid] = (y0 * WCC + x1i) * CDIM;
        o10[tid] = (y1 * WCC + x0) * CDIM;
        o11[tid] = (y1 * WCC + x1i) * CDIM;
        wxs[tid] = fx;
        wys[tid] = fy;
    } else if (tid < 384) {
        pbs[tid - 128] = pb[tid - 128];
    }
    __syncthreads();

    const __half* abase = g_att + (size_t)b * HW * CDIM;
    for (int e = tid; e < 32768; e += 512) {
        int k = e & 255, gl = e >> 8;
        const __half* bp = abase + k;
        float fx = wxs[gl], fy = wys[gl];
        float a00 = __half2float(bp[o00[gl]]);
        float a01 = __half2float(bp[o01[gl]]);
        float a10 = __half2float(bp[o10[gl]]);
        float a11 = __half2float(bp[o11[gl]]);
        float v = (a00 * (1.f - fx) + a01 * fx) * (1.f - fy)
                + (a10 * (1.f - fx) + a11 * fx) * fy;
        *(__half*)(smem + PJ_PS + ((uint32_t)gl * 264 + k) * 2) = __float2half(v);
    }

    const uint32_t a_row  = (lane & 7) + ((lane >> 3) & 1) * 8;
    const uint32_t a_koff = (lane >> 4) * 8;
    const uint32_t b_row  = (lane & 7) + (lane >> 4) * 8;
    const uint32_t b_koff = ((lane >> 3) & 1) * 8;
    const uint32_t ps_base = sbase + PJ_PS;

    float d[4][4][4];
#pragma unroll
    for (int mi = 0; mi < 4; mi++)
#pragma unroll
        for (int nf = 0; nf < 4; nf++)
#pragma unroll
            for (int q = 0; q < 4; q++) d[mi][nf][q] = 0.f;

    for (int c = 0; c < 4; c++) {
        if (c < 3) {
            cpW((c + 1) * 64, (c + 1) & 1); CP_COMMIT();
            CP_WAIT1();
        } else {
            CP_WAIT0();
        }
        __syncthreads();

        const uint32_t wsb = sbase + PJ_WBUF + (uint32_t)(c & 1) * 36864;
#pragma unroll
        for (int ks = 0; ks < 4; ks++) {
            const int k0 = ks * 16;
            const int kg = c * 64 + k0;
            uint32_t b0[4], b1[4];
            LDM_X4(b0, ps_base + (((uint32_t)(wx * 32)      + b_row) * 264 + kg + b_koff) * 2);
            LDM_X4(b1, ps_base + (((uint32_t)(wx * 32 + 16) + b_row) * 264 + kg + b_koff) * 2);
            uint32_t a[4][4];
#pragma unroll
            for (int mi = 0; mi < 4; mi++)
                LDM_X4(a[mi], wsb + (((uint32_t)(wy * 64 + mi * 16) + a_row) * 72
                                      + k0 + a_koff) * 2);
#pragma unroll
            for (int mi = 0; mi < 4; mi++) {
                MMA16816(d[mi][0], a[mi], b0[0], b0[1]);
                MMA16816(d[mi][1], a[mi], b0[2], b0[3]);
                MMA16816(d[mi][2], a[mi], b1[0], b1[1]);
                MMA16816(d[mi][3], a[mi], b1[2], b1[3]);
            }
        }
        __syncthreads();
    }

    float* stage = (float*)(smem + PJ_STAGE);
#pragma unroll
    for (int h = 0; h < 2; h++) {
        if ((wy >> 1) == h) {
            int r = lane >> 2, c2 = (lane & 3) * 2;
#pragma unroll
            for (int mi = 0; mi < 4; mi++) {
                int row = wy * 64 + mi * 16 + r - 128 * h;
#pragma unroll
                for (int nf = 0; nf < 4; nf++) {
                    int col = wx * 32 + nf * 8 + c2;
                    stage[col * 129 + row]           = d[mi][nf][0];
                    stage[(col + 1) * 129 + row]     = d[mi][nf][1];
                    stage[col * 129 + row + 8]       = d[mi][nf][2];
                    stage[(col + 1) * 129 + row + 8] = d[mi][nf][3];
                }
            }
        }
        __syncthreads();
        for (int e = tid; e < 16384; e += 512) {
            int gl = e & 127, cl = e >> 7;
            int ch = 128 * h + cl;
            size_t idx = ((size_t)b * CDIM + ch) * TJ + p0 + gl;
            x1[idx] = x[idx] + stage[gl * 129 + cl] + pbs[ch];
        }
        __syncthreads();
    }
}

// ---------------------------------------------------------------------------
// K4: fused MLP on HMMA, big-tile (unchanged from round 9)
// ---------------------------------------------------------------------------
#define M2_SN   0
#define M2_TN   1024
#define M2_S2   2048
#define M2_T2   3072
#define M2_S1   4096
#define M2_T1   4608
#define M2_XS   5120
#define M2_HS   72704
#define M2_WB   107520
#define M2_ST   M2_XS
#define M2_TOT  181248

__global__ void __launch_bounds__(512, 1) k_mlp_mma2(
    const float* x1,
    const float* __restrict__ b1g, const float* __restrict__ b1b,
    const float* __restrict__ b1m, const float* __restrict__ b1v,
    const float* __restrict__ fb1,
    const float* __restrict__ b2g, const float* __restrict__ b2b,
    const float* __restrict__ b2m, const float* __restrict__ b2v,
    const float* __restrict__ fb2,
    const float* __restrict__ n2g, const float* __restrict__ n2b,
    const float* __restrict__ n2m, const float* __restrict__ n2v,
    float* out)
{
    extern __shared__ char smem[];
    const uint32_t sbase = smem_u32(smem);
    const int tid = threadIdx.x;
    const int wid = tid >> 5, lane = tid & 31;
    const int wy = wid & 3, wx = wid >> 2;

    const int b  = blockIdx.x / 17;
    const int p0 = (blockIdx.x - b * 17) * 128;

    float* sn = (float*)(smem + M2_SN);
    float* tn = (float*)(smem + M2_TN);
    float* s2 = (float*)(smem + M2_S2);
    float* t2 = (float*)(smem + M2_T2);
    float* s1 = (float*)(smem + M2_S1);
    float* t1 = (float*)(smem + M2_T1);

    auto cpW1 = [&](int nt, int c, int bsel) {
        uint32_t dstb = sbase + M2_WB + (uint32_t)bsel * 36864;
        const __half* src = g_w1h + nt * 32768 + c * 64;
#pragma unroll
        for (int t = 0; t < 2; t++) {
            int e = tid + t * 512;
            int row = e >> 3, col = e & 7;
            CP_ASYNC16(dstb + ((uint32_t)row * 72 + col * 8) * 2,
                       (const void*)(src + (size_t)row * 256 + col * 8));
        }
    };
    auto cpW2 = [&](int nt, int c, int bsel) {
        uint32_t dstb = sbase + M2_WB + (uint32_t)bsel * 36864;
        const __half* src = g_w2h + nt * 32768 + c * 64;
#pragma unroll
        for (int t = 0; t < 4; t++) {
            int e = tid + t * 512;
            int row = e >> 3, col = e & 7;
            CP_ASYNC16(dstb + ((uint32_t)row * 72 + col * 8) * 2,
                       (const void*)(src + (size_t)row * 128 + col * 8));
        }
    };

    cpW1(0, 0, 0); CP_COMMIT();

    if (tid < 256) {
        float s = n2g[tid] * rsqrtf(n2v[tid] + 1e-5f);
        sn[tid] = s;
        tn[tid] = n2b[tid] - n2m[tid] * s;
    } else {
        int c = tid - 256;
        float s = b2g[c] * rsqrtf(b2v[c] + 1e-5f);
        s2[c] = s;
        t2[c] = b2b[c] - b2m[c] * s + fb2[c] * s;
    }
    __syncthreads();

    const float* xb = x1 + (size_t)b * CDIM * TJ;
    for (int e = tid; e < 32768; e += 512) {
        int i = e & 255, p = e >> 8;
        float v = xb[(size_t)i * TJ + p0 + p] * sn[i] + tn[i];
        *(__half*)(smem + M2_XS + ((uint32_t)p * 264 + i) * 2) = __float2half(v);
    }

    const uint32_t a_row  = (lane & 7) + ((lane >> 3) & 1) * 8;
    const uint32_t a_koff = (lane >> 4) * 8;
    const uint32_t b_row  = (lane & 7) + (lane >> 4) * 8;
    const uint32_t b_koff = ((lane >> 3) & 1) * 8;

    const uint32_t xs_base = sbase + M2_XS;
    const uint32_t hs_base = sbase + M2_HS;

    float d2[4][4][4];
#pragma unroll
    for (int mi = 0; mi < 4; mi++)
#pragma unroll
        for (int nf = 0; nf < 4; nf++)
#pragma unroll
            for (int q = 0; q < 4; q++) d2[mi][nf][q] = 0.f;

    int buf = 0;

    for (int nt = 0; nt < 8; nt++) {
        if (tid < 128) {
            int j = nt * 128 + tid;
            float s = b1g[j] * rsqrtf(b1v[j] + 1e-5f);
            s1[tid] = s;
            t1[tid] = b1b[j] - b1m[j] * s + fb1[j] * s;
        }

        float d1[2][4][4];
#pragma unroll
        for (int mi = 0; mi < 2; mi++)
#pragma unroll
            for (int nf = 0; nf < 4; nf++)
#pragma unroll
                for (int q = 0; q < 4; q++) d1[mi][nf][q] = 0.f;

        for (int c = 0; c < 4; c++) {
            if (c < 3) cpW1(nt, c + 1, buf ^ 1);
            else       cpW2(nt, 0, buf ^ 1);
            CP_COMMIT(); CP_WAIT1();
            __syncthreads();

            const uint32_t wsb = sbase + M2_WB + (uint32_t)buf * 36864;
#pragma unroll
            for (int ks = 0; ks < 4; ks++) {
                const int k0 = ks * 16;
                const int kg = c * 64 + k0;
                uint32_t b0[4], b1[4];
                LDM_X4(b0, xs_base + (((uint32_t)(wx * 32)      + b_row) * 264 + kg + b_koff) * 2);
                LDM_X4(b1, xs_base + (((uint32_t)(wx * 32 + 16) + b_row) * 264 + kg + b_koff) * 2);
                uint32_t a[2][4];
#pragma unroll
                for (int mi = 0; mi < 2; mi++)
                    LDM_X4(a[mi], wsb + (((uint32_t)(wy * 32 + mi * 16) + a_row) * 72
                                          + k0 + a_koff) * 2);
#pragma unroll
                for (int mi = 0; mi < 2; mi++) {
                    MMA16816(d1[mi][0], a[mi], b0[0], b0[1]);
                    MMA16816(d1[mi][1], a[mi], b0[2], b0[3]);
                    MMA16816(d1[mi][2], a[mi], b1[0], b1[1]);
                    MMA16816(d1[mi][3], a[mi], b1[2], b1[3]);
                }
            }
            buf ^= 1;
            __syncthreads();
        }

        {
            int r = lane >> 2, c2l = (lane & 3) * 2;
#pragma unroll
            for (int mi = 0; mi < 2; mi++) {
                int j = wy * 32 + mi * 16 + r;
                float sj0 = s1[j],     tj0 = t1[j];
                float sj8 = s1[j + 8], tj8 = t1[j + 8];
#pragma unroll
                for (int nf = 0; nf < 4; nf++) {
                    int pos = wx * 32 + nf * 8 + c2l;
                    __half* h0 = (__half*)(smem + M2_HS + ((uint32_t)pos * 136 + j) * 2);
                    __half* h1 = (__half*)(smem + M2_HS + ((uint32_t)(pos + 1) * 136 + j) * 2);
                    h0[0] = __float2half(gelu_exact(d1[mi][nf][0] * sj0 + tj0));
                    h1[0] = __float2half(gelu_exact(d1[mi][nf][1] * sj0 + tj0));
                    h0[8] = __float2half(gelu_exact(d1[mi][nf][2] * sj8 + tj8));
                    h1[8] = __float2half(gelu_exact(d1[mi][nf][3] * sj8 + tj8));
                }
            }
        }

        for (int c = 0; c < 2; c++) {
            if (c == 0)        { cpW2(nt, 1, buf ^ 1); CP_COMMIT(); CP_WAIT1(); }
            else if (nt < 7)   { cpW1(nt + 1, 0, buf ^ 1); CP_COMMIT(); CP_WAIT1(); }
            else               { CP_WAIT0(); }
            __syncthreads();

            const uint32_t wsb = sbase + M2_WB + (uint32_t)buf * 36864;
#pragma unroll
            for (int ks = 0; ks < 4; ks++) {
                const int k0 = ks * 16;
                const int kg = c * 64 + k0;
                uint32_t b0[4], b1[4];
                LDM_X4(b0, hs_base + (((uint32_t)(wx * 32)      + b_row) * 136 + kg + b_koff) * 2);
                LDM_X4(b1, hs_base + (((uint32_t)(wx * 32 + 16) + b_row) * 136 + kg + b_koff) * 2);
                uint32_t a[4][4];
#pragma unroll
                for (int mi = 0; mi < 4; mi++)
                    LDM_X4(a[mi], wsb + (((uint32_t)(wy * 64 + mi * 16) + a_row) * 72
                                          + k0 + a_koff) * 2);
#pragma unroll
                for (int mi = 0; mi < 4; mi++) {
                    MMA16816(d2[mi][0], a[mi], b0[0], b0[1]);
                    MMA16816(d2[mi][1], a[mi], b0[2], b0[3]);
                    MMA16816(d2[mi][2], a[mi], b1[0], b1[1]);
                    MMA16816(d2[mi][3], a[mi], b1[2], b1[3]);
                }
            }
            buf ^= 1;
            __syncthreads();
        }
    }

    float* stage = (float*)(smem + M2_ST);
#pragma unroll
    for (int h = 0; h < 2; h++) {
        if ((wy >> 1) == h) {
            int r = lane >> 2, c2l = (lane & 3) * 2;
#pragma unroll
            for (int mi = 0; mi < 4; mi++) {
                int row = wy * 64 + mi * 16 + r - 128 * h;
#pragma unroll
                for (int nf = 0; nf < 4; nf++) {
                    int col = wx * 32 + nf * 8 + c2l;
                    stage[col * 129 + row]           = d2[mi][nf][0];
                    stage[(col + 1) * 129 + row]     = d2[mi][nf][1];
                    stage[col * 129 + row + 8]       = d2[mi][nf][2];
                    stage[(col + 1) * 129 + row + 8] = d2[mi][nf][3];
                }
            }
        }
        __syncthreads();
        for (int e = tid; e < 16384; e += 512) {
            int gl = e & 127, cl = e >> 7;
            int ch = 128 * h + cl;
            size_t idx = ((size_t)b * CDIM + ch) * TJ + p0 + gl;
            out[idx] = x1[idx] + stage[gl * 129 + cl] * s2[ch] + t2[ch];
        }
        __syncthreads();
    }
}

// ---------------------------------------------------------------------------
extern "C" void kernel_launch(void* const* d_in, const int* in_sizes, int n_in,
                              void* d_out, int out_size)
{
    const float* x    = (const float*)d_in[0];
    const float* n1g  = (const float*)d_in[1];
    const float* n1b  = (const float*)d_in[2];
    const float* n1m  = (const float*)d_in[3];
    const float* n1v  = (const float*)d_in[4];
    const float* qkvw = (const float*)d_in[5];
    const float* qg   = (const float*)d_in[6];
    const float* qb   = (const float*)d_in[7];
    const float* qm   = (const float*)d_in[8];
    const float* qv   = (const float*)d_in[9];
    const float* pw   = (const float*)d_in[10];
    const float* pb   = (const float*)d_in[11];
    const float* n2g  = (const float*)d_in[12];
    const float* n2b  = (const float*)d_in[13];
    const float* n2m  = (const float*)d_in[14];
    const float* n2v  = (const float*)d_in[15];
    const float* w1   = (const float*)d_in[16];
    const float* fb1  = (const float*)d_in[17];
    const float* b1g  = (const float*)d_in[18];
    const float* b1b  = (const float*)d_in[19];
    const float* b1m  = (const float*)d_in[20];
    const float* b1v  = (const float*)d_in[21];
    const float* w2   = (const float*)d_in[22];
    const float* fb2  = (const float*)d_in[23];
    const float* b2g  = (const float*)d_in[24];
    const float* b2b  = (const float*)d_in[25];
    const float* b2m  = (const float*)d_in[26];
    const float* b2v  = (const float*)d_in[27];
    float* out = (float*)d_out;

    cudaFuncSetAttribute(k_attn_mma, cudaFuncAttributeMaxDynamicSharedMemorySize, AT_TOT);
    cudaFuncSetAttribute(k_conv_mma, cudaFuncAttributeMaxDynamicSharedMemorySize, CV_TOT);
    cudaFuncSetAttribute(k_proj_mma, cudaFuncAttributeMaxDynamicSharedMemorySize, PJ_TOT);
    cudaFuncSetAttribute(k_mlp_mma2, cudaFuncAttributeMaxDynamicSharedMemorySize, M2_TOT);

    k_prep_all<<<16384 + 4608, 512>>>(w1, w2, qkvw, pw, x, n1g, n1b, n1m, n1v);
    k_conv_mma<<<dim3(3, 129), 512, CV_TOT>>>(qg, qb, qm, qv);
    k_attn_mma<<<512, 544, AT_TOT>>>();
    k_proj_mma<<<1088, 512, PJ_TOT>>>(pb, x, out);
    k_mlp_mma2<<<1088, 512, M2_TOT>>>(out,
                                      b1g, b1b, b1m, b1v, fb1,
                                      b2g, b2b, b2m, b2v, fb2,
                                      n2g, n2b, n2m, n2v, out);
}